// round 4
// baseline (speedup 1.0000x reference)
#include <cuda_runtime.h>
#include <cuda_bf16.h>
#include <math.h>

// Problem constants: B=4, S=2048, D=2048, H=16, hd=128
#define Bb_ 4
#define S_  2048
#define H_  16
#define HD_ 128
#define D_  2048

// ---------------- scratch (device globals; allocation-free) ----------------
__device__ float g_q[16777216];       // [B,H,S,hd]
__device__ float g_k[16777216];       // [B,H,S,hd]
__device__ float g_v[16777216];       // [B,H,S,hd]
__device__ float g_attn[16777216];    // [B,S,D]  (h*hd+d contiguous)
__device__ float g_scores[268435456]; // [B,H,S,S]

// ---------------- fp32 SIMT GEMM, 128x128x8 tile, 8x8 microtile ----------------
// MODE: 0 = plain C write, 1 = qkv scatter, 2 = scores (scale+causal mask),
//       3 = attn scatter.  BT: B stored [N,K] row-major (used for Q@K^T).
// KLIMIT: causal K truncation for P@V.
#define BM 128
#define BN 128
#define BK 8

template<int MODE, bool BT, bool KLIMIT>
__global__ __launch_bounds__(256)
void gemm_f32(const float* __restrict__ A, const float* __restrict__ Bm,
              float* __restrict__ C,
              int M, int N, int K, int lda, int ldb, int ldc,
              long long strideA, long long strideB, long long strideC)
{
    const int z = blockIdx.z;
    const float* Ab = A + (long long)z * strideA;
    const float* Bb = Bm + (long long)z * strideB;
    float* Cb = C + (long long)z * strideC;

    const int m0 = blockIdx.y * BM;
    const int n0 = blockIdx.x * BN;

    if (MODE == 2) {
        // block entirely above the causal diagonal: never read -> skip
        if (n0 > m0 + BM - 1) return;
    }

    int Kend = K;
    if (KLIMIT) { int ke = m0 + BM; Kend = (ke < K) ? ke : K; }
    const int nk = Kend / BK;   // all K values here are multiples of 8

    __shared__ float As[2][BK][BM];
    __shared__ float Bs[2][BK][BN];

    const int tid = threadIdx.x;
    const int tx = tid & 15;          // 0..15 -> 8 columns (2x float4)
    const int ty = tid >> 4;          // 0..15 -> 8 rows

    // global-load thread mapping
    const int a_row = tid >> 1;       // 0..127
    const int a_kq  = tid & 1;        // 0..1 (k quad)
    const int b_k   = tid >> 5;       // 0..7  (NN B)
    const int b_c4  = tid & 31;       // 0..31 (NN B col quad)

    float acc[8][8];
#pragma unroll
    for (int i = 0; i < 8; i++)
#pragma unroll
        for (int j = 0; j < 8; j++) acc[i][j] = 0.f;

    // ---- stage tile 0 ----
    {
        float4 av = *(const float4*)(Ab + (long long)(m0 + a_row) * lda + a_kq * 4);
        As[0][a_kq*4+0][a_row] = av.x; As[0][a_kq*4+1][a_row] = av.y;
        As[0][a_kq*4+2][a_row] = av.z; As[0][a_kq*4+3][a_row] = av.w;
        if (!BT) {
            float4 bv = *(const float4*)(Bb + (long long)b_k * ldb + n0 + b_c4 * 4);
            *(float4*)&Bs[0][b_k][b_c4*4] = bv;
        } else {
            float4 bv = *(const float4*)(Bb + (long long)(n0 + a_row) * ldb + a_kq * 4);
            Bs[0][a_kq*4+0][a_row] = bv.x; Bs[0][a_kq*4+1][a_row] = bv.y;
            Bs[0][a_kq*4+2][a_row] = bv.z; Bs[0][a_kq*4+3][a_row] = bv.w;
        }
    }
    __syncthreads();

    int buf = 0;
    for (int kt = 0; kt < nk; ++kt) {
        float4 av, bv;
        const bool pf = (kt + 1 < nk);
        if (pf) {
            const int k0 = (kt + 1) * BK;
            av = *(const float4*)(Ab + (long long)(m0 + a_row) * lda + k0 + a_kq * 4);
            if (!BT) bv = *(const float4*)(Bb + (long long)(k0 + b_k) * ldb + n0 + b_c4 * 4);
            else     bv = *(const float4*)(Bb + (long long)(n0 + a_row) * ldb + k0 + a_kq * 4);
        }

#pragma unroll
        for (int kk = 0; kk < BK; ++kk) {
            float a[8], b[8];
            float4 t0 = *(const float4*)&As[buf][kk][ty * 4];
            float4 t1 = *(const float4*)&As[buf][kk][64 + ty * 4];
            a[0]=t0.x; a[1]=t0.y; a[2]=t0.z; a[3]=t0.w;
            a[4]=t1.x; a[5]=t1.y; a[6]=t1.z; a[7]=t1.w;
            float4 u0 = *(const float4*)&Bs[buf][kk][tx * 4];
            float4 u1 = *(const float4*)&Bs[buf][kk][64 + tx * 4];
            b[0]=u0.x; b[1]=u0.y; b[2]=u0.z; b[3]=u0.w;
            b[4]=u1.x; b[5]=u1.y; b[6]=u1.z; b[7]=u1.w;
#pragma unroll
            for (int i = 0; i < 8; i++)
#pragma unroll
                for (int j = 0; j < 8; j++)
                    acc[i][j] = fmaf(a[i], b[j], acc[i][j]);
        }

        if (pf) {
            const int nb = buf ^ 1;
            As[nb][a_kq*4+0][a_row] = av.x; As[nb][a_kq*4+1][a_row] = av.y;
            As[nb][a_kq*4+2][a_row] = av.z; As[nb][a_kq*4+3][a_row] = av.w;
            if (!BT) {
                *(float4*)&Bs[nb][b_k][b_c4*4] = bv;
            } else {
                Bs[nb][a_kq*4+0][a_row] = bv.x; Bs[nb][a_kq*4+1][a_row] = bv.y;
                Bs[nb][a_kq*4+2][a_row] = bv.z; Bs[nb][a_kq*4+3][a_row] = bv.w;
            }
            __syncthreads();
            buf = nb;
        }
    }

    // ---- epilogue ----
#pragma unroll
    for (int i = 0; i < 8; i++) {
        const int gm = m0 + ((i < 4) ? (ty * 4 + i) : (64 + ty * 4 + i - 4));
#pragma unroll
        for (int jh = 0; jh < 2; jh++) {
            const int gn = n0 + ((jh == 0) ? tx * 4 : 64 + tx * 4);
            float4 v;
            v.x = acc[i][jh*4+0]; v.y = acc[i][jh*4+1];
            v.z = acc[i][jh*4+2]; v.w = acc[i][jh*4+3];

            if (MODE == 0) {
                *(float4*)(Cb + (long long)gm * ldc + gn) = v;
            } else if (MODE == 1) {
                // row gm = b*S+s ; col gn = t*2048 + h*128 + d
                const int b = gm >> 11, s = gm & 2047;
                const int t = gn >> 11, h = (gn >> 7) & 15, d = gn & 127;
                float* dst = (t == 0) ? g_q : (t == 1) ? g_k : g_v;
                *(float4*)(dst + (((long long)(b * H_ + h) * S_ + s) * HD_ + d)) = v;
            } else if (MODE == 2) {
                const float scale = 0.08838834764831845f; // 1/sqrt(128)
                v.x = (gn + 0 > gm) ? -1e30f : v.x * scale;
                v.y = (gn + 1 > gm) ? -1e30f : v.y * scale;
                v.z = (gn + 2 > gm) ? -1e30f : v.z * scale;
                v.w = (gn + 3 > gm) ? -1e30f : v.w * scale;
                *(float4*)(Cb + (long long)gm * ldc + gn) = v;
            } else { // MODE 3: attn scatter [B,S,D]
                const int b = z >> 4, h = z & 15;
                *(float4*)(g_attn + ((long long)(b * S_ + gm)) * D_ + h * HD_ + gn) = v;
            }
        }
    }
}

// ---------------- RoPE on q and k, in place, [B,H,S,hd] ----------------
__global__ void rope_kernel(const float* __restrict__ cosT,
                            const float* __restrict__ sinT)
{
    const long long idx = (long long)blockIdx.x * 256 + threadIdx.x;
    // total = (B*H) * S * (hd/2) = 64 * 2048 * 64 = 2^23
    const int i = (int)(idx & 63);
    const int s = (int)((idx >> 6) & 2047);
    const int z = (int)(idx >> 17);
    const float c  = cosT[s * 64 + i];
    const float sn = sinT[s * 64 + i];
    const long long base = ((long long)z * S_ + s) * HD_;
    float q1 = g_q[base + i], q2 = g_q[base + 64 + i];
    g_q[base + i]      = q1 * c - q2 * sn;
    g_q[base + 64 + i] = q1 * sn + q2 * c;
    float k1 = g_k[base + i], k2 = g_k[base + 64 + i];
    g_k[base + i]      = k1 * c - k2 * sn;
    g_k[base + 64 + i] = k1 * sn + k2 * c;
}

// ---------------- causal row softmax over g_scores, in place ----------------
// Reads only k <= q; zero-fills (q, k_tile_end) so the K-limited PV GEMM
// never reads unwritten memory.
__global__ void softmax_kernel()
{
    const int q = blockIdx.x;     // 0..S-1
    const int z = blockIdx.y;     // 0..B*H-1
    float* row = g_scores + ((long long)z * S_ + q) * S_;
    const int len = q + 1;
    const int tid = threadIdx.x;  // 256 threads

    __shared__ float red[256];

    float m = -1e30f;
    for (int k = tid; k < len; k += 256) m = fmaxf(m, row[k]);
    red[tid] = m; __syncthreads();
    for (int s = 128; s > 0; s >>= 1) {
        if (tid < s) red[tid] = fmaxf(red[tid], red[tid + s]);
        __syncthreads();
    }
    m = red[0];
    __syncthreads();

    float sum = 0.f;
    for (int k = tid; k < len; k += 256) {
        float e = __expf(row[k] - m);
        row[k] = e;
        sum += e;
    }
    red[tid] = sum; __syncthreads();
    for (int s = 128; s > 0; s >>= 1) {
        if (tid < s) red[tid] += red[tid + s];
        __syncthreads();
    }
    const float inv = 1.0f / red[0];

    for (int k = tid; k < len; k += 256) row[k] *= inv;

    // zero-fill up to the end of this row's 128-aligned K tile
    const int kend = ((q >> 7) + 1) << 7;
    for (int k = len + tid; k < kend; k += 256) row[k] = 0.f;
}

// ---------------- launch ----------------
extern "C" void kernel_launch(void* const* d_in, const int* in_sizes, int n_in,
                              void* d_out, int out_size)
{
    const float* x     = (const float*)d_in[0]; // [4,2048,2048]
    const float* cosT  = (const float*)d_in[1]; // [2048,64]
    const float* sinT  = (const float*)d_in[2]; // [2048,64]
    const float* w_qkv = (const float*)d_in[3]; // [2048,6144]
    const float* w_out = (const float*)d_in[4]; // [2048,2048]
    float* out = (float*)d_out;                 // [4,2048,2048]
    (void)in_sizes; (void)n_in; (void)out_size;

    float *qp, *kp, *vp, *sp, *ap;
    cudaGetSymbolAddress((void**)&qp, g_q);
    cudaGetSymbolAddress((void**)&kp, g_k);
    cudaGetSymbolAddress((void**)&vp, g_v);
    cudaGetSymbolAddress((void**)&sp, g_scores);
    cudaGetSymbolAddress((void**)&ap, g_attn);

    const long long SHD = (long long)S_ * HD_;   // per-(b,h) q/k/v stride
    const long long SS  = (long long)S_ * S_;    // per-(b,h) scores stride

    // 1) QKV projection: [8192,2048] @ [2048,6144], scatter into q/k/v
    gemm_f32<1, false, false><<<dim3(6144 / BN, 8192 / BM, 1), 256>>>(
        x, w_qkv, nullptr, 8192, 6144, 2048, 2048, 6144, 0, 0, 0, 0);

    // 2) RoPE on q and k
    rope_kernel<<<(Bb_ * H_ * S_ * (HD_ / 2)) / 256, 256>>>(cosT, sinT);

    // 3) scores = (Q @ K^T) / sqrt(hd), causal mask, block-skip above diagonal
    gemm_f32<2, true, false><<<dim3(S_ / BN, S_ / BM, Bb_ * H_), 256>>>(
        qp, kp, sp, S_, S_, HD_, HD_, HD_, S_, SHD, SHD, SS);

    // 4) causal softmax rows
    softmax_kernel<<<dim3(S_, Bb_ * H_), 256>>>();

    // 5) attn = P @ V (K-limited by causal structure), scatter to [B,S,D]
    gemm_f32<3, false, true><<<dim3(1, S_ / BM, Bb_ * H_), 256>>>(
        sp, vp, nullptr, S_, HD_, S_, S_, HD_, 0, SS, SHD, 0);

    // 6) out = attn @ w_out
    gemm_f32<0, false, false><<<dim3(D_ / BN, 8192 / BM, 1), 256>>>(
        ap, w_out, out, 8192, 2048, 2048, 2048, 2048, 2048, 0, 0, 0);
}

// round 9
// speedup vs baseline: 1.8582x; 1.8582x over previous
#include <cuda_runtime.h>
#include <cuda_bf16.h>
#include <cstdint>
#include <math.h>

// Problem constants: B=4, S=2048, D=2048, H=16, hd=128
#define Bb_ 4
#define S_  2048
#define H_  16
#define HD_ 128
#define D_  2048

// ---------------- scratch (device globals; allocation-free) ----------------
__device__ float g_q[16777216];        // [B,H,S,hd]
__device__ float g_k[16777216];        // [B,H,S,hd]
__device__ float g_v[16777216];        // V^T: [B,H,hd,S]
__device__ float g_attn[16777216];     // [B,S,D]
__device__ float g_scores[268435456];  // [B,H,S,S]
__device__ float g_wqkvT[12582912];    // [6144,2048]
__device__ float g_woutT[4194304];     // [2048,2048]

// ---------------- helpers ----------------
__device__ __forceinline__ uint32_t smem_u32(const void* p) {
    uint32_t a;
    asm("{ .reg .u64 t; cvta.to.shared.u64 t, %1; cvt.u32.u64 %0, t; }" : "=r"(a) : "l"(p));
    return a;
}
__device__ __forceinline__ void ldsm4(uint32_t* r, uint32_t addr) {
    asm volatile("ldmatrix.sync.aligned.m8n8.x4.shared.b16 {%0,%1,%2,%3}, [%4];"
                 : "=r"(r[0]), "=r"(r[1]), "=r"(r[2]), "=r"(r[3]) : "r"(addr));
}
__device__ __forceinline__ void mma_bf16(float* c, const uint32_t* a, uint32_t b0, uint32_t b1) {
    asm volatile(
        "mma.sync.aligned.m16n8k16.row.col.f32.bf16.bf16.f32 "
        "{%0,%1,%2,%3}, {%4,%5,%6,%7}, {%8,%9}, {%0,%1,%2,%3};"
        : "+f"(c[0]), "+f"(c[1]), "+f"(c[2]), "+f"(c[3])
        : "r"(a[0]), "r"(a[1]), "r"(a[2]), "r"(a[3]), "r"(b0), "r"(b1));
}
__device__ __forceinline__ uint32_t sw128(uint32_t off) { return off ^ ((off >> 3) & 0x70); }

// ---------------- bf16x2 mma.sync TN GEMM ----------------
// C[M,N] = A[M,K] @ B[N,K]^T, fp32 in, split into bf16 hi/lo, 3 passes.
// Block 128x128, 8 warps (4x2), warp tile 32x64, K chunk 64.
// MODE: 0 = plain C, 1 = qkv scatter (V transposed), 2 = scores scale+mask,
//       3 = PV scatter to g_attn.  KLIMIT: causal K truncation for PV.
#define SMEM_GEMM_BYTES 132096
#define TOFF(buf, which) (1024u + (uint32_t)(buf) * 65536u + (uint32_t)(which) * 16384u)

__device__ __forceinline__ void split_pack_store(float4 v, char* hi, char* lo, uint32_t sw) {
    __nv_bfloat16 hx = __float2bfloat16(v.x), hy = __float2bfloat16(v.y);
    __nv_bfloat16 hz = __float2bfloat16(v.z), hw = __float2bfloat16(v.w);
    uint32_t h01 = (uint32_t)__bfloat16_as_ushort(hx) | ((uint32_t)__bfloat16_as_ushort(hy) << 16);
    uint32_t h23 = (uint32_t)__bfloat16_as_ushort(hz) | ((uint32_t)__bfloat16_as_ushort(hw) << 16);
    *(uint2*)(hi + sw) = make_uint2(h01, h23);
    __nv_bfloat16 lx = __float2bfloat16(v.x - __bfloat162float(hx));
    __nv_bfloat16 ly = __float2bfloat16(v.y - __bfloat162float(hy));
    __nv_bfloat16 lz = __float2bfloat16(v.z - __bfloat162float(hz));
    __nv_bfloat16 lw = __float2bfloat16(v.w - __bfloat162float(hw));
    uint32_t l01 = (uint32_t)__bfloat16_as_ushort(lx) | ((uint32_t)__bfloat16_as_ushort(ly) << 16);
    uint32_t l23 = (uint32_t)__bfloat16_as_ushort(lz) | ((uint32_t)__bfloat16_as_ushort(lw) << 16);
    *(uint2*)(lo + sw) = make_uint2(l01, l23);
}

// Load one 128x64 fp32 chunk directly -> hi/lo bf16 SW128 tiles (256 threads).
__device__ __forceinline__ void load_chunk_direct(const float* __restrict__ src, int ld,
                                                  int row0, int kbase,
                                                  char* hi, char* lo, int t) {
    const int rp = t >> 4, cf = t & 15;
    const float* p = src + (long long)(row0 + rp) * ld + kbase + cf * 4;
#pragma unroll
    for (int pass = 0; pass < 8; ++pass) {
        float4 v = *(const float4*)p;
        p += (long long)16 * ld;
        uint32_t sw = sw128((rp + pass * 16) * 128 + cf * 8);
        split_pack_store(v, hi, lo, sw);
    }
}

template<int MODE, bool KLIMIT>
__global__ __launch_bounds__(256, 1)
void gemm_tc(const float* __restrict__ A, const float* __restrict__ Bm,
             float* __restrict__ C,
             int K, int lda, int ldb, int ldc,
             long long strideA, long long strideB, long long strideC)
{
    const int m0 = blockIdx.y * 128;
    const int n0 = blockIdx.x * 128;
    if (MODE == 2) {
        if (n0 > m0 + 127) return;   // fully above causal diagonal
    }
    const int z = blockIdx.z;
    const float* Ab = A + (long long)z * strideA;
    const float* Bb = Bm + (long long)z * strideB;
    float* Cb = C + (long long)z * strideC;

    int Kend = K;
    if (KLIMIT) { int ke = m0 + 128; Kend = (ke < K) ? ke : K; }
    const int nchunks = Kend >> 6;

    extern __shared__ char smem[];
    const uint32_t sb = smem_u32(smem);
    const int tid = threadIdx.x;
    const int wid = tid >> 5;
    const int lane = tid & 31;
    const int wm = (wid & 3) * 32;       // warp M offset in tile
    const int wn = (wid >> 2) * 64;      // warp N offset in tile
    const int lq = lane >> 3, lr = lane & 7;

    // ldmatrix per-thread row components
    const int a_row = wm + (lq & 1) * 8 + lr;     // + i*16
    const int a_kc2 = (lq >> 1) * 16;             // k byte offset from quad
    const int b_row = wn + (lq >> 1) * 8 + lr;    // + jp*16
    const int b_kc2 = (lq & 1) * 16;

    // global-load mapping
    const int rp = tid >> 4, cf = tid & 15;

    float acc[2][8][4];
#pragma unroll
    for (int i = 0; i < 2; i++)
#pragma unroll
        for (int j = 0; j < 8; j++)
#pragma unroll
            for (int e = 0; e < 4; e++) acc[i][j][e] = 0.f;

    // stage chunk 0
    load_chunk_direct(Ab, lda, m0, 0, smem + TOFF(0, 0), smem + TOFF(0, 1), tid);
    load_chunk_direct(Bb, ldb, n0, 0, smem + TOFF(0, 2), smem + TOFF(0, 3), tid);
    __syncthreads();

    for (int c = 0; c < nchunks; ++c) {
        const int buf = c & 1;
        const bool pf = (c + 1 < nchunks);

        // prefetch next chunk into registers (overlaps with MMA loop)
        float4 areg[8], breg[8];
        if (pf) {
            const int kb = (c + 1) * 64;
            const float* pa = Ab + (long long)(m0 + rp) * lda + kb + cf * 4;
            const float* pb = Bb + (long long)(n0 + rp) * ldb + kb + cf * 4;
#pragma unroll
            for (int p = 0; p < 8; ++p) {
                areg[p] = *(const float4*)pa; pa += (long long)16 * lda;
                breg[p] = *(const float4*)pb; pb += (long long)16 * ldb;
            }
        }

        // ---- compute chunk from smem buf ----
        const uint32_t sAhi = sb + TOFF(buf, 0), sAlo = sb + TOFF(buf, 1);
        const uint32_t sBhi = sb + TOFF(buf, 2), sBlo = sb + TOFF(buf, 3);
#pragma unroll
        for (int kk = 0; kk < 4; ++kk) {
            uint32_t ahi[2][4], alo[2][4], bhi[4][4], blo[4][4];
#pragma unroll
            for (int i = 0; i < 2; ++i) {
                uint32_t sw = sw128((a_row + i * 16) * 128 + kk * 32 + a_kc2);
                ldsm4(ahi[i], sAhi + sw);
                ldsm4(alo[i], sAlo + sw);
            }
#pragma unroll
            for (int jp = 0; jp < 4; ++jp) {
                uint32_t sw = sw128((b_row + jp * 16) * 128 + kk * 32 + b_kc2);
                ldsm4(bhi[jp], sBhi + sw);
                ldsm4(blo[jp], sBlo + sw);
            }
#pragma unroll
            for (int i = 0; i < 2; ++i)
#pragma unroll
                for (int jp = 0; jp < 4; ++jp) {
                    mma_bf16(acc[i][2 * jp],     ahi[i], bhi[jp][0], bhi[jp][1]);
                    mma_bf16(acc[i][2 * jp + 1], ahi[i], bhi[jp][2], bhi[jp][3]);
                    mma_bf16(acc[i][2 * jp],     ahi[i], blo[jp][0], blo[jp][1]);
                    mma_bf16(acc[i][2 * jp + 1], ahi[i], blo[jp][2], blo[jp][3]);
                    mma_bf16(acc[i][2 * jp],     alo[i], bhi[jp][0], bhi[jp][1]);
                    mma_bf16(acc[i][2 * jp + 1], alo[i], bhi[jp][2], bhi[jp][3]);
                }
        }
        __syncthreads();

        if (pf) {
            const int nb = buf ^ 1;
            char* Ahi = smem + TOFF(nb, 0); char* Alo = smem + TOFF(nb, 1);
            char* Bhi = smem + TOFF(nb, 2); char* Blo = smem + TOFF(nb, 3);
#pragma unroll
            for (int p = 0; p < 8; ++p) {
                uint32_t sw = sw128((rp + p * 16) * 128 + cf * 8);
                split_pack_store(areg[p], Ahi, Alo, sw);
                split_pack_store(breg[p], Bhi, Blo, sw);
            }
            __syncthreads();
        }
    }

    // ---- epilogue from register fragments ----
    const int lm = lane >> 2;
    const int ln = (lane & 3) * 2;
    const float scale = 0.08838834764831845f;  // 1/sqrt(128)

#pragma unroll
    for (int i = 0; i < 2; ++i) {
#pragma unroll
        for (int j = 0; j < 8; ++j) {
            const int gn = n0 + wn + j * 8 + ln;
#pragma unroll
            for (int half = 0; half < 2; ++half) {
                const int gm = m0 + wm + i * 16 + lm + half * 8;
                float v0 = acc[i][j][half * 2 + 0];
                float v1 = acc[i][j][half * 2 + 1];

                if (MODE == 0) {
                    *(float2*)(Cb + (long long)gm * ldc + gn) = make_float2(v0, v1);
                } else if (MODE == 1) {
                    const int t = gn >> 11, h = (gn >> 7) & 15, d = gn & 127;
                    const int b = gm >> 11, s = gm & 2047;
                    if (t < 2) {
                        float* dst = (t == 0 ? g_q : g_k) +
                                     (((long long)(b * H_ + h) * S_ + s) * HD_ + d);
                        *(float2*)dst = make_float2(v0, v1);
                    } else {
                        float* dst = g_v + (((long long)(b * H_ + h) * HD_ + d) * S_ + s);
                        dst[0] = v0;
                        dst[S_] = v1;
                    }
                } else if (MODE == 2) {
                    float o0 = (gn + 0 > gm) ? -1e30f : v0 * scale;
                    float o1 = (gn + 1 > gm) ? -1e30f : v1 * scale;
                    *(float2*)(Cb + (long long)gm * ldc + gn) = make_float2(o0, o1);
                } else {  // MODE 3
                    const int b = z >> 4, h = z & 15;
                    *(float2*)(g_attn + ((long long)(b * S_ + gm)) * D_ + h * HD_ + gn) =
                        make_float2(v0, v1);
                }
            }
        }
    }
}

// ---------------- fp32 tile transpose: dst[C][R] = src[R][C] ----------------
__global__ void transpose_f32(const float* __restrict__ src, float* __restrict__ dst,
                              int R, int Cc)
{
    __shared__ float t[32][33];
    const int bx = blockIdx.x * 32, by = blockIdx.y * 32;
    const int txx = threadIdx.x, tyy = threadIdx.y;
#pragma unroll
    for (int i = 0; i < 4; ++i)
        t[tyy + i * 8][txx] = src[(long long)(by + tyy + i * 8) * Cc + bx + txx];
    __syncthreads();
#pragma unroll
    for (int i = 0; i < 4; ++i)
        dst[(long long)(bx + tyy + i * 8) * R + by + txx] = t[txx][tyy + i * 8];
}

// ---------------- RoPE on q and k, in place, [B,H,S,hd] ----------------
__global__ void rope_kernel(const float* __restrict__ cosT,
                            const float* __restrict__ sinT)
{
    const long long idx = (long long)blockIdx.x * 256 + threadIdx.x;
    const int i = (int)(idx & 63);
    const int s = (int)((idx >> 6) & 2047);
    const int z = (int)(idx >> 17);
    const float c  = cosT[s * 64 + i];
    const float sn = sinT[s * 64 + i];
    const long long base = ((long long)z * S_ + s) * HD_;
    float q1 = g_q[base + i], q2 = g_q[base + 64 + i];
    g_q[base + i]      = q1 * c - q2 * sn;
    g_q[base + 64 + i] = q1 * sn + q2 * c;
    float k1 = g_k[base + i], k2 = g_k[base + 64 + i];
    g_k[base + i]      = k1 * c - k2 * sn;
    g_k[base + 64 + i] = k1 * sn + k2 * c;
}

// ---------------- causal row softmax over g_scores, in place ----------------
__global__ void softmax_kernel()
{
    const int q = blockIdx.x;
    const int z = blockIdx.y;
    float* row = g_scores + ((long long)z * S_ + q) * S_;
    const int len = q + 1;
    const int tid = threadIdx.x;

    __shared__ float red[256];

    float m = -1e30f;
    for (int k = tid; k < len; k += 256) m = fmaxf(m, row[k]);
    red[tid] = m; __syncthreads();
    for (int s = 128; s > 0; s >>= 1) {
        if (tid < s) red[tid] = fmaxf(red[tid], red[tid + s]);
        __syncthreads();
    }
    m = red[0];
    __syncthreads();

    float sum = 0.f;
    for (int k = tid; k < len; k += 256) {
        float e = __expf(row[k] - m);
        row[k] = e;
        sum += e;
    }
    red[tid] = sum; __syncthreads();
    for (int s = 128; s > 0; s >>= 1) {
        if (tid < s) red[tid] += red[tid + s];
        __syncthreads();
    }
    const float inv = 1.0f / red[0];

    for (int k = tid; k < len; k += 256) row[k] *= inv;

    const int kend = ((q >> 7) + 1) << 7;
    for (int k = len + tid; k < kend; k += 256) row[k] = 0.f;
}

// ---------------- launch ----------------
extern "C" void kernel_launch(void* const* d_in, const int* in_sizes, int n_in,
                              void* d_out, int out_size)
{
    const float* x     = (const float*)d_in[0]; // [4,2048,2048]
    const float* cosT  = (const float*)d_in[1]; // [2048,64]
    const float* sinT  = (const float*)d_in[2]; // [2048,64]
    const float* w_qkv = (const float*)d_in[3]; // [2048,6144]
    const float* w_out = (const float*)d_in[4]; // [2048,2048]
    float* out = (float*)d_out;                 // [4,2048,2048]
    (void)in_sizes; (void)n_in; (void)out_size;

    float *qp, *kp, *vp, *sp, *ap, *wqT, *woT;
    cudaGetSymbolAddress((void**)&qp, g_q);
    cudaGetSymbolAddress((void**)&kp, g_k);
    cudaGetSymbolAddress((void**)&vp, g_v);
    cudaGetSymbolAddress((void**)&sp, g_scores);
    cudaGetSymbolAddress((void**)&ap, g_attn);
    cudaGetSymbolAddress((void**)&wqT, g_wqkvT);
    cudaGetSymbolAddress((void**)&woT, g_woutT);

    cudaFuncSetAttribute(gemm_tc<0, false>, cudaFuncAttributeMaxDynamicSharedMemorySize, SMEM_GEMM_BYTES);
    cudaFuncSetAttribute(gemm_tc<1, false>, cudaFuncAttributeMaxDynamicSharedMemorySize, SMEM_GEMM_BYTES);
    cudaFuncSetAttribute(gemm_tc<2, false>, cudaFuncAttributeMaxDynamicSharedMemorySize, SMEM_GEMM_BYTES);
    cudaFuncSetAttribute(gemm_tc<3, true>,  cudaFuncAttributeMaxDynamicSharedMemorySize, SMEM_GEMM_BYTES);

    const long long SHD = (long long)S_ * HD_;   // per-(b,h) q/k/v stride
    const long long SS  = (long long)S_ * S_;    // per-(b,h) scores stride

    // 0) transpose weights to [N,K]
    transpose_f32<<<dim3(6144 / 32, 2048 / 32), dim3(32, 8)>>>(w_qkv, wqT, 2048, 6144);
    transpose_f32<<<dim3(2048 / 32, 2048 / 32), dim3(32, 8)>>>(w_out, woT, 2048, 2048);

    // 1) QKV projection: x[8192,2048] @ w_qkvT[6144,2048]^T, scatter q/k/vT
    gemm_tc<1, false><<<dim3(48, 64, 1), 256, SMEM_GEMM_BYTES>>>(
        x, wqT, nullptr, 2048, 2048, 2048, 0, 0, 0, 0);

    // 2) RoPE
    rope_kernel<<<(Bb_ * H_ * S_ * (HD_ / 2)) / 256, 256>>>(cosT, sinT);

    // 3) scores = (Q @ K^T) * scale, causal mask, block-skip above diagonal
    gemm_tc<2, false><<<dim3(16, 16, 64), 256, SMEM_GEMM_BYTES>>>(
        qp, kp, sp, 128, 128, 128, 2048, SHD, SHD, SS);

    // 4) causal softmax rows
    softmax_kernel<<<dim3(S_, Bb_ * H_), 256>>>();

    // 5) attn = P @ V (V stored transposed; causal K-limit), scatter [B,S,D]
    gemm_tc<3, true><<<dim3(1, 16, 64), 256, SMEM_GEMM_BYTES>>>(
        sp, vp, nullptr, 2048, 2048, 2048, 0, SS, SHD, 0);

    // 6) out = attn @ w_outT^T
    gemm_tc<0, false><<<dim3(16, 64, 1), 256, SMEM_GEMM_BYTES>>>(
        ap, woT, out, 2048, 2048, 2048, 2048, 0, 0, 0);
}

// round 10
// speedup vs baseline: 2.2874x; 1.2309x over previous
#include <cuda_runtime.h>
#include <cuda_bf16.h>
#include <cstdint>
#include <math.h>

// Problem constants: B=4, S=2048, D=2048, H=16, hd=128
#define Bb_ 4
#define S_  2048
#define H_  16
#define HD_ 128
#define D_  2048

// ---------------- scratch (device globals; allocation-free) ----------------
__device__ float g_q[16777216];          // [B,H,S,hd] fp32 (pre-rope)
__device__ float g_k[16777216];          // [B,H,S,hd] fp32 (pre-rope)
__device__ __nv_bfloat16 g_qh[16777216]; // [B,H,S,hd] post-rope hi
__device__ __nv_bfloat16 g_ql[16777216]; // post-rope lo
__device__ __nv_bfloat16 g_kh[16777216];
__device__ __nv_bfloat16 g_kl[16777216];
__device__ __nv_bfloat16 g_vh[16777216]; // [B,H,S,hd] hi
__device__ __nv_bfloat16 g_vl[16777216]; // lo
__device__ float g_attn[16777216];       // [B,S,D]
__device__ float g_wqkvT[12582912];      // [6144,2048]
__device__ float g_woutT[4194304];       // [2048,2048]

// ---------------- helpers ----------------
__device__ __forceinline__ uint32_t smem_u32(const void* p) {
    uint32_t a;
    asm("{ .reg .u64 t; cvta.to.shared.u64 t, %1; cvt.u32.u64 %0, t; }" : "=r"(a) : "l"(p));
    return a;
}
__device__ __forceinline__ void ldsm4(uint32_t* r, uint32_t addr) {
    asm volatile("ldmatrix.sync.aligned.m8n8.x4.shared.b16 {%0,%1,%2,%3}, [%4];"
                 : "=r"(r[0]), "=r"(r[1]), "=r"(r[2]), "=r"(r[3]) : "r"(addr));
}
__device__ __forceinline__ void ldsm4t(uint32_t* r, uint32_t addr) {
    asm volatile("ldmatrix.sync.aligned.m8n8.x4.trans.shared.b16 {%0,%1,%2,%3}, [%4];"
                 : "=r"(r[0]), "=r"(r[1]), "=r"(r[2]), "=r"(r[3]) : "r"(addr));
}
__device__ __forceinline__ void mma_bf16(float* c, const uint32_t* a, uint32_t b0, uint32_t b1) {
    asm volatile(
        "mma.sync.aligned.m16n8k16.row.col.f32.bf16.bf16.f32 "
        "{%0,%1,%2,%3}, {%4,%5,%6,%7}, {%8,%9}, {%0,%1,%2,%3};"
        : "+f"(c[0]), "+f"(c[1]), "+f"(c[2]), "+f"(c[3])
        : "r"(a[0]), "r"(a[1]), "r"(a[2]), "r"(a[3]), "r"(b0), "r"(b1));
}
__device__ __forceinline__ uint32_t sw128(uint32_t off) { return off ^ ((off >> 3) & 0x70); }
__device__ __forceinline__ void cpa16(uint32_t dst, const void* src) {
    asm volatile("cp.async.cg.shared.global [%0], [%1], 16;" :: "r"(dst), "l"(src));
}
__device__ __forceinline__ void cpa_commit() { asm volatile("cp.async.commit_group;" ::: "memory"); }
__device__ __forceinline__ void cpa_wait0()  { asm volatile("cp.async.wait_group 0;" ::: "memory"); }
__device__ __forceinline__ float ex2(float x) {
    float r; asm("ex2.approx.f32 %0, %1;" : "=f"(r) : "f"(x)); return r;
}
__device__ __forceinline__ uint32_t packbf(float a, float b) {
    __nv_bfloat16 ha = __float2bfloat16(a), hb = __float2bfloat16(b);
    return (uint32_t)__bfloat16_as_ushort(ha) | ((uint32_t)__bfloat16_as_ushort(hb) << 16);
}

// ---------------- bf16x2 mma.sync TN GEMM (projections) ----------------
// C[M,N] = A[M,K] @ B[N,K]^T, fp32 in, split into bf16 hi/lo, 3 passes.
// Block 128x128, 8 warps (4x2), warp tile 32x64, K chunk 64.
// MODE: 0 = plain C write, 1 = qkv scatter (q,k fp32; v bf16 hi/lo)
#define SMEM_GEMM_BYTES 132096
#define TOFF(buf, which) (1024u + (uint32_t)(buf) * 65536u + (uint32_t)(which) * 16384u)

__device__ __forceinline__ void split_pack_store(float4 v, char* hi, char* lo, uint32_t sw) {
    __nv_bfloat16 hx = __float2bfloat16(v.x), hy = __float2bfloat16(v.y);
    __nv_bfloat16 hz = __float2bfloat16(v.z), hw = __float2bfloat16(v.w);
    uint32_t h01 = (uint32_t)__bfloat16_as_ushort(hx) | ((uint32_t)__bfloat16_as_ushort(hy) << 16);
    uint32_t h23 = (uint32_t)__bfloat16_as_ushort(hz) | ((uint32_t)__bfloat16_as_ushort(hw) << 16);
    *(uint2*)(hi + sw) = make_uint2(h01, h23);
    __nv_bfloat16 lx = __float2bfloat16(v.x - __bfloat162float(hx));
    __nv_bfloat16 ly = __float2bfloat16(v.y - __bfloat162float(hy));
    __nv_bfloat16 lz = __float2bfloat16(v.z - __bfloat162float(hz));
    __nv_bfloat16 lw = __float2bfloat16(v.w - __bfloat162float(hw));
    uint32_t l01 = (uint32_t)__bfloat16_as_ushort(lx) | ((uint32_t)__bfloat16_as_ushort(ly) << 16);
    uint32_t l23 = (uint32_t)__bfloat16_as_ushort(lz) | ((uint32_t)__bfloat16_as_ushort(lw) << 16);
    *(uint2*)(lo + sw) = make_uint2(l01, l23);
}

__device__ __forceinline__ void load_chunk_direct(const float* __restrict__ src, int ld,
                                                  int row0, int kbase,
                                                  char* hi, char* lo, int t) {
    const int rp = t >> 4, cf = t & 15;
    const float* p = src + (long long)(row0 + rp) * ld + kbase + cf * 4;
#pragma unroll
    for (int pass = 0; pass < 8; ++pass) {
        float4 v = *(const float4*)p;
        p += (long long)16 * ld;
        uint32_t sw = sw128((rp + pass * 16) * 128 + cf * 8);
        split_pack_store(v, hi, lo, sw);
    }
}

template<int MODE>
__global__ __launch_bounds__(256, 1)
void gemm_tc(const float* __restrict__ A, const float* __restrict__ Bm,
             float* __restrict__ C, int K, int lda, int ldb, int ldc)
{
    const int m0 = blockIdx.y * 128;
    const int n0 = blockIdx.x * 128;
    const int nchunks = K >> 6;

    extern __shared__ char smem[];
    const uint32_t sb = smem_u32(smem);
    const int tid = threadIdx.x;
    const int wid = tid >> 5;
    const int lane = tid & 31;
    const int wm = (wid & 3) * 32;
    const int wn = (wid >> 2) * 64;
    const int lq = lane >> 3, lr = lane & 7;

    const int a_row = wm + (lq & 1) * 8 + lr;
    const int a_kc2 = (lq >> 1) * 16;
    const int b_row = wn + (lq >> 1) * 8 + lr;
    const int b_kc2 = (lq & 1) * 16;
    const int rp = tid >> 4, cf = tid & 15;

    float acc[2][8][4];
#pragma unroll
    for (int i = 0; i < 2; i++)
#pragma unroll
        for (int j = 0; j < 8; j++)
#pragma unroll
            for (int e = 0; e < 4; e++) acc[i][j][e] = 0.f;

    load_chunk_direct(A, lda, m0, 0, smem + TOFF(0, 0), smem + TOFF(0, 1), tid);
    load_chunk_direct(Bm, ldb, n0, 0, smem + TOFF(0, 2), smem + TOFF(0, 3), tid);
    __syncthreads();

    for (int c = 0; c < nchunks; ++c) {
        const int buf = c & 1;
        const bool pf = (c + 1 < nchunks);
        float4 areg[8], breg[8];
        if (pf) {
            const int kb = (c + 1) * 64;
            const float* pa = A + (long long)(m0 + rp) * lda + kb + cf * 4;
            const float* pb = Bm + (long long)(n0 + rp) * ldb + kb + cf * 4;
#pragma unroll
            for (int p = 0; p < 8; ++p) {
                areg[p] = *(const float4*)pa; pa += (long long)16 * lda;
                breg[p] = *(const float4*)pb; pb += (long long)16 * ldb;
            }
        }
        const uint32_t sAhi = sb + TOFF(buf, 0), sAlo = sb + TOFF(buf, 1);
        const uint32_t sBhi = sb + TOFF(buf, 2), sBlo = sb + TOFF(buf, 3);
#pragma unroll
        for (int kk = 0; kk < 4; ++kk) {
            uint32_t ahi[2][4], alo[2][4], bhi[4][4], blo[4][4];
#pragma unroll
            for (int i = 0; i < 2; ++i) {
                uint32_t sw = sw128((a_row + i * 16) * 128 + kk * 32 + a_kc2);
                ldsm4(ahi[i], sAhi + sw);
                ldsm4(alo[i], sAlo + sw);
            }
#pragma unroll
            for (int jp = 0; jp < 4; ++jp) {
                uint32_t sw = sw128((b_row + jp * 16) * 128 + kk * 32 + b_kc2);
                ldsm4(bhi[jp], sBhi + sw);
                ldsm4(blo[jp], sBlo + sw);
            }
#pragma unroll
            for (int i = 0; i < 2; ++i)
#pragma unroll
                for (int jp = 0; jp < 4; ++jp) {
                    mma_bf16(acc[i][2 * jp],     ahi[i], bhi[jp][0], bhi[jp][1]);
                    mma_bf16(acc[i][2 * jp + 1], ahi[i], bhi[jp][2], bhi[jp][3]);
                    mma_bf16(acc[i][2 * jp],     ahi[i], blo[jp][0], blo[jp][1]);
                    mma_bf16(acc[i][2 * jp + 1], ahi[i], blo[jp][2], blo[jp][3]);
                    mma_bf16(acc[i][2 * jp],     alo[i], bhi[jp][0], bhi[jp][1]);
                    mma_bf16(acc[i][2 * jp + 1], alo[i], bhi[jp][2], bhi[jp][3]);
                }
        }
        __syncthreads();
        if (pf) {
            const int nb = buf ^ 1;
            char* Ahi = smem + TOFF(nb, 0); char* Alo = smem + TOFF(nb, 1);
            char* Bhi = smem + TOFF(nb, 2); char* Blo = smem + TOFF(nb, 3);
#pragma unroll
            for (int p = 0; p < 8; ++p) {
                uint32_t sw = sw128((rp + p * 16) * 128 + cf * 8);
                split_pack_store(areg[p], Ahi, Alo, sw);
                split_pack_store(breg[p], Bhi, Blo, sw);
            }
            __syncthreads();
        }
    }

    const int lm = lane >> 2;
    const int ln = (lane & 3) * 2;
#pragma unroll
    for (int i = 0; i < 2; ++i) {
#pragma unroll
        for (int j = 0; j < 8; ++j) {
            const int gn = n0 + wn + j * 8 + ln;
#pragma unroll
            for (int half = 0; half < 2; ++half) {
                const int gm = m0 + wm + i * 16 + lm + half * 8;
                float v0 = acc[i][j][half * 2 + 0];
                float v1 = acc[i][j][half * 2 + 1];
                if (MODE == 0) {
                    *(float2*)(C + (long long)gm * ldc + gn) = make_float2(v0, v1);
                } else {
                    const int t = gn >> 11, h = (gn >> 7) & 15, d = gn & 127;
                    const int b = gm >> 11, s = gm & 2047;
                    const long long idx = ((long long)(b * H_ + h) * S_ + s) * HD_ + d;
                    if (t == 0)      *(float2*)(g_q + idx) = make_float2(v0, v1);
                    else if (t == 1) *(float2*)(g_k + idx) = make_float2(v0, v1);
                    else {
                        __nv_bfloat16 h0 = __float2bfloat16(v0), h1 = __float2bfloat16(v1);
                        *(uint32_t*)(g_vh + idx) =
                            (uint32_t)__bfloat16_as_ushort(h0) | ((uint32_t)__bfloat16_as_ushort(h1) << 16);
                        __nv_bfloat16 l0 = __float2bfloat16(v0 - __bfloat162float(h0));
                        __nv_bfloat16 l1 = __float2bfloat16(v1 - __bfloat162float(h1));
                        *(uint32_t*)(g_vl + idx) =
                            (uint32_t)__bfloat16_as_ushort(l0) | ((uint32_t)__bfloat16_as_ushort(l1) << 16);
                    }
                }
            }
        }
    }
}

// ---------------- fp32 tile transpose ----------------
__global__ void transpose_f32(const float* __restrict__ src, float* __restrict__ dst,
                              int R, int Cc)
{
    __shared__ float t[32][33];
    const int bx = blockIdx.x * 32, by = blockIdx.y * 32;
    const int txx = threadIdx.x, tyy = threadIdx.y;
#pragma unroll
    for (int i = 0; i < 4; ++i)
        t[tyy + i * 8][txx] = src[(long long)(by + tyy + i * 8) * Cc + bx + txx];
    __syncthreads();
#pragma unroll
    for (int i = 0; i < 4; ++i)
        dst[(long long)(bx + tyy + i * 8) * R + by + txx] = t[txx][tyy + i * 8];
}

// ---------------- RoPE + bf16 hi/lo split for Q,K ----------------
__global__ void rope_split(const float* __restrict__ cosT, const float* __restrict__ sinT)
{
    const long long idx = (long long)blockIdx.x * 256 + threadIdx.x;
    const int i = (int)(idx & 63);
    const int s = (int)((idx >> 6) & 2047);
    const int z = (int)(idx >> 17);
    const float c  = cosT[s * 64 + i];
    const float sn = sinT[s * 64 + i];
    const long long base = ((long long)z * S_ + s) * HD_;

    float q1 = g_q[base + i], q2 = g_q[base + 64 + i];
    float qa = q1 * c - q2 * sn, qb = q1 * sn + q2 * c;
    __nv_bfloat16 h;
    h = __float2bfloat16(qa); g_qh[base + i] = h;      g_ql[base + i]      = __float2bfloat16(qa - __bfloat162float(h));
    h = __float2bfloat16(qb); g_qh[base + 64 + i] = h; g_ql[base + 64 + i] = __float2bfloat16(qb - __bfloat162float(h));

    float k1 = g_k[base + i], k2 = g_k[base + 64 + i];
    float ka = k1 * c - k2 * sn, kb = k1 * sn + k2 * c;
    h = __float2bfloat16(ka); g_kh[base + i] = h;      g_kl[base + i]      = __float2bfloat16(ka - __bfloat162float(h));
    h = __float2bfloat16(kb); g_kh[base + 64 + i] = h; g_kl[base + 64 + i] = __float2bfloat16(kb - __bfloat162float(h));
}

// ---------------- fused flash attention ----------------
// CTA: (q-tile 128, bh). 8 warps x 16 q-rows. K/V chunks of 64 rows,
// double-buffered cp.async. Q resident in smem. Scores in registers;
// MMA1 C-frag repacked in place as MMA2 A-frag. hi/lo split everywhere.
// smem: Q hi[2 x 16KB] lo[2 x 16KB] = 64KB at 0;
//       KV buf b at 65536+b*65536: Khi 16KB, Klo 16KB, Vhi 16KB, Vlo 16KB.
#define FA_SMEM 196608

__device__ __forceinline__ void fa_load_kv(uint32_t kvbase, int bh, int s0, int tid) {
#pragma unroll
    for (int p = 0; p < 4; ++p) {
        const int g = tid + p * 256;          // 0..1023
        const int row = g >> 4;               // 0..63
        const int b16i = g & 15;
        const uint32_t byte = b16i * 16;
        const long long srcoff = (((long long)(bh << 11) + s0 + row) << 7) + b16i * 8;
        const uint32_t dst = kvbase + (byte >> 7) * 8192 + sw128(row * 128 + (byte & 127));
        cpa16(dst,         g_kh + srcoff);
        cpa16(dst + 16384, g_kl + srcoff);
        cpa16(dst + 32768, g_vh + srcoff);
        cpa16(dst + 49152, g_vl + srcoff);
    }
}

__global__ __launch_bounds__(256, 1)
void flash_attn()
{
    const int qt = 15 - blockIdx.x;           // big tiles first
    const int q0 = qt << 7;
    const int bh = blockIdx.y;
    const int nch = (qt + 1) * 2;

    extern __shared__ char smem[];
    const uint32_t sb = smem_u32(smem);
    const int tid = threadIdx.x;
    const int w = tid >> 5;
    const int lane = tid & 31;
    const int wq = w * 16;
    const int lq = lane >> 3, lr = lane & 7;
    const int lc = lane & 3;                  // col pair index
    const int lrow = lane >> 2;               // row within 8

    // ---- prologue: load Q (hi/lo) + chunk 0 ----
#pragma unroll
    for (int p = 0; p < 8; ++p) {
        const int g = tid + p * 256;          // 0..2047
        const int row = g >> 4;               // 0..127
        const int b16i = g & 15;
        const uint32_t byte = b16i * 16;
        const long long srcoff = (((long long)(bh << 11) + q0 + row) << 7) + b16i * 8;
        const uint32_t dst = sb + (byte >> 7) * 16384 + sw128(row * 128 + (byte & 127));
        cpa16(dst,         g_qh + srcoff);
        cpa16(dst + 32768, g_ql + srcoff);
    }
    fa_load_kv(sb + 65536, bh, 0, tid);
    cpa_commit();
    cpa_wait0();
    __syncthreads();

    const float C = 0.08838834764831845f * 1.4426950408889634f; // scale*log2(e)
    float o[16][4];
#pragma unroll
    for (int t = 0; t < 16; ++t)
#pragma unroll
        for (int e = 0; e < 4; ++e) o[t][e] = 0.f;
    float m0 = -1e30f, m1 = -1e30f, l0 = 0.f, l1 = 0.f;

    for (int c = 0; c < nch; ++c) {
        const uint32_t kvb = sb + 65536 + (uint32_t)(c & 1) * 65536;
        if (c + 1 < nch) {
            fa_load_kv(sb + 65536 + (uint32_t)((c + 1) & 1) * 65536, bh, (c + 1) * 64, tid);
            cpa_commit();
        }

        // ---- MMA1: scores[16q x 64k] ----
        float s[8][4];
#pragma unroll
        for (int j = 0; j < 8; ++j)
#pragma unroll
            for (int e = 0; e < 4; ++e) s[j][e] = 0.f;

#pragma unroll
        for (int kk = 0; kk < 8; ++kk) {
            const int arow = wq + (lq & 1) * 8 + lr;
            const uint32_t akb = kk * 32 + (lq >> 1) * 16;
            const uint32_t qaddr = sb + (akb >> 7) * 16384 + sw128(arow * 128 + (akb & 127));
            uint32_t ahi[4], alo[4];
            ldsm4(ahi, qaddr);
            ldsm4(alo, qaddr + 32768);
#pragma unroll
            for (int nt = 0; nt < 4; ++nt) {
                const int brow = nt * 16 + (lq >> 1) * 8 + lr;
                const uint32_t bkb = kk * 32 + (lq & 1) * 16;
                const uint32_t kaddr = kvb + (bkb >> 7) * 8192 + sw128(brow * 128 + (bkb & 127));
                uint32_t bh4[4], bl4[4];
                ldsm4(bh4, kaddr);
                ldsm4(bl4, kaddr + 16384);
                mma_bf16(s[2 * nt],     ahi, bh4[0], bh4[1]);
                mma_bf16(s[2 * nt + 1], ahi, bh4[2], bh4[3]);
                mma_bf16(s[2 * nt],     ahi, bl4[0], bl4[1]);
                mma_bf16(s[2 * nt + 1], ahi, bl4[2], bl4[3]);
                mma_bf16(s[2 * nt],     alo, bh4[0], bh4[1]);
                mma_bf16(s[2 * nt + 1], alo, bh4[2], bh4[3]);
            }
        }

        // ---- causal mask (only near diagonal) ----
        if (c * 64 + 63 > q0 + wq) {
            const int r0g = q0 + wq + lrow;
#pragma unroll
            for (int j = 0; j < 8; ++j) {
                const int k0 = c * 64 + 8 * j + 2 * lc;
                if (k0 > r0g)         s[j][0] = -1e30f;
                if (k0 + 1 > r0g)     s[j][1] = -1e30f;
                if (k0 > r0g + 8)     s[j][2] = -1e30f;
                if (k0 + 1 > r0g + 8) s[j][3] = -1e30f;
            }
        }

        // ---- online softmax update ----
        float mx0 = -1e30f, mx1 = -1e30f;
#pragma unroll
        for (int j = 0; j < 8; ++j) {
            mx0 = fmaxf(mx0, fmaxf(s[j][0], s[j][1]));
            mx1 = fmaxf(mx1, fmaxf(s[j][2], s[j][3]));
        }
        mx0 = fmaxf(mx0, __shfl_xor_sync(0xffffffffu, mx0, 1));
        mx0 = fmaxf(mx0, __shfl_xor_sync(0xffffffffu, mx0, 2));
        mx1 = fmaxf(mx1, __shfl_xor_sync(0xffffffffu, mx1, 1));
        mx1 = fmaxf(mx1, __shfl_xor_sync(0xffffffffu, mx1, 2));
        const float mn0 = fmaxf(m0, mx0), mn1 = fmaxf(m1, mx1);
        const float al0 = ex2((m0 - mn0) * C), al1 = ex2((m1 - mn1) * C);
        m0 = mn0; m1 = mn1;
        l0 *= al0; l1 *= al1;
#pragma unroll
        for (int t = 0; t < 16; ++t) {
            o[t][0] *= al0; o[t][1] *= al0; o[t][2] *= al1; o[t][3] *= al1;
        }
        uint32_t ph[8][2], pl[8][2];
#pragma unroll
        for (int j = 0; j < 8; ++j) {
            float p0 = ex2((s[j][0] - m0) * C);
            float p1 = ex2((s[j][1] - m0) * C);
            float p2 = ex2((s[j][2] - m1) * C);
            float p3 = ex2((s[j][3] - m1) * C);
            l0 += p0 + p1; l1 += p2 + p3;
            __nv_bfloat16 h0 = __float2bfloat16(p0), h1 = __float2bfloat16(p1);
            __nv_bfloat16 h2 = __float2bfloat16(p2), h3 = __float2bfloat16(p3);
            ph[j][0] = (uint32_t)__bfloat16_as_ushort(h0) | ((uint32_t)__bfloat16_as_ushort(h1) << 16);
            ph[j][1] = (uint32_t)__bfloat16_as_ushort(h2) | ((uint32_t)__bfloat16_as_ushort(h3) << 16);
            pl[j][0] = packbf(p0 - __bfloat162float(h0), p1 - __bfloat162float(h1));
            pl[j][1] = packbf(p2 - __bfloat162float(h2), p3 - __bfloat162float(h3));
        }

        // ---- MMA2: O += P @ V (V via trans ldmatrix from [s,hd]) ----
#pragma unroll
        for (int kk = 0; kk < 4; ++kk) {
            uint32_t pa_h[4] = { ph[2 * kk][0], ph[2 * kk][1], ph[2 * kk + 1][0], ph[2 * kk + 1][1] };
            uint32_t pa_l[4] = { pl[2 * kk][0], pl[2 * kk][1], pl[2 * kk + 1][0], pl[2 * kk + 1][1] };
#pragma unroll
            for (int nt = 0; nt < 8; ++nt) {
                const int vrow = kk * 16 + (lq & 1) * 8 + lr;
                const uint32_t nb = nt * 32 + (lq >> 1) * 16;
                const uint32_t vaddr = kvb + 32768 + (nb >> 7) * 8192 + sw128(vrow * 128 + (nb & 127));
                uint32_t vh4[4], vl4[4];
                ldsm4t(vh4, vaddr);
                ldsm4t(vl4, vaddr + 16384);
                mma_bf16(o[2 * nt],     pa_h, vh4[0], vh4[1]);
                mma_bf16(o[2 * nt + 1], pa_h, vh4[2], vh4[3]);
                mma_bf16(o[2 * nt],     pa_h, vl4[0], vl4[1]);
                mma_bf16(o[2 * nt + 1], pa_h, vl4[2], vl4[3]);
                mma_bf16(o[2 * nt],     pa_l, vh4[0], vh4[1]);
                mma_bf16(o[2 * nt + 1], pa_l, vh4[2], vh4[3]);
            }
        }

        cpa_wait0();
        __syncthreads();
    }

    // ---- finalize: normalize by row sum, write [B,S,D] ----
    l0 += __shfl_xor_sync(0xffffffffu, l0, 1);
    l0 += __shfl_xor_sync(0xffffffffu, l0, 2);
    l1 += __shfl_xor_sync(0xffffffffu, l1, 1);
    l1 += __shfl_xor_sync(0xffffffffu, l1, 2);
    const float inv0 = 1.f / l0, inv1 = 1.f / l1;

    const int b = bh >> 4, h = bh & 15;
    const int row0 = q0 + wq + lrow;
    float* dst0 = g_attn + ((long long)(b * S_ + row0) * D_) + h * HD_ + 2 * lc;
    float* dst1 = dst0 + (long long)8 * D_;
#pragma unroll
    for (int t = 0; t < 16; ++t) {
        *(float2*)(dst0 + 8 * t) = make_float2(o[t][0] * inv0, o[t][1] * inv0);
        *(float2*)(dst1 + 8 * t) = make_float2(o[t][2] * inv1, o[t][3] * inv1);
    }
}

// ---------------- launch ----------------
extern "C" void kernel_launch(void* const* d_in, const int* in_sizes, int n_in,
                              void* d_out, int out_size)
{
    const float* x     = (const float*)d_in[0]; // [4,2048,2048]
    const float* cosT  = (const float*)d_in[1]; // [2048,64]
    const float* sinT  = (const float*)d_in[2]; // [2048,64]
    const float* w_qkv = (const float*)d_in[3]; // [2048,6144]
    const float* w_out = (const float*)d_in[4]; // [2048,2048]
    float* out = (float*)d_out;                 // [4,2048,2048]
    (void)in_sizes; (void)n_in; (void)out_size;

    float *ap, *wqT, *woT;
    cudaGetSymbolAddress((void**)&ap, g_attn);
    cudaGetSymbolAddress((void**)&wqT, g_wqkvT);
    cudaGetSymbolAddress((void**)&woT, g_woutT);

    cudaFuncSetAttribute(gemm_tc<0>, cudaFuncAttributeMaxDynamicSharedMemorySize, SMEM_GEMM_BYTES);
    cudaFuncSetAttribute(gemm_tc<1>, cudaFuncAttributeMaxDynamicSharedMemorySize, SMEM_GEMM_BYTES);
    cudaFuncSetAttribute(flash_attn, cudaFuncAttributeMaxDynamicSharedMemorySize, FA_SMEM);

    // 0) transpose weights to [N,K]
    transpose_f32<<<dim3(6144 / 32, 2048 / 32), dim3(32, 8)>>>(w_qkv, wqT, 2048, 6144);
    transpose_f32<<<dim3(2048 / 32, 2048 / 32), dim3(32, 8)>>>(w_out, woT, 2048, 2048);

    // 1) QKV projection; scatter q,k fp32 and v bf16 hi/lo
    gemm_tc<1><<<dim3(48, 64, 1), 256, SMEM_GEMM_BYTES>>>(
        x, wqT, nullptr, 2048, 2048, 2048, 0);

    // 2) RoPE + hi/lo split of q,k
    rope_split<<<(Bb_ * H_ * S_ * (HD_ / 2)) / 256, 256>>>(cosT, sinT);

    // 3) fused flash attention -> g_attn [B,S,D]
    flash_attn<<<dim3(16, Bb_ * H_), 256, FA_SMEM>>>();

    // 4) out = attn @ w_outT^T
    gemm_tc<0><<<dim3(16, 64, 1), 256, SMEM_GEMM_BYTES>>>(
        ap, woT, out, 2048, 2048, 2048, 2048);
}

// round 11
// speedup vs baseline: 3.1921x; 1.3955x over previous
#include <cuda_runtime.h>
#include <cuda_bf16.h>
#include <cstdint>
#include <math.h>

// Problem constants: B=4, S=2048, D=2048, H=16, hd=128
#define Bb_ 4
#define S_  2048
#define H_  16
#define HD_ 128
#define D_  2048

// ---------------- scratch (device globals; allocation-free) ----------------
__device__ float g_q[16777216];          // [B,H,S,hd] fp32 (pre-rope)
__device__ float g_k[16777216];          // [B,H,S,hd] fp32 (pre-rope)
__device__ __nv_bfloat16 g_qh[16777216]; // [B,H,S,hd] post-rope hi
__device__ __nv_bfloat16 g_ql[16777216]; // post-rope lo
__device__ __nv_bfloat16 g_kh[16777216];
__device__ __nv_bfloat16 g_kl[16777216];
__device__ __nv_bfloat16 g_vh[16777216]; // [B,H,S,hd] hi
__device__ __nv_bfloat16 g_vl[16777216]; // lo
__device__ __nv_bfloat16 g_xh[16777216]; // x split [8192,2048]
__device__ __nv_bfloat16 g_xl[16777216];
__device__ __nv_bfloat16 g_wqh[12582912]; // w_qkv^T split [6144,2048]
__device__ __nv_bfloat16 g_wql[12582912];
__device__ __nv_bfloat16 g_woh[4194304];  // w_out^T split [2048,2048]
__device__ __nv_bfloat16 g_wol[4194304];
__device__ __nv_bfloat16 g_ah[16777216];  // attn split [B,S,D]
__device__ __nv_bfloat16 g_al[16777216];

// ---------------- helpers ----------------
__device__ __forceinline__ uint32_t smem_u32(const void* p) {
    uint32_t a;
    asm("{ .reg .u64 t; cvta.to.shared.u64 t, %1; cvt.u32.u64 %0, t; }" : "=r"(a) : "l"(p));
    return a;
}
__device__ __forceinline__ void ldsm4(uint32_t* r, uint32_t addr) {
    asm volatile("ldmatrix.sync.aligned.m8n8.x4.shared.b16 {%0,%1,%2,%3}, [%4];"
                 : "=r"(r[0]), "=r"(r[1]), "=r"(r[2]), "=r"(r[3]) : "r"(addr));
}
__device__ __forceinline__ void ldsm4t(uint32_t* r, uint32_t addr) {
    asm volatile("ldmatrix.sync.aligned.m8n8.x4.trans.shared.b16 {%0,%1,%2,%3}, [%4];"
                 : "=r"(r[0]), "=r"(r[1]), "=r"(r[2]), "=r"(r[3]) : "r"(addr));
}
__device__ __forceinline__ void mma_bf16(float* c, const uint32_t* a, uint32_t b0, uint32_t b1) {
    asm volatile(
        "mma.sync.aligned.m16n8k16.row.col.f32.bf16.bf16.f32 "
        "{%0,%1,%2,%3}, {%4,%5,%6,%7}, {%8,%9}, {%0,%1,%2,%3};"
        : "+f"(c[0]), "+f"(c[1]), "+f"(c[2]), "+f"(c[3])
        : "r"(a[0]), "r"(a[1]), "r"(a[2]), "r"(a[3]), "r"(b0), "r"(b1));
}
__device__ __forceinline__ uint32_t sw128(uint32_t off) { return off ^ ((off >> 3) & 0x70); }
__device__ __forceinline__ void cpa16(uint32_t dst, const void* src) {
    asm volatile("cp.async.cg.shared.global [%0], [%1], 16;" :: "r"(dst), "l"(src));
}
__device__ __forceinline__ void cpa_commit() { asm volatile("cp.async.commit_group;" ::: "memory"); }
__device__ __forceinline__ void cpa_wait0()  { asm volatile("cp.async.wait_group 0;" ::: "memory"); }
__device__ __forceinline__ float ex2(float x) {
    float r; asm("ex2.approx.f32 %0, %1;" : "=f"(r) : "f"(x)); return r;
}
__device__ __forceinline__ uint32_t packbf(float a, float b) {
    __nv_bfloat16 ha = __float2bfloat16(a), hb = __float2bfloat16(b);
    return (uint32_t)__bfloat16_as_ushort(ha) | ((uint32_t)__bfloat16_as_ushort(hb) << 16);
}
__device__ __forceinline__ void store_split2(__nv_bfloat16* hi, __nv_bfloat16* lo,
                                             long long idx, float a, float b) {
    __nv_bfloat16 ha = __float2bfloat16(a), hb = __float2bfloat16(b);
    *(uint32_t*)(hi + idx) =
        (uint32_t)__bfloat16_as_ushort(ha) | ((uint32_t)__bfloat16_as_ushort(hb) << 16);
    *(uint32_t*)(lo + idx) = packbf(a - __bfloat162float(ha), b - __bfloat162float(hb));
}

// ---------------- one-time split kernels ----------------
__global__ void split_f32(const float* __restrict__ src,
                          __nv_bfloat16* __restrict__ hi, __nv_bfloat16* __restrict__ lo)
{
    const long long i = (long long)blockIdx.x * 256 + threadIdx.x;   // per float4
    float4 v = ((const float4*)src)[i];
    __nv_bfloat16 hx = __float2bfloat16(v.x), hy = __float2bfloat16(v.y);
    __nv_bfloat16 hz = __float2bfloat16(v.z), hw = __float2bfloat16(v.w);
    uint2 h;
    h.x = (uint32_t)__bfloat16_as_ushort(hx) | ((uint32_t)__bfloat16_as_ushort(hy) << 16);
    h.y = (uint32_t)__bfloat16_as_ushort(hz) | ((uint32_t)__bfloat16_as_ushort(hw) << 16);
    ((uint2*)hi)[i] = h;
    uint2 l;
    l.x = packbf(v.x - __bfloat162float(hx), v.y - __bfloat162float(hy));
    l.y = packbf(v.z - __bfloat162float(hz), v.w - __bfloat162float(hw));
    ((uint2*)lo)[i] = l;
}

// transpose + split: hi/lo[C][R] = split(src[R][C])
__global__ void transpose_split(const float* __restrict__ src,
                                __nv_bfloat16* __restrict__ hi, __nv_bfloat16* __restrict__ lo,
                                int R, int Cc)
{
    __shared__ float t[32][33];
    const int bx = blockIdx.x * 32, by = blockIdx.y * 32;
    const int txx = threadIdx.x, tyy = threadIdx.y;
#pragma unroll
    for (int i = 0; i < 4; ++i)
        t[tyy + i * 8][txx] = src[(long long)(by + tyy + i * 8) * Cc + bx + txx];
    __syncthreads();
#pragma unroll
    for (int i = 0; i < 4; ++i) {
        float v = t[txx][tyy + i * 8];
        const long long idx = (long long)(bx + tyy + i * 8) * R + by + txx;
        __nv_bfloat16 h = __float2bfloat16(v);
        hi[idx] = h;
        lo[idx] = __float2bfloat16(v - __bfloat162float(h));
    }
}

// ---------------- pre-split bf16 mma.sync TN GEMM ----------------
// C[M,N] = (Ah+Al)[M,K] @ (Bh+Bl)[N,K]^T, 3 MMA passes, cp.async mainloop.
// Block 128x128, 8 warps (4x2), warp tile 32x64, K chunk 64.
// MODE: 0 = plain fp32 C write, 1 = qkv scatter (q,k fp32; v bf16 hi/lo)
#define SMEM_GEMM_BYTES 132096
#define TOFF(buf, which) (1024u + (uint32_t)(buf) * 65536u + (uint32_t)(which) * 16384u)

// one 128x64 bf16 tile -> SW128 smem via cp.async (256 threads, 4 per thread)
__device__ __forceinline__ void cpa_tile(uint32_t sdst, const __nv_bfloat16* __restrict__ src,
                                         int ld, int row0, int kbase, int tid) {
#pragma unroll
    for (int p = 0; p < 4; ++p) {
        const int g = tid + p * 256;         // 0..1023
        const int row = g >> 3;              // 0..127
        const int seg = g & 7;               // 16B segment
        cpa16(sdst + sw128(row * 128 + seg * 16),
              src + (long long)(row0 + row) * ld + kbase + seg * 8);
    }
}

template<int MODE>
__global__ __launch_bounds__(256, 1)
void gemm_bf(const __nv_bfloat16* __restrict__ Ah, const __nv_bfloat16* __restrict__ Al,
             const __nv_bfloat16* __restrict__ Bh, const __nv_bfloat16* __restrict__ Bl,
             float* __restrict__ C, int K, int lda, int ldb, int ldc)
{
    const int m0 = blockIdx.y * 128;
    const int n0 = blockIdx.x * 128;
    const int nchunks = K >> 6;

    extern __shared__ char smem[];
    const uint32_t sb = smem_u32(smem);
    const int tid = threadIdx.x;
    const int wid = tid >> 5;
    const int lane = tid & 31;
    const int wm = (wid & 3) * 32;
    const int wn = (wid >> 2) * 64;
    const int lq = lane >> 3, lr = lane & 7;

    const int a_row = wm + (lq & 1) * 8 + lr;
    const int a_kc2 = (lq >> 1) * 16;
    const int b_row = wn + (lq >> 1) * 8 + lr;
    const int b_kc2 = (lq & 1) * 16;

    float acc[2][8][4];
#pragma unroll
    for (int i = 0; i < 2; i++)
#pragma unroll
        for (int j = 0; j < 8; j++)
#pragma unroll
            for (int e = 0; e < 4; e++) acc[i][j][e] = 0.f;

    cpa_tile(sb + TOFF(0, 0), Ah, lda, m0, 0, tid);
    cpa_tile(sb + TOFF(0, 1), Al, lda, m0, 0, tid);
    cpa_tile(sb + TOFF(0, 2), Bh, ldb, n0, 0, tid);
    cpa_tile(sb + TOFF(0, 3), Bl, ldb, n0, 0, tid);
    cpa_commit();
    cpa_wait0();
    __syncthreads();

    for (int c = 0; c < nchunks; ++c) {
        const int buf = c & 1;
        const bool pf = (c + 1 < nchunks);
        if (pf) {
            const int nb = buf ^ 1;
            const int kb = (c + 1) * 64;
            cpa_tile(sb + TOFF(nb, 0), Ah, lda, m0, kb, tid);
            cpa_tile(sb + TOFF(nb, 1), Al, lda, m0, kb, tid);
            cpa_tile(sb + TOFF(nb, 2), Bh, ldb, n0, kb, tid);
            cpa_tile(sb + TOFF(nb, 3), Bl, ldb, n0, kb, tid);
            cpa_commit();
        }

        const uint32_t sAhi = sb + TOFF(buf, 0), sAlo = sb + TOFF(buf, 1);
        const uint32_t sBhi = sb + TOFF(buf, 2), sBlo = sb + TOFF(buf, 3);
#pragma unroll
        for (int kk = 0; kk < 4; ++kk) {
            uint32_t ahi[2][4], alo[2][4], bhi[4][4], blo[4][4];
#pragma unroll
            for (int i = 0; i < 2; ++i) {
                uint32_t sw = sw128((a_row + i * 16) * 128 + kk * 32 + a_kc2);
                ldsm4(ahi[i], sAhi + sw);
                ldsm4(alo[i], sAlo + sw);
            }
#pragma unroll
            for (int jp = 0; jp < 4; ++jp) {
                uint32_t sw = sw128((b_row + jp * 16) * 128 + kk * 32 + b_kc2);
                ldsm4(bhi[jp], sBhi + sw);
                ldsm4(blo[jp], sBlo + sw);
            }
#pragma unroll
            for (int i = 0; i < 2; ++i)
#pragma unroll
                for (int jp = 0; jp < 4; ++jp) {
                    mma_bf16(acc[i][2 * jp],     ahi[i], bhi[jp][0], bhi[jp][1]);
                    mma_bf16(acc[i][2 * jp + 1], ahi[i], bhi[jp][2], bhi[jp][3]);
                    mma_bf16(acc[i][2 * jp],     ahi[i], blo[jp][0], blo[jp][1]);
                    mma_bf16(acc[i][2 * jp + 1], ahi[i], blo[jp][2], blo[jp][3]);
                    mma_bf16(acc[i][2 * jp],     alo[i], bhi[jp][0], bhi[jp][1]);
                    mma_bf16(acc[i][2 * jp + 1], alo[i], bhi[jp][2], bhi[jp][3]);
                }
        }
        if (pf) cpa_wait0();
        __syncthreads();
    }

    const int lm = lane >> 2;
    const int ln = (lane & 3) * 2;
#pragma unroll
    for (int i = 0; i < 2; ++i) {
#pragma unroll
        for (int j = 0; j < 8; ++j) {
            const int gn = n0 + wn + j * 8 + ln;
#pragma unroll
            for (int half = 0; half < 2; ++half) {
                const int gm = m0 + wm + i * 16 + lm + half * 8;
                float v0 = acc[i][j][half * 2 + 0];
                float v1 = acc[i][j][half * 2 + 1];
                if (MODE == 0) {
                    *(float2*)(C + (long long)gm * ldc + gn) = make_float2(v0, v1);
                } else {
                    const int t = gn >> 11, h = (gn >> 7) & 15, d = gn & 127;
                    const int b = gm >> 11, s = gm & 2047;
                    const long long idx = ((long long)(b * H_ + h) * S_ + s) * HD_ + d;
                    if (t == 0)      *(float2*)(g_q + idx) = make_float2(v0, v1);
                    else if (t == 1) *(float2*)(g_k + idx) = make_float2(v0, v1);
                    else             store_split2(g_vh, g_vl, idx, v0, v1);
                }
            }
        }
    }
}

// ---------------- RoPE + bf16 hi/lo split for Q,K ----------------
__global__ void rope_split(const float* __restrict__ cosT, const float* __restrict__ sinT)
{
    const long long idx = (long long)blockIdx.x * 256 + threadIdx.x;
    const int i = (int)(idx & 63);
    const int s = (int)((idx >> 6) & 2047);
    const int z = (int)(idx >> 17);
    const float c  = cosT[s * 64 + i];
    const float sn = sinT[s * 64 + i];
    const long long base = ((long long)z * S_ + s) * HD_;

    float q1 = g_q[base + i], q2 = g_q[base + 64 + i];
    float qa = q1 * c - q2 * sn, qb = q1 * sn + q2 * c;
    __nv_bfloat16 h;
    h = __float2bfloat16(qa); g_qh[base + i] = h;      g_ql[base + i]      = __float2bfloat16(qa - __bfloat162float(h));
    h = __float2bfloat16(qb); g_qh[base + 64 + i] = h; g_ql[base + 64 + i] = __float2bfloat16(qb - __bfloat162float(h));

    float k1 = g_k[base + i], k2 = g_k[base + 64 + i];
    float ka = k1 * c - k2 * sn, kb = k1 * sn + k2 * c;
    h = __float2bfloat16(ka); g_kh[base + i] = h;      g_kl[base + i]      = __float2bfloat16(ka - __bfloat162float(h));
    h = __float2bfloat16(kb); g_kh[base + 64 + i] = h; g_kl[base + 64 + i] = __float2bfloat16(kb - __bfloat162float(h));
}

// ---------------- fused flash attention ----------------
// CTA: (q-tile 128, bh). 8 warps x 16 q-rows. K/V chunks of 64 rows,
// double-buffered cp.async. Q resident in smem. Scores in registers;
// MMA1 C-frag repacked in place as MMA2 A-frag. hi/lo split everywhere.
// Epilogue writes attn as bf16 hi/lo (feeds out-proj directly).
#define FA_SMEM 196608

__device__ __forceinline__ void fa_load_kv(uint32_t kvbase, int bh, int s0, int tid) {
#pragma unroll
    for (int p = 0; p < 4; ++p) {
        const int g = tid + p * 256;
        const int row = g >> 4;
        const int b16i = g & 15;
        const uint32_t byte = b16i * 16;
        const long long srcoff = (((long long)(bh << 11) + s0 + row) << 7) + b16i * 8;
        const uint32_t dst = kvbase + (byte >> 7) * 8192 + sw128(row * 128 + (byte & 127));
        cpa16(dst,         g_kh + srcoff);
        cpa16(dst + 16384, g_kl + srcoff);
        cpa16(dst + 32768, g_vh + srcoff);
        cpa16(dst + 49152, g_vl + srcoff);
    }
}

__global__ __launch_bounds__(256, 1)
void flash_attn()
{
    const int qt = 15 - blockIdx.x;
    const int q0 = qt << 7;
    const int bh = blockIdx.y;
    const int nch = (qt + 1) * 2;

    extern __shared__ char smem[];
    const uint32_t sb = smem_u32(smem);
    const int tid = threadIdx.x;
    const int w = tid >> 5;
    const int lane = tid & 31;
    const int wq = w * 16;
    const int lq = lane >> 3, lr = lane & 7;
    const int lc = lane & 3;
    const int lrow = lane >> 2;

#pragma unroll
    for (int p = 0; p < 8; ++p) {
        const int g = tid + p * 256;
        const int row = g >> 4;
        const int b16i = g & 15;
        const uint32_t byte = b16i * 16;
        const long long srcoff = (((long long)(bh << 11) + q0 + row) << 7) + b16i * 8;
        const uint32_t dst = sb + (byte >> 7) * 16384 + sw128(row * 128 + (byte & 127));
        cpa16(dst,         g_qh + srcoff);
        cpa16(dst + 32768, g_ql + srcoff);
    }
    fa_load_kv(sb + 65536, bh, 0, tid);
    cpa_commit();
    cpa_wait0();
    __syncthreads();

    const float C = 0.08838834764831845f * 1.4426950408889634f; // scale*log2(e)
    float o[16][4];
#pragma unroll
    for (int t = 0; t < 16; ++t)
#pragma unroll
        for (int e = 0; e < 4; ++e) o[t][e] = 0.f;
    float m0 = -1e30f, m1 = -1e30f, l0 = 0.f, l1 = 0.f;

    for (int c = 0; c < nch; ++c) {
        const uint32_t kvb = sb + 65536 + (uint32_t)(c & 1) * 65536;
        if (c + 1 < nch) {
            fa_load_kv(sb + 65536 + (uint32_t)((c + 1) & 1) * 65536, bh, (c + 1) * 64, tid);
            cpa_commit();
        }

        float s[8][4];
#pragma unroll
        for (int j = 0; j < 8; ++j)
#pragma unroll
            for (int e = 0; e < 4; ++e) s[j][e] = 0.f;

#pragma unroll
        for (int kk = 0; kk < 8; ++kk) {
            const int arow = wq + (lq & 1) * 8 + lr;
            const uint32_t akb = kk * 32 + (lq >> 1) * 16;
            const uint32_t qaddr = sb + (akb >> 7) * 16384 + sw128(arow * 128 + (akb & 127));
            uint32_t ahi[4], alo[4];
            ldsm4(ahi, qaddr);
            ldsm4(alo, qaddr + 32768);
#pragma unroll
            for (int nt = 0; nt < 4; ++nt) {
                const int brow = nt * 16 + (lq >> 1) * 8 + lr;
                const uint32_t bkb = kk * 32 + (lq & 1) * 16;
                const uint32_t kaddr = kvb + (bkb >> 7) * 8192 + sw128(brow * 128 + (bkb & 127));
                uint32_t bh4[4], bl4[4];
                ldsm4(bh4, kaddr);
                ldsm4(bl4, kaddr + 16384);
                mma_bf16(s[2 * nt],     ahi, bh4[0], bh4[1]);
                mma_bf16(s[2 * nt + 1], ahi, bh4[2], bh4[3]);
                mma_bf16(s[2 * nt],     ahi, bl4[0], bl4[1]);
                mma_bf16(s[2 * nt + 1], ahi, bl4[2], bl4[3]);
                mma_bf16(s[2 * nt],     alo, bh4[0], bh4[1]);
                mma_bf16(s[2 * nt + 1], alo, bh4[2], bh4[3]);
            }
        }

        if (c * 64 + 63 > q0 + wq) {
            const int r0g = q0 + wq + lrow;
#pragma unroll
            for (int j = 0; j < 8; ++j) {
                const int k0 = c * 64 + 8 * j + 2 * lc;
                if (k0 > r0g)         s[j][0] = -1e30f;
                if (k0 + 1 > r0g)     s[j][1] = -1e30f;
                if (k0 > r0g + 8)     s[j][2] = -1e30f;
                if (k0 + 1 > r0g + 8) s[j][3] = -1e30f;
            }
        }

        float mx0 = -1e30f, mx1 = -1e30f;
#pragma unroll
        for (int j = 0; j < 8; ++j) {
            mx0 = fmaxf(mx0, fmaxf(s[j][0], s[j][1]));
            mx1 = fmaxf(mx1, fmaxf(s[j][2], s[j][3]));
        }
        mx0 = fmaxf(mx0, __shfl_xor_sync(0xffffffffu, mx0, 1));
        mx0 = fmaxf(mx0, __shfl_xor_sync(0xffffffffu, mx0, 2));
        mx1 = fmaxf(mx1, __shfl_xor_sync(0xffffffffu, mx1, 1));
        mx1 = fmaxf(mx1, __shfl_xor_sync(0xffffffffu, mx1, 2));
        const float mn0 = fmaxf(m0, mx0), mn1 = fmaxf(m1, mx1);
        const float al0 = ex2((m0 - mn0) * C), al1 = ex2((m1 - mn1) * C);
        m0 = mn0; m1 = mn1;
        l0 *= al0; l1 *= al1;
#pragma unroll
        for (int t = 0; t < 16; ++t) {
            o[t][0] *= al0; o[t][1] *= al0; o[t][2] *= al1; o[t][3] *= al1;
        }
        uint32_t ph[8][2], pl[8][2];
#pragma unroll
        for (int j = 0; j < 8; ++j) {
            float p0 = ex2((s[j][0] - m0) * C);
            float p1 = ex2((s[j][1] - m0) * C);
            float p2 = ex2((s[j][2] - m1) * C);
            float p3 = ex2((s[j][3] - m1) * C);
            l0 += p0 + p1; l1 += p2 + p3;
            __nv_bfloat16 h0 = __float2bfloat16(p0), h1 = __float2bfloat16(p1);
            __nv_bfloat16 h2 = __float2bfloat16(p2), h3 = __float2bfloat16(p3);
            ph[j][0] = (uint32_t)__bfloat16_as_ushort(h0) | ((uint32_t)__bfloat16_as_ushort(h1) << 16);
            ph[j][1] = (uint32_t)__bfloat16_as_ushort(h2) | ((uint32_t)__bfloat16_as_ushort(h3) << 16);
            pl[j][0] = packbf(p0 - __bfloat162float(h0), p1 - __bfloat162float(h1));
            pl[j][1] = packbf(p2 - __bfloat162float(h2), p3 - __bfloat162float(h3));
        }

#pragma unroll
        for (int kk = 0; kk < 4; ++kk) {
            uint32_t pa_h[4] = { ph[2 * kk][0], ph[2 * kk][1], ph[2 * kk + 1][0], ph[2 * kk + 1][1] };
            uint32_t pa_l[4] = { pl[2 * kk][0], pl[2 * kk][1], pl[2 * kk + 1][0], pl[2 * kk + 1][1] };
#pragma unroll
            for (int nt = 0; nt < 8; ++nt) {
                const int vrow = kk * 16 + (lq & 1) * 8 + lr;
                const uint32_t nb = nt * 32 + (lq >> 1) * 16;
                const uint32_t vaddr = kvb + 32768 + (nb >> 7) * 8192 + sw128(vrow * 128 + (nb & 127));
                uint32_t vh4[4], vl4[4];
                ldsm4t(vh4, vaddr);
                ldsm4t(vl4, vaddr + 16384);
                mma_bf16(o[2 * nt],     pa_h, vh4[0], vh4[1]);
                mma_bf16(o[2 * nt + 1], pa_h, vh4[2], vh4[3]);
                mma_bf16(o[2 * nt],     pa_h, vl4[0], vl4[1]);
                mma_bf16(o[2 * nt + 1], pa_h, vl4[2], vl4[3]);
                mma_bf16(o[2 * nt],     pa_l, vh4[0], vh4[1]);
                mma_bf16(o[2 * nt + 1], pa_l, vh4[2], vh4[3]);
            }
        }

        cpa_wait0();
        __syncthreads();
    }

    l0 += __shfl_xor_sync(0xffffffffu, l0, 1);
    l0 += __shfl_xor_sync(0xffffffffu, l0, 2);
    l1 += __shfl_xor_sync(0xffffffffu, l1, 1);
    l1 += __shfl_xor_sync(0xffffffffu, l1, 2);
    const float inv0 = 1.f / l0, inv1 = 1.f / l1;

    // write attn directly as bf16 hi/lo [B,S,D]
    const int b = bh >> 4, h = bh & 15;
    const int row0 = q0 + wq + lrow;
    const long long base0 = ((long long)(b * S_ + row0)) * D_ + h * HD_ + 2 * lc;
    const long long base1 = base0 + 8LL * D_;
#pragma unroll
    for (int t = 0; t < 16; ++t) {
        store_split2(g_ah, g_al, base0 + 8 * t, o[t][0] * inv0, o[t][1] * inv0);
        store_split2(g_ah, g_al, base1 + 8 * t, o[t][2] * inv1, o[t][3] * inv1);
    }
}

// ---------------- launch ----------------
extern "C" void kernel_launch(void* const* d_in, const int* in_sizes, int n_in,
                              void* d_out, int out_size)
{
    const float* x     = (const float*)d_in[0]; // [4,2048,2048]
    const float* cosT  = (const float*)d_in[1]; // [2048,64]
    const float* sinT  = (const float*)d_in[2]; // [2048,64]
    const float* w_qkv = (const float*)d_in[3]; // [2048,6144]
    const float* w_out = (const float*)d_in[4]; // [2048,2048]
    float* out = (float*)d_out;                 // [4,2048,2048]
    (void)in_sizes; (void)n_in; (void)out_size;

    __nv_bfloat16 *xh, *xl, *wqh, *wql, *woh, *wol, *ah, *al;
    cudaGetSymbolAddress((void**)&xh, g_xh);
    cudaGetSymbolAddress((void**)&xl, g_xl);
    cudaGetSymbolAddress((void**)&wqh, g_wqh);
    cudaGetSymbolAddress((void**)&wql, g_wql);
    cudaGetSymbolAddress((void**)&woh, g_woh);
    cudaGetSymbolAddress((void**)&wol, g_wol);
    cudaGetSymbolAddress((void**)&ah, g_ah);
    cudaGetSymbolAddress((void**)&al, g_al);

    cudaFuncSetAttribute(gemm_bf<0>, cudaFuncAttributeMaxDynamicSharedMemorySize, SMEM_GEMM_BYTES);
    cudaFuncSetAttribute(gemm_bf<1>, cudaFuncAttributeMaxDynamicSharedMemorySize, SMEM_GEMM_BYTES);
    cudaFuncSetAttribute(flash_attn, cudaFuncAttributeMaxDynamicSharedMemorySize, FA_SMEM);

    // 0) one-time pre-splits (x elementwise; weights transpose+split)
    split_f32<<<16384, 256>>>(x, xh, xl);   // 16.8M floats / 4
    transpose_split<<<dim3(6144 / 32, 2048 / 32), dim3(32, 8)>>>(w_qkv, wqh, wql, 2048, 6144);
    transpose_split<<<dim3(2048 / 32, 2048 / 32), dim3(32, 8)>>>(w_out, woh, wol, 2048, 2048);

    // 1) QKV projection (all-bf16 mainloop); scatter q,k fp32 and v bf16 hi/lo
    gemm_bf<1><<<dim3(48, 64, 1), 256, SMEM_GEMM_BYTES>>>(
        xh, xl, wqh, wql, nullptr, 2048, 2048, 2048, 0);

    // 2) RoPE + hi/lo split of q,k
    rope_split<<<(Bb_ * H_ * S_ * (HD_ / 2)) / 256, 256>>>(cosT, sinT);

    // 3) fused flash attention -> g_ah/g_al bf16 [B,S,D]
    flash_attn<<<dim3(16, Bb_ * H_), 256, FA_SMEM>>>();

    // 4) out = attn @ w_outT^T (all-bf16 mainloop)
    gemm_bf<0><<<dim3(16, 64, 1), 256, SMEM_GEMM_BYTES>>>(
        ah, al, woh, wol, out, 2048, 2048, 2048, 2048);
}

// round 12
// speedup vs baseline: 4.4734x; 1.4014x over previous
#include <cuda_runtime.h>
#include <cuda_fp16.h>
#include <cstdint>
#include <math.h>

// Problem constants: B=4, S=2048, D=2048, H=16, hd=128
#define Bb_ 4
#define S_  2048
#define H_  16
#define HD_ 128
#define D_  2048

// ---------------- scratch (device globals; allocation-free) ----------------
__device__ float g_q[16777216];       // [B,H,S,hd] fp32 (pre-rope)
__device__ float g_k[16777216];       // [B,H,S,hd] fp32 (pre-rope)
__device__ __half g_qh[16777216];     // post-rope Q hi (fp16 2-term)
__device__ __half g_ql[16777216];     // post-rope Q lo
__device__ __half g_kh[16777216];     // post-rope K (fp16 1-term)
__device__ __half g_vh[16777216];     // V (fp16 1-term)
__device__ __half g_xh[16777216];     // x hi [8192,2048]
__device__ __half g_xl[16777216];     // x lo
__device__ __half g_wqh[12582912];    // w_qkv^T fp16 1-term [6144,2048]
__device__ __half g_woh[4194304];     // w_out^T fp16 1-term [2048,2048]
__device__ __half g_ah[16777216];     // attn hi [B,S,D]
__device__ __half g_al[16777216];     // attn lo

// ---------------- helpers ----------------
__device__ __forceinline__ uint32_t smem_u32(const void* p) {
    uint32_t a;
    asm("{ .reg .u64 t; cvta.to.shared.u64 t, %1; cvt.u32.u64 %0, t; }" : "=r"(a) : "l"(p));
    return a;
}
__device__ __forceinline__ void ldsm4(uint32_t* r, uint32_t addr) {
    asm volatile("ldmatrix.sync.aligned.m8n8.x4.shared.b16 {%0,%1,%2,%3}, [%4];"
                 : "=r"(r[0]), "=r"(r[1]), "=r"(r[2]), "=r"(r[3]) : "r"(addr));
}
__device__ __forceinline__ void ldsm4t(uint32_t* r, uint32_t addr) {
    asm volatile("ldmatrix.sync.aligned.m8n8.x4.trans.shared.b16 {%0,%1,%2,%3}, [%4];"
                 : "=r"(r[0]), "=r"(r[1]), "=r"(r[2]), "=r"(r[3]) : "r"(addr));
}
__device__ __forceinline__ void mma_f16(float* c, const uint32_t* a, uint32_t b0, uint32_t b1) {
    asm volatile(
        "mma.sync.aligned.m16n8k16.row.col.f32.f16.f16.f32 "
        "{%0,%1,%2,%3}, {%4,%5,%6,%7}, {%8,%9}, {%0,%1,%2,%3};"
        : "+f"(c[0]), "+f"(c[1]), "+f"(c[2]), "+f"(c[3])
        : "r"(a[0]), "r"(a[1]), "r"(a[2]), "r"(a[3]), "r"(b0), "r"(b1));
}
__device__ __forceinline__ uint32_t sw128(uint32_t off) { return off ^ ((off >> 3) & 0x70); }
__device__ __forceinline__ void cpa16(uint32_t dst, const void* src) {
    asm volatile("cp.async.cg.shared.global [%0], [%1], 16;" :: "r"(dst), "l"(src));
}
__device__ __forceinline__ void cpa_commit() { asm volatile("cp.async.commit_group;" ::: "memory"); }
__device__ __forceinline__ void cpa_wait0()  { asm volatile("cp.async.wait_group 0;" ::: "memory"); }
__device__ __forceinline__ float ex2(float x) {
    float r; asm("ex2.approx.f32 %0, %1;" : "=f"(r) : "f"(x)); return r;
}
__device__ __forceinline__ uint32_t packh(float a, float b) {
    __half ha = __float2half(a), hb = __float2half(b);
    return (uint32_t)__half_as_ushort(ha) | ((uint32_t)__half_as_ushort(hb) << 16);
}
// store pair as fp16 hi + fp16 lo (2-term split)
__device__ __forceinline__ void store_split2h(__half* hi, __half* lo,
                                              long long idx, float a, float b) {
    __half ha = __float2half(a), hb = __float2half(b);
    *(uint32_t*)(hi + idx) =
        (uint32_t)__half_as_ushort(ha) | ((uint32_t)__half_as_ushort(hb) << 16);
    *(uint32_t*)(lo + idx) = packh(a - __half2float(ha), b - __half2float(hb));
}

// ---------------- one-time split kernels ----------------
__global__ void split_f32h(const float* __restrict__ src,
                           __half* __restrict__ hi, __half* __restrict__ lo)
{
    const long long i = (long long)blockIdx.x * 256 + threadIdx.x;   // per float4
    float4 v = ((const float4*)src)[i];
    __half hx = __float2half(v.x), hy = __float2half(v.y);
    __half hz = __float2half(v.z), hw = __float2half(v.w);
    uint2 h;
    h.x = (uint32_t)__half_as_ushort(hx) | ((uint32_t)__half_as_ushort(hy) << 16);
    h.y = (uint32_t)__half_as_ushort(hz) | ((uint32_t)__half_as_ushort(hw) << 16);
    ((uint2*)hi)[i] = h;
    uint2 l;
    l.x = packh(v.x - __half2float(hx), v.y - __half2float(hy));
    l.y = packh(v.z - __half2float(hz), v.w - __half2float(hw));
    ((uint2*)lo)[i] = l;
}

// transpose + fp16 round (1-term): dst[C][R] = fp16(src[R][C])
__global__ void transpose_h(const float* __restrict__ src, __half* __restrict__ dst,
                            int R, int Cc)
{
    __shared__ float t[32][33];
    const int bx = blockIdx.x * 32, by = blockIdx.y * 32;
    const int txx = threadIdx.x, tyy = threadIdx.y;
#pragma unroll
    for (int i = 0; i < 4; ++i)
        t[tyy + i * 8][txx] = src[(long long)(by + tyy + i * 8) * Cc + bx + txx];
    __syncthreads();
#pragma unroll
    for (int i = 0; i < 4; ++i)
        dst[(long long)(bx + tyy + i * 8) * R + by + txx] = __float2half(t[txx][tyy + i * 8]);
}

// ---------------- fp16 2-pass mma.sync TN GEMM ----------------
// C[M,N] = (Ah+Al)[M,K] @ Bh[N,K]^T, fp32 accum. Error = fp16 rounding of B.
// Block 128x128, 8 warps (4x2), warp tile 32x64, K chunk 64, cp.async 2-stage.
// MODE: 0 = plain fp32 C write, 1 = qkv scatter (q,k fp32; v fp16 1-term)
#define SMEM_GEMM_BYTES 99328
#define TOFF(buf, which) (1024u + (uint32_t)(buf) * 49152u + (uint32_t)(which) * 16384u)

// one 128x64 fp16 tile -> SW128 smem via cp.async (256 threads, 4 per thread)
__device__ __forceinline__ void cpa_tile(uint32_t sdst, const __half* __restrict__ src,
                                         int ld, int row0, int kbase, int tid) {
#pragma unroll
    for (int p = 0; p < 4; ++p) {
        const int g = tid + p * 256;         // 0..1023
        const int row = g >> 3;              // 0..127
        const int seg = g & 7;               // 16B segment
        cpa16(sdst + sw128(row * 128 + seg * 16),
              src + (long long)(row0 + row) * ld + kbase + seg * 8);
    }
}

template<int MODE>
__global__ __launch_bounds__(256, 1)
void gemm_hf(const __half* __restrict__ Ah, const __half* __restrict__ Al,
             const __half* __restrict__ Bh,
             float* __restrict__ C, int K, int lda, int ldb, int ldc)
{
    const int m0 = blockIdx.y * 128;
    const int n0 = blockIdx.x * 128;
    const int nchunks = K >> 6;

    extern __shared__ char smem[];
    const uint32_t sb = smem_u32(smem);
    const int tid = threadIdx.x;
    const int lane = tid & 31;
    const int wid = tid >> 5;
    const int wm = (wid & 3) * 32;
    const int wn = (wid >> 2) * 64;
    const int lq = lane >> 3, lr = lane & 7;

    const int a_row = wm + (lq & 1) * 8 + lr;
    const int a_kc2 = (lq >> 1) * 16;
    const int b_row = wn + (lq >> 1) * 8 + lr;
    const int b_kc2 = (lq & 1) * 16;

    float acc[2][8][4];
#pragma unroll
    for (int i = 0; i < 2; i++)
#pragma unroll
        for (int j = 0; j < 8; j++)
#pragma unroll
            for (int e = 0; e < 4; e++) acc[i][j][e] = 0.f;

    cpa_tile(sb + TOFF(0, 0), Ah, lda, m0, 0, tid);
    cpa_tile(sb + TOFF(0, 1), Al, lda, m0, 0, tid);
    cpa_tile(sb + TOFF(0, 2), Bh, ldb, n0, 0, tid);
    cpa_commit();
    cpa_wait0();
    __syncthreads();

    for (int c = 0; c < nchunks; ++c) {
        const int buf = c & 1;
        const bool pf = (c + 1 < nchunks);
        if (pf) {
            const int nb = buf ^ 1;
            const int kb = (c + 1) * 64;
            cpa_tile(sb + TOFF(nb, 0), Ah, lda, m0, kb, tid);
            cpa_tile(sb + TOFF(nb, 1), Al, lda, m0, kb, tid);
            cpa_tile(sb + TOFF(nb, 2), Bh, ldb, n0, kb, tid);
            cpa_commit();
        }

        const uint32_t sAhi = sb + TOFF(buf, 0), sAlo = sb + TOFF(buf, 1);
        const uint32_t sBh = sb + TOFF(buf, 2);
#pragma unroll
        for (int kk = 0; kk < 4; ++kk) {
            uint32_t ahi[2][4], alo[2][4], bh4[4][4];
#pragma unroll
            for (int i = 0; i < 2; ++i) {
                uint32_t sw = sw128((a_row + i * 16) * 128 + kk * 32 + a_kc2);
                ldsm4(ahi[i], sAhi + sw);
                ldsm4(alo[i], sAlo + sw);
            }
#pragma unroll
            for (int jp = 0; jp < 4; ++jp) {
                uint32_t sw = sw128((b_row + jp * 16) * 128 + kk * 32 + b_kc2);
                ldsm4(bh4[jp], sBh + sw);
            }
#pragma unroll
            for (int i = 0; i < 2; ++i)
#pragma unroll
                for (int jp = 0; jp < 4; ++jp) {
                    mma_f16(acc[i][2 * jp],     ahi[i], bh4[jp][0], bh4[jp][1]);
                    mma_f16(acc[i][2 * jp + 1], ahi[i], bh4[jp][2], bh4[jp][3]);
                    mma_f16(acc[i][2 * jp],     alo[i], bh4[jp][0], bh4[jp][1]);
                    mma_f16(acc[i][2 * jp + 1], alo[i], bh4[jp][2], bh4[jp][3]);
                }
        }
        if (pf) cpa_wait0();
        __syncthreads();
    }

    const int lm = lane >> 2;
    const int ln = (lane & 3) * 2;
#pragma unroll
    for (int i = 0; i < 2; ++i) {
#pragma unroll
        for (int j = 0; j < 8; ++j) {
            const int gn = n0 + wn + j * 8 + ln;
#pragma unroll
            for (int half = 0; half < 2; ++half) {
                const int gm = m0 + wm + i * 16 + lm + half * 8;
                float v0 = acc[i][j][half * 2 + 0];
                float v1 = acc[i][j][half * 2 + 1];
                if (MODE == 0) {
                    *(float2*)(C + (long long)gm * ldc + gn) = make_float2(v0, v1);
                } else {
                    const int t = gn >> 11, h = (gn >> 7) & 15, d = gn & 127;
                    const int b = gm >> 11, s = gm & 2047;
                    const long long idx = ((long long)(b * H_ + h) * S_ + s) * HD_ + d;
                    if (t == 0)      *(float2*)(g_q + idx) = make_float2(v0, v1);
                    else if (t == 1) *(float2*)(g_k + idx) = make_float2(v0, v1);
                    else             *(uint32_t*)(g_vh + idx) = packh(v0, v1);
                }
            }
        }
    }
}

// ---------------- RoPE: Q -> fp16 hi/lo, K -> fp16 1-term ----------------
__global__ void rope_split(const float* __restrict__ cosT, const float* __restrict__ sinT)
{
    const long long idx = (long long)blockIdx.x * 256 + threadIdx.x;
    const int i = (int)(idx & 63);
    const int s = (int)((idx >> 6) & 2047);
    const int z = (int)(idx >> 17);
    const float c  = cosT[s * 64 + i];
    const float sn = sinT[s * 64 + i];
    const long long base = ((long long)z * S_ + s) * HD_;

    float q1 = g_q[base + i], q2 = g_q[base + 64 + i];
    float qa = q1 * c - q2 * sn, qb = q1 * sn + q2 * c;
    __half h;
    h = __float2half(qa); g_qh[base + i] = h;      g_ql[base + i]      = __float2half(qa - __half2float(h));
    h = __float2half(qb); g_qh[base + 64 + i] = h; g_ql[base + 64 + i] = __float2half(qb - __half2float(h));

    float k1 = g_k[base + i], k2 = g_k[base + 64 + i];
    g_kh[base + i]      = __float2half(k1 * c - k2 * sn);
    g_kh[base + 64 + i] = __float2half(k1 * sn + k2 * c);
}

// ---------------- fused flash attention (fp16 2-pass) ----------------
// CTA: (q-tile 128, bh). 8 warps x 16 q-rows. K/V chunks 64 rows, double-
// buffered cp.async. Q 2-term resident; K,V 1-term. Scores in registers;
// P 2-term for MMA2. Epilogue writes attn fp16 hi/lo.
// smem: Qh 32KB @0, Ql 32KB @32768; buffers @65536+buf*32768: Kh 16KB, Vh 16KB.
#define FA_SMEM 131072

__device__ __forceinline__ void fa_load_kv(uint32_t kvbase, int bh, int s0, int tid) {
#pragma unroll
    for (int p = 0; p < 4; ++p) {
        const int g = tid + p * 256;          // 0..1023
        const int row = g >> 4;               // 0..63
        const int b16i = g & 15;
        const uint32_t byte = b16i * 16;      // 0..255 within 256B row
        const long long srcoff = (((long long)(bh << 11) + s0 + row) << 7) + b16i * 8;
        const uint32_t dst = kvbase + (byte >> 7) * 8192 + sw128(row * 128 + (byte & 127));
        cpa16(dst,         g_kh + srcoff);
        cpa16(dst + 16384, g_vh + srcoff);
    }
}

__global__ __launch_bounds__(256, 1)
void flash_attn()
{
    const int qt = 15 - blockIdx.x;           // big tiles first
    const int q0 = qt << 7;
    const int bh = blockIdx.y;
    const int nch = (qt + 1) * 2;

    extern __shared__ char smem[];
    const uint32_t sb = smem_u32(smem);
    const int tid = threadIdx.x;
    const int w = tid >> 5;
    const int lane = tid & 31;
    const int wq = w * 16;
    const int lq = lane >> 3, lr = lane & 7;
    const int lc = lane & 3;
    const int lrow = lane >> 2;

    // prologue: Q hi/lo + chunk 0
#pragma unroll
    for (int p = 0; p < 8; ++p) {
        const int g = tid + p * 256;
        const int row = g >> 4;               // 0..127
        const int b16i = g & 15;
        const uint32_t byte = b16i * 16;
        const long long srcoff = (((long long)(bh << 11) + q0 + row) << 7) + b16i * 8;
        const uint32_t dst = sb + (byte >> 7) * 16384 + sw128(row * 128 + (byte & 127));
        cpa16(dst,         g_qh + srcoff);
        cpa16(dst + 32768, g_ql + srcoff);
    }
    fa_load_kv(sb + 65536, bh, 0, tid);
    cpa_commit();
    cpa_wait0();
    __syncthreads();

    const float C = 0.08838834764831845f * 1.4426950408889634f; // scale*log2(e)
    float o[16][4];
#pragma unroll
    for (int t = 0; t < 16; ++t)
#pragma unroll
        for (int e = 0; e < 4; ++e) o[t][e] = 0.f;
    float m0 = -1e30f, m1 = -1e30f, l0 = 0.f, l1 = 0.f;

    for (int c = 0; c < nch; ++c) {
        const uint32_t kvb = sb + 65536 + (uint32_t)(c & 1) * 32768;
        if (c + 1 < nch) {
            fa_load_kv(sb + 65536 + (uint32_t)((c + 1) & 1) * 32768, bh, (c + 1) * 64, tid);
            cpa_commit();
        }

        // MMA1: scores[16q x 64k] = (Qh+Ql) @ Kh^T
        float s[8][4];
#pragma unroll
        for (int j = 0; j < 8; ++j)
#pragma unroll
            for (int e = 0; e < 4; ++e) s[j][e] = 0.f;

#pragma unroll
        for (int kk = 0; kk < 8; ++kk) {
            const int arow = wq + (lq & 1) * 8 + lr;
            const uint32_t akb = kk * 32 + (lq >> 1) * 16;
            const uint32_t qaddr = sb + (akb >> 7) * 16384 + sw128(arow * 128 + (akb & 127));
            uint32_t ahi[4], alo[4];
            ldsm4(ahi, qaddr);
            ldsm4(alo, qaddr + 32768);
#pragma unroll
            for (int nt = 0; nt < 4; ++nt) {
                const int brow = nt * 16 + (lq >> 1) * 8 + lr;
                const uint32_t bkb = kk * 32 + (lq & 1) * 16;
                const uint32_t kaddr = kvb + (bkb >> 7) * 8192 + sw128(brow * 128 + (bkb & 127));
                uint32_t bh4[4];
                ldsm4(bh4, kaddr);
                mma_f16(s[2 * nt],     ahi, bh4[0], bh4[1]);
                mma_f16(s[2 * nt + 1], ahi, bh4[2], bh4[3]);
                mma_f16(s[2 * nt],     alo, bh4[0], bh4[1]);
                mma_f16(s[2 * nt + 1], alo, bh4[2], bh4[3]);
            }
        }

        // causal mask near diagonal
        if (c * 64 + 63 > q0 + wq) {
            const int r0g = q0 + wq + lrow;
#pragma unroll
            for (int j = 0; j < 8; ++j) {
                const int k0 = c * 64 + 8 * j + 2 * lc;
                if (k0 > r0g)         s[j][0] = -1e30f;
                if (k0 + 1 > r0g)     s[j][1] = -1e30f;
                if (k0 > r0g + 8)     s[j][2] = -1e30f;
                if (k0 + 1 > r0g + 8) s[j][3] = -1e30f;
            }
        }

        // online softmax
        float mx0 = -1e30f, mx1 = -1e30f;
#pragma unroll
        for (int j = 0; j < 8; ++j) {
            mx0 = fmaxf(mx0, fmaxf(s[j][0], s[j][1]));
            mx1 = fmaxf(mx1, fmaxf(s[j][2], s[j][3]));
        }
        mx0 = fmaxf(mx0, __shfl_xor_sync(0xffffffffu, mx0, 1));
        mx0 = fmaxf(mx0, __shfl_xor_sync(0xffffffffu, mx0, 2));
        mx1 = fmaxf(mx1, __shfl_xor_sync(0xffffffffu, mx1, 1));
        mx1 = fmaxf(mx1, __shfl_xor_sync(0xffffffffu, mx1, 2));
        const float mn0 = fmaxf(m0, mx0), mn1 = fmaxf(m1, mx1);
        const float al0 = ex2((m0 - mn0) * C), al1 = ex2((m1 - mn1) * C);
        m0 = mn0; m1 = mn1;
        l0 *= al0; l1 *= al1;
#pragma unroll
        for (int t = 0; t < 16; ++t) {
            o[t][0] *= al0; o[t][1] *= al0; o[t][2] *= al1; o[t][3] *= al1;
        }
        uint32_t ph[8][2], pl[8][2];
#pragma unroll
        for (int j = 0; j < 8; ++j) {
            float p0 = ex2((s[j][0] - m0) * C);
            float p1 = ex2((s[j][1] - m0) * C);
            float p2 = ex2((s[j][2] - m1) * C);
            float p3 = ex2((s[j][3] - m1) * C);
            l0 += p0 + p1; l1 += p2 + p3;
            __half h0 = __float2half(p0), h1 = __float2half(p1);
            __half h2 = __float2half(p2), h3 = __float2half(p3);
            ph[j][0] = (uint32_t)__half_as_ushort(h0) | ((uint32_t)__half_as_ushort(h1) << 16);
            ph[j][1] = (uint32_t)__half_as_ushort(h2) | ((uint32_t)__half_as_ushort(h3) << 16);
            pl[j][0] = packh(p0 - __half2float(h0), p1 - __half2float(h1));
            pl[j][1] = packh(p2 - __half2float(h2), p3 - __half2float(h3));
        }

        // MMA2: O += (Ph+Pl) @ Vh (V via trans ldmatrix)
#pragma unroll
        for (int kk = 0; kk < 4; ++kk) {
            uint32_t pa_h[4] = { ph[2 * kk][0], ph[2 * kk][1], ph[2 * kk + 1][0], ph[2 * kk + 1][1] };
            uint32_t pa_l[4] = { pl[2 * kk][0], pl[2 * kk][1], pl[2 * kk + 1][0], pl[2 * kk + 1][1] };
#pragma unroll
            for (int nt = 0; nt < 8; ++nt) {
                const int vrow = kk * 16 + (lq & 1) * 8 + lr;
                const uint32_t nb = nt * 32 + (lq >> 1) * 16;
                const uint32_t vaddr = kvb + 16384 + (nb >> 7) * 8192 + sw128(vrow * 128 + (nb & 127));
                uint32_t vh4[4];
                ldsm4t(vh4, vaddr);
                mma_f16(o[2 * nt],     pa_h, vh4[0], vh4[1]);
                mma_f16(o[2 * nt + 1], pa_h, vh4[2], vh4[3]);
                mma_f16(o[2 * nt],     pa_l, vh4[0], vh4[1]);
                mma_f16(o[2 * nt + 1], pa_l, vh4[2], vh4[3]);
            }
        }

        cpa_wait0();
        __syncthreads();
    }

    l0 += __shfl_xor_sync(0xffffffffu, l0, 1);
    l0 += __shfl_xor_sync(0xffffffffu, l0, 2);
    l1 += __shfl_xor_sync(0xffffffffu, l1, 1);
    l1 += __shfl_xor_sync(0xffffffffu, l1, 2);
    const float inv0 = 1.f / l0, inv1 = 1.f / l1;

    // write attn as fp16 hi/lo [B,S,D]
    const int b = bh >> 4, h = bh & 15;
    const int row0 = q0 + wq + lrow;
    const long long base0 = ((long long)(b * S_ + row0)) * D_ + h * HD_ + 2 * lc;
    const long long base1 = base0 + 8LL * D_;
#pragma unroll
    for (int t = 0; t < 16; ++t) {
        store_split2h(g_ah, g_al, base0 + 8 * t, o[t][0] * inv0, o[t][1] * inv0);
        store_split2h(g_ah, g_al, base1 + 8 * t, o[t][2] * inv1, o[t][3] * inv1);
    }
}

// ---------------- launch ----------------
extern "C" void kernel_launch(void* const* d_in, const int* in_sizes, int n_in,
                              void* d_out, int out_size)
{
    const float* x     = (const float*)d_in[0]; // [4,2048,2048]
    const float* cosT  = (const float*)d_in[1]; // [2048,64]
    const float* sinT  = (const float*)d_in[2]; // [2048,64]
    const float* w_qkv = (const float*)d_in[3]; // [2048,6144]
    const float* w_out = (const float*)d_in[4]; // [2048,2048]
    float* out = (float*)d_out;                 // [4,2048,2048]
    (void)in_sizes; (void)n_in; (void)out_size;

    __half *xh, *xl, *wqh, *woh, *ah, *al;
    cudaGetSymbolAddress((void**)&xh, g_xh);
    cudaGetSymbolAddress((void**)&xl, g_xl);
    cudaGetSymbolAddress((void**)&wqh, g_wqh);
    cudaGetSymbolAddress((void**)&woh, g_woh);
    cudaGetSymbolAddress((void**)&ah, g_ah);
    cudaGetSymbolAddress((void**)&al, g_al);

    cudaFuncSetAttribute(gemm_hf<0>, cudaFuncAttributeMaxDynamicSharedMemorySize, SMEM_GEMM_BYTES);
    cudaFuncSetAttribute(gemm_hf<1>, cudaFuncAttributeMaxDynamicSharedMemorySize, SMEM_GEMM_BYTES);
    cudaFuncSetAttribute(flash_attn, cudaFuncAttributeMaxDynamicSharedMemorySize, FA_SMEM);

    // 0) one-time pre-splits
    split_f32h<<<16384, 256>>>(x, xh, xl);   // 16.8M floats / 4 per thread
    transpose_h<<<dim3(6144 / 32, 2048 / 32), dim3(32, 8)>>>(w_qkv, wqh, 2048, 6144);
    transpose_h<<<dim3(2048 / 32, 2048 / 32), dim3(32, 8)>>>(w_out, woh, 2048, 2048);

    // 1) QKV projection; scatter q,k fp32 and v fp16
    gemm_hf<1><<<dim3(48, 64, 1), 256, SMEM_GEMM_BYTES>>>(
        xh, xl, wqh, nullptr, 2048, 2048, 2048, 0);

    // 2) RoPE + fp16 packing of q (2-term) and k (1-term)
    rope_split<<<(Bb_ * H_ * S_ * (HD_ / 2)) / 256, 256>>>(cosT, sinT);

    // 3) fused flash attention -> g_ah/g_al fp16 [B,S,D]
    flash_attn<<<dim3(16, Bb_ * H_), 256, FA_SMEM>>>();

    // 4) out = attn @ w_outT^T
    gemm_hf<0><<<dim3(16, 64, 1), 256, SMEM_GEMM_BYTES>>>(
        ah, al, woh, out, 2048, 2048, 2048, 2048);
}

// round 13
// speedup vs baseline: 6.3945x; 1.4294x over previous
#include <cuda_runtime.h>
#include <cuda_fp16.h>
#include <cstdint>
#include <math.h>

// Problem constants: B=4, S=2048, D=2048, H=16, hd=128
#define Bb_ 4
#define S_  2048
#define H_  16
#define HD_ 128
#define D_  2048

// ---------------- scratch (device globals; allocation-free) ----------------
__device__ float g_q[16777216];       // [B,H,S,hd] fp32 (pre-rope)
__device__ float g_k[16777216];       // [B,H,S,hd] fp32 (pre-rope)
__device__ __half g_qh[16777216];     // post-rope Q hi (fp16 2-term)
__device__ __half g_ql[16777216];     // post-rope Q lo
__device__ __half g_kh[16777216];     // post-rope K (fp16 1-term)
__device__ __half g_vh[16777216];     // V (fp16 1-term)
__device__ __half g_xh[16777216];     // x fp16 1-term [8192,2048]
__device__ __half g_wqh[12582912];    // w_qkv^T fp16 1-term [6144,2048]
__device__ __half g_woh[4194304];     // w_out^T fp16 1-term [2048,2048]
__device__ __half g_ah[16777216];     // attn fp16 1-term [B,S,D]

// ---------------- helpers ----------------
__device__ __forceinline__ uint32_t smem_u32(const void* p) {
    uint32_t a;
    asm("{ .reg .u64 t; cvta.to.shared.u64 t, %1; cvt.u32.u64 %0, t; }" : "=r"(a) : "l"(p));
    return a;
}
__device__ __forceinline__ void ldsm4(uint32_t* r, uint32_t addr) {
    asm volatile("ldmatrix.sync.aligned.m8n8.x4.shared.b16 {%0,%1,%2,%3}, [%4];"
                 : "=r"(r[0]), "=r"(r[1]), "=r"(r[2]), "=r"(r[3]) : "r"(addr));
}
__device__ __forceinline__ void ldsm4t(uint32_t* r, uint32_t addr) {
    asm volatile("ldmatrix.sync.aligned.m8n8.x4.trans.shared.b16 {%0,%1,%2,%3}, [%4];"
                 : "=r"(r[0]), "=r"(r[1]), "=r"(r[2]), "=r"(r[3]) : "r"(addr));
}
__device__ __forceinline__ void mma_f16(float* c, const uint32_t* a, uint32_t b0, uint32_t b1) {
    asm volatile(
        "mma.sync.aligned.m16n8k16.row.col.f32.f16.f16.f32 "
        "{%0,%1,%2,%3}, {%4,%5,%6,%7}, {%8,%9}, {%0,%1,%2,%3};"
        : "+f"(c[0]), "+f"(c[1]), "+f"(c[2]), "+f"(c[3])
        : "r"(a[0]), "r"(a[1]), "r"(a[2]), "r"(a[3]), "r"(b0), "r"(b1));
}
__device__ __forceinline__ uint32_t sw128(uint32_t off) { return off ^ ((off >> 3) & 0x70); }
__device__ __forceinline__ void cpa16(uint32_t dst, const void* src) {
    asm volatile("cp.async.cg.shared.global [%0], [%1], 16;" :: "r"(dst), "l"(src));
}
__device__ __forceinline__ void cpa_commit() { asm volatile("cp.async.commit_group;" ::: "memory"); }
__device__ __forceinline__ void cpa_wait0()  { asm volatile("cp.async.wait_group 0;" ::: "memory"); }
__device__ __forceinline__ float ex2(float x) {
    float r; asm("ex2.approx.f32 %0, %1;" : "=f"(r) : "f"(x)); return r;
}
__device__ __forceinline__ uint32_t packh(float a, float b) {
    __half ha = __float2half(a), hb = __float2half(b);
    return (uint32_t)__half_as_ushort(ha) | ((uint32_t)__half_as_ushort(hb) << 16);
}

// ---------------- one-time conversion kernels ----------------
__global__ void round_f32h(const float* __restrict__ src, __half* __restrict__ dst)
{
    const long long i = (long long)blockIdx.x * 256 + threadIdx.x;   // per float4
    float4 v = ((const float4*)src)[i];
    uint2 h;
    h.x = packh(v.x, v.y);
    h.y = packh(v.z, v.w);
    ((uint2*)dst)[i] = h;
}

// transpose + fp16 round (1-term): dst[C][R] = fp16(src[R][C])
__global__ void transpose_h(const float* __restrict__ src, __half* __restrict__ dst,
                            int R, int Cc)
{
    __shared__ float t[32][33];
    const int bx = blockIdx.x * 32, by = blockIdx.y * 32;
    const int txx = threadIdx.x, tyy = threadIdx.y;
#pragma unroll
    for (int i = 0; i < 4; ++i)
        t[tyy + i * 8][txx] = src[(long long)(by + tyy + i * 8) * Cc + bx + txx];
    __syncthreads();
#pragma unroll
    for (int i = 0; i < 4; ++i)
        dst[(long long)(bx + tyy + i * 8) * R + by + txx] = __float2half(t[txx][tyy + i * 8]);
}

// ---------------- fp16 1-pass mma.sync TN GEMM ----------------
// C[M,N] = Ah[M,K] @ Bh[N,K]^T, fp32 accum. Both operands fp16 1-term.
// Block 128x128, 8 warps (4x2), warp tile 32x64, K chunk 64, cp.async 2-stage.
// MODE: 0 = plain fp32 C write, 1 = qkv scatter (q,k fp32; v fp16 1-term)
#define SMEM_GEMM_BYTES 66560
#define TOFF(buf, which) (1024u + (uint32_t)(buf) * 32768u + (uint32_t)(which) * 16384u)

// one 128x64 fp16 tile -> SW128 smem via cp.async (256 threads, 4 per thread)
__device__ __forceinline__ void cpa_tile(uint32_t sdst, const __half* __restrict__ src,
                                         int ld, int row0, int kbase, int tid) {
#pragma unroll
    for (int p = 0; p < 4; ++p) {
        const int g = tid + p * 256;         // 0..1023
        const int row = g >> 3;              // 0..127
        const int seg = g & 7;               // 16B segment
        cpa16(sdst + sw128(row * 128 + seg * 16),
              src + (long long)(row0 + row) * ld + kbase + seg * 8);
    }
}

template<int MODE>
__global__ __launch_bounds__(256, 1)
void gemm_hf(const __half* __restrict__ Ah, const __half* __restrict__ Bh,
             float* __restrict__ C, int K, int lda, int ldb, int ldc)
{
    const int m0 = blockIdx.y * 128;
    const int n0 = blockIdx.x * 128;
    const int nchunks = K >> 6;

    extern __shared__ char smem[];
    const uint32_t sb = smem_u32(smem);
    const int tid = threadIdx.x;
    const int lane = tid & 31;
    const int wid = tid >> 5;
    const int wm = (wid & 3) * 32;
    const int wn = (wid >> 2) * 64;
    const int lq = lane >> 3, lr = lane & 7;

    const int a_row = wm + (lq & 1) * 8 + lr;
    const int a_kc2 = (lq >> 1) * 16;
    const int b_row = wn + (lq >> 1) * 8 + lr;
    const int b_kc2 = (lq & 1) * 16;

    float acc[2][8][4];
#pragma unroll
    for (int i = 0; i < 2; i++)
#pragma unroll
        for (int j = 0; j < 8; j++)
#pragma unroll
            for (int e = 0; e < 4; e++) acc[i][j][e] = 0.f;

    cpa_tile(sb + TOFF(0, 0), Ah, lda, m0, 0, tid);
    cpa_tile(sb + TOFF(0, 1), Bh, ldb, n0, 0, tid);
    cpa_commit();
    cpa_wait0();
    __syncthreads();

    for (int c = 0; c < nchunks; ++c) {
        const int buf = c & 1;
        const bool pf = (c + 1 < nchunks);
        if (pf) {
            const int nb = buf ^ 1;
            const int kb = (c + 1) * 64;
            cpa_tile(sb + TOFF(nb, 0), Ah, lda, m0, kb, tid);
            cpa_tile(sb + TOFF(nb, 1), Bh, ldb, n0, kb, tid);
            cpa_commit();
        }

        const uint32_t sA = sb + TOFF(buf, 0);
        const uint32_t sB = sb + TOFF(buf, 1);
#pragma unroll
        for (int kk = 0; kk < 4; ++kk) {
            uint32_t a4[2][4], b4[4][4];
#pragma unroll
            for (int i = 0; i < 2; ++i) {
                uint32_t sw = sw128((a_row + i * 16) * 128 + kk * 32 + a_kc2);
                ldsm4(a4[i], sA + sw);
            }
#pragma unroll
            for (int jp = 0; jp < 4; ++jp) {
                uint32_t sw = sw128((b_row + jp * 16) * 128 + kk * 32 + b_kc2);
                ldsm4(b4[jp], sB + sw);
            }
#pragma unroll
            for (int i = 0; i < 2; ++i)
#pragma unroll
                for (int jp = 0; jp < 4; ++jp) {
                    mma_f16(acc[i][2 * jp],     a4[i], b4[jp][0], b4[jp][1]);
                    mma_f16(acc[i][2 * jp + 1], a4[i], b4[jp][2], b4[jp][3]);
                }
        }
        if (pf) cpa_wait0();
        __syncthreads();
    }

    const int lm = lane >> 2;
    const int ln = (lane & 3) * 2;
#pragma unroll
    for (int i = 0; i < 2; ++i) {
#pragma unroll
        for (int j = 0; j < 8; ++j) {
            const int gn = n0 + wn + j * 8 + ln;
#pragma unroll
            for (int half = 0; half < 2; ++half) {
                const int gm = m0 + wm + i * 16 + lm + half * 8;
                float v0 = acc[i][j][half * 2 + 0];
                float v1 = acc[i][j][half * 2 + 1];
                if (MODE == 0) {
                    *(float2*)(C + (long long)gm * ldc + gn) = make_float2(v0, v1);
                } else {
                    const int t = gn >> 11, h = (gn >> 7) & 15, d = gn & 127;
                    const int b = gm >> 11, s = gm & 2047;
                    const long long idx = ((long long)(b * H_ + h) * S_ + s) * HD_ + d;
                    if (t == 0)      *(float2*)(g_q + idx) = make_float2(v0, v1);
                    else if (t == 1) *(float2*)(g_k + idx) = make_float2(v0, v1);
                    else             *(uint32_t*)(g_vh + idx) = packh(v0, v1);
                }
            }
        }
    }
}

// ---------------- RoPE: Q -> fp16 hi/lo, K -> fp16 1-term ----------------
__global__ void rope_split(const float* __restrict__ cosT, const float* __restrict__ sinT)
{
    const long long idx = (long long)blockIdx.x * 256 + threadIdx.x;
    const int i = (int)(idx & 63);
    const int s = (int)((idx >> 6) & 2047);
    const int z = (int)(idx >> 17);
    const float c  = cosT[s * 64 + i];
    const float sn = sinT[s * 64 + i];
    const long long base = ((long long)z * S_ + s) * HD_;

    float q1 = g_q[base + i], q2 = g_q[base + 64 + i];
    float qa = q1 * c - q2 * sn, qb = q1 * sn + q2 * c;
    __half h;
    h = __float2half(qa); g_qh[base + i] = h;      g_ql[base + i]      = __float2half(qa - __half2float(h));
    h = __float2half(qb); g_qh[base + 64 + i] = h; g_ql[base + 64 + i] = __float2half(qb - __half2float(h));

    float k1 = g_k[base + i], k2 = g_k[base + 64 + i];
    g_kh[base + i]      = __float2half(k1 * c - k2 * sn);
    g_kh[base + 64 + i] = __float2half(k1 * sn + k2 * c);
}

// ---------------- fused flash attention (Q 2-term, K/V 1-term, P 2-term) ----
// CTA: (q-tile 128, bh). 8 warps x 16 q-rows. K/V chunks 64 rows, double-
// buffered cp.async. Scores in registers; MMA1 C-frag repacked as MMA2 A-frag.
// smem: Qh 32KB @0, Ql 32KB @32768; buffers @65536+buf*32768: Kh 16KB, Vh 16KB.
#define FA_SMEM 131072

__device__ __forceinline__ void fa_load_kv(uint32_t kvbase, int bh, int s0, int tid) {
#pragma unroll
    for (int p = 0; p < 4; ++p) {
        const int g = tid + p * 256;          // 0..1023
        const int row = g >> 4;               // 0..63
        const int b16i = g & 15;
        const uint32_t byte = b16i * 16;
        const long long srcoff = (((long long)(bh << 11) + s0 + row) << 7) + b16i * 8;
        const uint32_t dst = kvbase + (byte >> 7) * 8192 + sw128(row * 128 + (byte & 127));
        cpa16(dst,         g_kh + srcoff);
        cpa16(dst + 16384, g_vh + srcoff);
    }
}

__global__ __launch_bounds__(256, 1)
void flash_attn()
{
    const int qt = 15 - blockIdx.x;           // big tiles first
    const int q0 = qt << 7;
    const int bh = blockIdx.y;
    const int nch = (qt + 1) * 2;

    extern __shared__ char smem[];
    const uint32_t sb = smem_u32(smem);
    const int tid = threadIdx.x;
    const int w = tid >> 5;
    const int lane = tid & 31;
    const int wq = w * 16;
    const int lq = lane >> 3, lr = lane & 7;
    const int lc = lane & 3;
    const int lrow = lane >> 2;

    // prologue: Q hi/lo + chunk 0
#pragma unroll
    for (int p = 0; p < 8; ++p) {
        const int g = tid + p * 256;
        const int row = g >> 4;               // 0..127
        const int b16i = g & 15;
        const uint32_t byte = b16i * 16;
        const long long srcoff = (((long long)(bh << 11) + q0 + row) << 7) + b16i * 8;
        const uint32_t dst = sb + (byte >> 7) * 16384 + sw128(row * 128 + (byte & 127));
        cpa16(dst,         g_qh + srcoff);
        cpa16(dst + 32768, g_ql + srcoff);
    }
    fa_load_kv(sb + 65536, bh, 0, tid);
    cpa_commit();
    cpa_wait0();
    __syncthreads();

    const float C = 0.08838834764831845f * 1.4426950408889634f; // scale*log2(e)
    float o[16][4];
#pragma unroll
    for (int t = 0; t < 16; ++t)
#pragma unroll
        for (int e = 0; e < 4; ++e) o[t][e] = 0.f;
    float m0 = -1e30f, m1 = -1e30f, l0 = 0.f, l1 = 0.f;

    for (int c = 0; c < nch; ++c) {
        const uint32_t kvb = sb + 65536 + (uint32_t)(c & 1) * 32768;
        if (c + 1 < nch) {
            fa_load_kv(sb + 65536 + (uint32_t)((c + 1) & 1) * 32768, bh, (c + 1) * 64, tid);
            cpa_commit();
        }

        // MMA1: scores[16q x 64k] = (Qh+Ql) @ Kh^T
        float s[8][4];
#pragma unroll
        for (int j = 0; j < 8; ++j)
#pragma unroll
            for (int e = 0; e < 4; ++e) s[j][e] = 0.f;

#pragma unroll
        for (int kk = 0; kk < 8; ++kk) {
            const int arow = wq + (lq & 1) * 8 + lr;
            const uint32_t akb = kk * 32 + (lq >> 1) * 16;
            const uint32_t qaddr = sb + (akb >> 7) * 16384 + sw128(arow * 128 + (akb & 127));
            uint32_t ahi[4], alo[4];
            ldsm4(ahi, qaddr);
            ldsm4(alo, qaddr + 32768);
#pragma unroll
            for (int nt = 0; nt < 4; ++nt) {
                const int brow = nt * 16 + (lq >> 1) * 8 + lr;
                const uint32_t bkb = kk * 32 + (lq & 1) * 16;
                const uint32_t kaddr = kvb + (bkb >> 7) * 8192 + sw128(brow * 128 + (bkb & 127));
                uint32_t bh4[4];
                ldsm4(bh4, kaddr);
                mma_f16(s[2 * nt],     ahi, bh4[0], bh4[1]);
                mma_f16(s[2 * nt + 1], ahi, bh4[2], bh4[3]);
                mma_f16(s[2 * nt],     alo, bh4[0], bh4[1]);
                mma_f16(s[2 * nt + 1], alo, bh4[2], bh4[3]);
            }
        }

        // causal mask near diagonal
        if (c * 64 + 63 > q0 + wq) {
            const int r0g = q0 + wq + lrow;
#pragma unroll
            for (int j = 0; j < 8; ++j) {
                const int k0 = c * 64 + 8 * j + 2 * lc;
                if (k0 > r0g)         s[j][0] = -1e30f;
                if (k0 + 1 > r0g)     s[j][1] = -1e30f;
                if (k0 > r0g + 8)     s[j][2] = -1e30f;
                if (k0 + 1 > r0g + 8) s[j][3] = -1e30f;
            }
        }

        // online softmax
        float mx0 = -1e30f, mx1 = -1e30f;
#pragma unroll
        for (int j = 0; j < 8; ++j) {
            mx0 = fmaxf(mx0, fmaxf(s[j][0], s[j][1]));
            mx1 = fmaxf(mx1, fmaxf(s[j][2], s[j][3]));
        }
        mx0 = fmaxf(mx0, __shfl_xor_sync(0xffffffffu, mx0, 1));
        mx0 = fmaxf(mx0, __shfl_xor_sync(0xffffffffu, mx0, 2));
        mx1 = fmaxf(mx1, __shfl_xor_sync(0xffffffffu, mx1, 1));
        mx1 = fmaxf(mx1, __shfl_xor_sync(0xffffffffu, mx1, 2));
        const float mn0 = fmaxf(m0, mx0), mn1 = fmaxf(m1, mx1);
        const float al0 = ex2((m0 - mn0) * C), al1 = ex2((m1 - mn1) * C);
        m0 = mn0; m1 = mn1;
        l0 *= al0; l1 *= al1;
#pragma unroll
        for (int t = 0; t < 16; ++t) {
            o[t][0] *= al0; o[t][1] *= al0; o[t][2] *= al1; o[t][3] *= al1;
        }
        uint32_t ph[8][2], pl[8][2];
#pragma unroll
        for (int j = 0; j < 8; ++j) {
            float p0 = ex2((s[j][0] - m0) * C);
            float p1 = ex2((s[j][1] - m0) * C);
            float p2 = ex2((s[j][2] - m1) * C);
            float p3 = ex2((s[j][3] - m1) * C);
            l0 += p0 + p1; l1 += p2 + p3;
            __half h0 = __float2half(p0), h1 = __float2half(p1);
            __half h2 = __float2half(p2), h3 = __float2half(p3);
            ph[j][0] = (uint32_t)__half_as_ushort(h0) | ((uint32_t)__half_as_ushort(h1) << 16);
            ph[j][1] = (uint32_t)__half_as_ushort(h2) | ((uint32_t)__half_as_ushort(h3) << 16);
            pl[j][0] = packh(p0 - __half2float(h0), p1 - __half2float(h1));
            pl[j][1] = packh(p2 - __half2float(h2), p3 - __half2float(h3));
        }

        // MMA2: O += (Ph+Pl) @ Vh (V via trans ldmatrix)
#pragma unroll
        for (int kk = 0; kk < 4; ++kk) {
            uint32_t pa_h[4] = { ph[2 * kk][0], ph[2 * kk][1], ph[2 * kk + 1][0], ph[2 * kk + 1][1] };
            uint32_t pa_l[4] = { pl[2 * kk][0], pl[2 * kk][1], pl[2 * kk + 1][0], pl[2 * kk + 1][1] };
#pragma unroll
            for (int nt = 0; nt < 8; ++nt) {
                const int vrow = kk * 16 + (lq & 1) * 8 + lr;
                const uint32_t nb = nt * 32 + (lq >> 1) * 16;
                const uint32_t vaddr = kvb + 16384 + (nb >> 7) * 8192 + sw128(vrow * 128 + (nb & 127));
                uint32_t vh4[4];
                ldsm4t(vh4, vaddr);
                mma_f16(o[2 * nt],     pa_h, vh4[0], vh4[1]);
                mma_f16(o[2 * nt + 1], pa_h, vh4[2], vh4[3]);
                mma_f16(o[2 * nt],     pa_l, vh4[0], vh4[1]);
                mma_f16(o[2 * nt + 1], pa_l, vh4[2], vh4[3]);
            }
        }

        cpa_wait0();
        __syncthreads();
    }

    l0 += __shfl_xor_sync(0xffffffffu, l0, 1);
    l0 += __shfl_xor_sync(0xffffffffu, l0, 2);
    l1 += __shfl_xor_sync(0xffffffffu, l1, 1);
    l1 += __shfl_xor_sync(0xffffffffu, l1, 2);
    const float inv0 = 1.f / l0, inv1 = 1.f / l1;

    // write attn as fp16 1-term [B,S,D]
    const int b = bh >> 4, h = bh & 15;
    const int row0 = q0 + wq + lrow;
    const long long base0 = ((long long)(b * S_ + row0)) * D_ + h * HD_ + 2 * lc;
    const long long base1 = base0 + 8LL * D_;
#pragma unroll
    for (int t = 0; t < 16; ++t) {
        *(uint32_t*)(g_ah + base0 + 8 * t) = packh(o[t][0] * inv0, o[t][1] * inv0);
        *(uint32_t*)(g_ah + base1 + 8 * t) = packh(o[t][2] * inv1, o[t][3] * inv1);
    }
}

// ---------------- launch ----------------
extern "C" void kernel_launch(void* const* d_in, const int* in_sizes, int n_in,
                              void* d_out, int out_size)
{
    const float* x     = (const float*)d_in[0]; // [4,2048,2048]
    const float* cosT  = (const float*)d_in[1]; // [2048,64]
    const float* sinT  = (const float*)d_in[2]; // [2048,64]
    const float* w_qkv = (const float*)d_in[3]; // [2048,6144]
    const float* w_out = (const float*)d_in[4]; // [2048,2048]
    float* out = (float*)d_out;                 // [4,2048,2048]
    (void)in_sizes; (void)n_in; (void)out_size;

    __half *xh, *wqh, *woh, *ah;
    cudaGetSymbolAddress((void**)&xh, g_xh);
    cudaGetSymbolAddress((void**)&wqh, g_wqh);
    cudaGetSymbolAddress((void**)&woh, g_woh);
    cudaGetSymbolAddress((void**)&ah, g_ah);

    cudaFuncSetAttribute(gemm_hf<0>, cudaFuncAttributeMaxDynamicSharedMemorySize, SMEM_GEMM_BYTES);
    cudaFuncSetAttribute(gemm_hf<1>, cudaFuncAttributeMaxDynamicSharedMemorySize, SMEM_GEMM_BYTES);
    cudaFuncSetAttribute(flash_attn, cudaFuncAttributeMaxDynamicSharedMemorySize, FA_SMEM);

    // 0) one-time conversions
    round_f32h<<<16384, 256>>>(x, xh);       // x -> fp16 1-term
    transpose_h<<<dim3(6144 / 32, 2048 / 32), dim3(32, 8)>>>(w_qkv, wqh, 2048, 6144);
    transpose_h<<<dim3(2048 / 32, 2048 / 32), dim3(32, 8)>>>(w_out, woh, 2048, 2048);

    // 1) QKV projection (1-pass); scatter q,k fp32 and v fp16
    gemm_hf<1><<<dim3(48, 64, 1), 256, SMEM_GEMM_BYTES>>>(
        xh, wqh, nullptr, 2048, 2048, 2048, 0);

    // 2) RoPE + fp16 packing of q (2-term) and k (1-term)
    rope_split<<<(Bb_ * H_ * S_ * (HD_ / 2)) / 256, 256>>>(cosT, sinT);

    // 3) fused flash attention -> g_ah fp16 [B,S,D]
    flash_attn<<<dim3(16, Bb_ * H_), 256, FA_SMEM>>>();

    // 4) out = attn @ w_outT^T (1-pass)
    gemm_hf<0><<<dim3(16, 64, 1), 256, SMEM_GEMM_BYTES>>>(
        ah, woh, out, 2048, 2048, 2048, 2048);
}

// round 14
// speedup vs baseline: 7.0280x; 1.0991x over previous
#include <cuda_runtime.h>
#include <cuda_fp16.h>
#include <cstdint>
#include <math.h>

// Problem constants: B=4, S=2048, D=2048, H=16, hd=128
#define Bb_ 4
#define S_  2048
#define H_  16
#define HD_ 128
#define D_  2048

// ---------------- scratch (device globals; allocation-free) ----------------
__device__ float g_q[16777216];       // [B,H,S,hd] fp32 (pre-rope)
__device__ float g_k[16777216];       // [B,H,S,hd] fp32 (pre-rope)
__device__ __half g_qh[16777216];     // post-rope Q fp16 1-term
__device__ __half g_kh[16777216];     // post-rope K fp16 1-term
__device__ __half g_vh[16777216];     // V fp16 1-term
__device__ __half g_xh[16777216];     // x fp16 1-term [8192,2048]
__device__ __half g_wqh[12582912];    // w_qkv^T fp16 [6144,2048]
__device__ __half g_woh[4194304];     // w_out^T fp16 [2048,2048]
__device__ __half g_ah[16777216];     // attn fp16 [B,S,D]

// ---------------- helpers ----------------
__device__ __forceinline__ uint32_t smem_u32(const void* p) {
    uint32_t a;
    asm("{ .reg .u64 t; cvta.to.shared.u64 t, %1; cvt.u32.u64 %0, t; }" : "=r"(a) : "l"(p));
    return a;
}
__device__ __forceinline__ void ldsm4(uint32_t* r, uint32_t addr) {
    asm volatile("ldmatrix.sync.aligned.m8n8.x4.shared.b16 {%0,%1,%2,%3}, [%4];"
                 : "=r"(r[0]), "=r"(r[1]), "=r"(r[2]), "=r"(r[3]) : "r"(addr));
}
__device__ __forceinline__ void ldsm4t(uint32_t* r, uint32_t addr) {
    asm volatile("ldmatrix.sync.aligned.m8n8.x4.trans.shared.b16 {%0,%1,%2,%3}, [%4];"
                 : "=r"(r[0]), "=r"(r[1]), "=r"(r[2]), "=r"(r[3]) : "r"(addr));
}
__device__ __forceinline__ void mma_f16(float* c, const uint32_t* a, uint32_t b0, uint32_t b1) {
    asm volatile(
        "mma.sync.aligned.m16n8k16.row.col.f32.f16.f16.f32 "
        "{%0,%1,%2,%3}, {%4,%5,%6,%7}, {%8,%9}, {%0,%1,%2,%3};"
        : "+f"(c[0]), "+f"(c[1]), "+f"(c[2]), "+f"(c[3])
        : "r"(a[0]), "r"(a[1]), "r"(a[2]), "r"(a[3]), "r"(b0), "r"(b1));
}
__device__ __forceinline__ uint32_t sw128(uint32_t off) { return off ^ ((off >> 3) & 0x70); }
__device__ __forceinline__ void cpa16(uint32_t dst, const void* src) {
    asm volatile("cp.async.cg.shared.global [%0], [%1], 16;" :: "r"(dst), "l"(src));
}
__device__ __forceinline__ void cpa_commit() { asm volatile("cp.async.commit_group;" ::: "memory"); }
__device__ __forceinline__ void cpa_wait0()  { asm volatile("cp.async.wait_group 0;" ::: "memory"); }
__device__ __forceinline__ void cpa_wait1()  { asm volatile("cp.async.wait_group 1;" ::: "memory"); }
__device__ __forceinline__ float ex2(float x) {
    float r; asm("ex2.approx.f32 %0, %1;" : "=f"(r) : "f"(x)); return r;
}
__device__ __forceinline__ uint32_t packh(float a, float b) {
    __half ha = __float2half(a), hb = __float2half(b);
    return (uint32_t)__half_as_ushort(ha) | ((uint32_t)__half_as_ushort(hb) << 16);
}

// ---------------- one-time conversion kernels ----------------
__global__ void round_f32h(const float* __restrict__ src, __half* __restrict__ dst)
{
    const long long i = (long long)blockIdx.x * 256 + threadIdx.x;   // per float4
    float4 v = ((const float4*)src)[i];
    uint2 h;
    h.x = packh(v.x, v.y);
    h.y = packh(v.z, v.w);
    ((uint2*)dst)[i] = h;
}

// transpose + fp16 round: dst[C][R] = fp16(src[R][C])
__global__ void transpose_h(const float* __restrict__ src, __half* __restrict__ dst,
                            int R, int Cc)
{
    __shared__ float t[32][33];
    const int bx = blockIdx.x * 32, by = blockIdx.y * 32;
    const int txx = threadIdx.x, tyy = threadIdx.y;
#pragma unroll
    for (int i = 0; i < 4; ++i)
        t[tyy + i * 8][txx] = src[(long long)(by + tyy + i * 8) * Cc + bx + txx];
    __syncthreads();
#pragma unroll
    for (int i = 0; i < 4; ++i)
        dst[(long long)(bx + tyy + i * 8) * R + by + txx] = __float2half(t[txx][tyy + i * 8]);
}

// ---------------- fp16 mma.sync TN GEMM, 3-stage pipeline ----------------
// C[M,N] = Ah[M,K] @ Bh[N,K]^T, fp32 accum. Block 128x128, 8 warps (4x2),
// warp tile 32x64, K chunk 64. 3-stage cp.async + register frag double-buffer.
// MODE: 0 = plain fp32 C write, 1 = qkv scatter (q,k fp32; v fp16)
#define SMEM_GEMM_BYTES 99328
#define TOFF(buf, which) (1024u + (uint32_t)(buf) * 32768u + (uint32_t)(which) * 16384u)

// one 128x64 fp16 tile -> SW128 smem via cp.async (256 threads, 4 per thread)
__device__ __forceinline__ void cpa_tile(uint32_t sdst, const __half* __restrict__ src,
                                         int ld, int row0, int kbase, int tid) {
#pragma unroll
    for (int p = 0; p < 4; ++p) {
        const int g = tid + p * 256;         // 0..1023
        const int row = g >> 3;              // 0..127
        const int seg = g & 7;               // 16B segment
        cpa16(sdst + sw128(row * 128 + seg * 16),
              src + (long long)(row0 + row) * ld + kbase + seg * 8);
    }
}

template<int MODE>
__global__ __launch_bounds__(256, 1)
void gemm_hf(const __half* __restrict__ Ah, const __half* __restrict__ Bh,
             float* __restrict__ C, int K, int lda, int ldb, int ldc)
{
    const int m0 = blockIdx.y * 128;
    const int n0 = blockIdx.x * 128;
    const int nchunks = K >> 6;   // >= 32 for all our shapes

    extern __shared__ char smem[];
    const uint32_t sb = smem_u32(smem);
    const int tid = threadIdx.x;
    const int lane = tid & 31;
    const int wid = tid >> 5;
    const int wm = (wid & 3) * 32;
    const int wn = (wid >> 2) * 64;
    const int lq = lane >> 3, lr = lane & 7;

    const int a_row = wm + (lq & 1) * 8 + lr;
    const int a_kc2 = (lq >> 1) * 16;
    const int b_row = wn + (lq >> 1) * 8 + lr;
    const int b_kc2 = (lq & 1) * 16;

    float acc[2][8][4];
#pragma unroll
    for (int i = 0; i < 2; i++)
#pragma unroll
        for (int j = 0; j < 8; j++)
#pragma unroll
            for (int e = 0; e < 4; e++) acc[i][j][e] = 0.f;

    // prologue: stage chunks 0 and 1 as separate commit groups
    cpa_tile(sb + TOFF(0, 0), Ah, lda, m0, 0, tid);
    cpa_tile(sb + TOFF(0, 1), Bh, ldb, n0, 0, tid);
    cpa_commit();
    cpa_tile(sb + TOFF(1, 0), Ah, lda, m0, 64, tid);
    cpa_tile(sb + TOFF(1, 1), Bh, ldb, n0, 64, tid);
    cpa_commit();
    cpa_wait1();            // chunk 0 resident
    __syncthreads();

    uint32_t aF[2][2][4], bF[2][4][4];

    for (int c = 0; c < nchunks; ++c) {
        const int buf = c % 3;
        // prefetch chunk c+2 (always commit a group to keep wait_group bookkeeping exact)
        if (c + 2 < nchunks) {
            const int nb = (c + 2) % 3;
            const int kb = (c + 2) * 64;
            cpa_tile(sb + TOFF(nb, 0), Ah, lda, m0, kb, tid);
            cpa_tile(sb + TOFF(nb, 1), Bh, ldb, n0, kb, tid);
        }
        cpa_commit();

        const uint32_t sA = sb + TOFF(buf, 0);
        const uint32_t sB = sb + TOFF(buf, 1);

        // fragment pipeline across kk
        {
#pragma unroll
            for (int i = 0; i < 2; ++i)
                ldsm4(aF[0][i], sA + sw128((a_row + i * 16) * 128 + a_kc2));
#pragma unroll
            for (int jp = 0; jp < 4; ++jp)
                ldsm4(bF[0][jp], sB + sw128((b_row + jp * 16) * 128 + b_kc2));
        }
#pragma unroll
        for (int kk = 0; kk < 4; ++kk) {
            const int cur = kk & 1;
            if (kk < 3) {
                const int nxt = cur ^ 1;
                const uint32_t kb = (kk + 1) * 32;
#pragma unroll
                for (int i = 0; i < 2; ++i)
                    ldsm4(aF[nxt][i], sA + sw128((a_row + i * 16) * 128 + kb + a_kc2));
#pragma unroll
                for (int jp = 0; jp < 4; ++jp)
                    ldsm4(bF[nxt][jp], sB + sw128((b_row + jp * 16) * 128 + kb + b_kc2));
            }
#pragma unroll
            for (int i = 0; i < 2; ++i)
#pragma unroll
                for (int jp = 0; jp < 4; ++jp) {
                    mma_f16(acc[i][2 * jp],     aF[cur][i], bF[cur][jp][0], bF[cur][jp][1]);
                    mma_f16(acc[i][2 * jp + 1], aF[cur][i], bF[cur][jp][2], bF[cur][jp][3]);
                }
        }

        cpa_wait1();        // chunk c+1's group retired (newest group may still fly)
        __syncthreads();
    }

    const int lm = lane >> 2;
    const int ln = (lane & 3) * 2;
#pragma unroll
    for (int i = 0; i < 2; ++i) {
#pragma unroll
        for (int j = 0; j < 8; ++j) {
            const int gn = n0 + wn + j * 8 + ln;
#pragma unroll
            for (int half = 0; half < 2; ++half) {
                const int gm = m0 + wm + i * 16 + lm + half * 8;
                float v0 = acc[i][j][half * 2 + 0];
                float v1 = acc[i][j][half * 2 + 1];
                if (MODE == 0) {
                    *(float2*)(C + (long long)gm * ldc + gn) = make_float2(v0, v1);
                } else {
                    const int t = gn >> 11, h = (gn >> 7) & 15, d = gn & 127;
                    const int b = gm >> 11, s = gm & 2047;
                    const long long idx = ((long long)(b * H_ + h) * S_ + s) * HD_ + d;
                    if (t == 0)      *(float2*)(g_q + idx) = make_float2(v0, v1);
                    else if (t == 1) *(float2*)(g_k + idx) = make_float2(v0, v1);
                    else             *(uint32_t*)(g_vh + idx) = packh(v0, v1);
                }
            }
        }
    }
}

// ---------------- RoPE: Q,K -> fp16 1-term ----------------
__global__ void rope_split(const float* __restrict__ cosT, const float* __restrict__ sinT)
{
    const long long idx = (long long)blockIdx.x * 256 + threadIdx.x;
    const int i = (int)(idx & 63);
    const int s = (int)((idx >> 6) & 2047);
    const int z = (int)(idx >> 17);
    const float c  = cosT[s * 64 + i];
    const float sn = sinT[s * 64 + i];
    const long long base = ((long long)z * S_ + s) * HD_;

    float q1 = g_q[base + i], q2 = g_q[base + 64 + i];
    g_qh[base + i]      = __float2half(q1 * c - q2 * sn);
    g_qh[base + 64 + i] = __float2half(q1 * sn + q2 * c);

    float k1 = g_k[base + i], k2 = g_k[base + 64 + i];
    g_kh[base + i]      = __float2half(k1 * c - k2 * sn);
    g_kh[base + 64 + i] = __float2half(k1 * sn + k2 * c);
}

// ---------------- fused flash attention (all fp16 1-term, fp32 accum) -------
// CTA: (q-tile 128, bh). 8 warps x 16 q-rows. K/V chunks 64 rows, double-
// buffered cp.async. Scores in registers; MMA1 C-frag repacked as MMA2 A-frag.
// smem: Q 32KB @0; kv buf b @32768+b*32768: Kh 16KB, Vh 16KB.
#define FA_SMEM 98304

__device__ __forceinline__ void fa_load_kv(uint32_t kvbase, int bh, int s0, int tid) {
#pragma unroll
    for (int p = 0; p < 4; ++p) {
        const int g = tid + p * 256;          // 0..1023
        const int row = g >> 4;               // 0..63
        const int b16i = g & 15;
        const uint32_t byte = b16i * 16;
        const long long srcoff = (((long long)(bh << 11) + s0 + row) << 7) + b16i * 8;
        const uint32_t dst = kvbase + (byte >> 7) * 8192 + sw128(row * 128 + (byte & 127));
        cpa16(dst,         g_kh + srcoff);
        cpa16(dst + 16384, g_vh + srcoff);
    }
}

__global__ __launch_bounds__(256, 1)
void flash_attn()
{
    const int qt = 15 - blockIdx.x;           // big tiles first
    const int q0 = qt << 7;
    const int bh = blockIdx.y;
    const int nch = (qt + 1) * 2;

    extern __shared__ char smem[];
    const uint32_t sb = smem_u32(smem);
    const int tid = threadIdx.x;
    const int w = tid >> 5;
    const int lane = tid & 31;
    const int wq = w * 16;
    const int lq = lane >> 3, lr = lane & 7;
    const int lc = lane & 3;
    const int lrow = lane >> 2;

    // prologue: Q + chunk 0
#pragma unroll
    for (int p = 0; p < 4; ++p) {
        const int g = tid + p * 256;          // 0..1023
        const int row = g >> 3;               // 0..127
        const int b16i = g & 7;               // 8 segs of 16B... (256B row => 16 segs; use 2 cpa)
        const uint32_t byte0 = b16i * 16;
        const long long srcoff0 = (((long long)(bh << 11) + q0 + row) << 7) + b16i * 8;
        cpa16(sb + (byte0 >> 7) * 16384 + sw128(row * 128 + (byte0 & 127)), g_qh + srcoff0);
        const uint32_t byte1 = byte0 + 128;
        const long long srcoff1 = srcoff0 + 64;
        cpa16(sb + (byte1 >> 7) * 16384 + sw128(row * 128 + (byte1 & 127)), g_qh + srcoff1);
    }
    fa_load_kv(sb + 32768, bh, 0, tid);
    cpa_commit();
    cpa_wait0();
    __syncthreads();

    const float C = 0.08838834764831845f * 1.4426950408889634f; // scale*log2(e)
    float o[16][4];
#pragma unroll
    for (int t = 0; t < 16; ++t)
#pragma unroll
        for (int e = 0; e < 4; ++e) o[t][e] = 0.f;
    float m0 = -1e30f, m1 = -1e30f, l0 = 0.f, l1 = 0.f;

    for (int c = 0; c < nch; ++c) {
        const uint32_t kvb = sb + 32768 + (uint32_t)(c & 1) * 32768;
        if (c + 1 < nch) {
            fa_load_kv(sb + 32768 + (uint32_t)((c + 1) & 1) * 32768, bh, (c + 1) * 64, tid);
            cpa_commit();
        }

        // MMA1: scores[16q x 64k] = Q @ K^T
        float s[8][4];
#pragma unroll
        for (int j = 0; j < 8; ++j)
#pragma unroll
            for (int e = 0; e < 4; ++e) s[j][e] = 0.f;

#pragma unroll
        for (int kk = 0; kk < 8; ++kk) {
            const int arow = wq + (lq & 1) * 8 + lr;
            const uint32_t akb = kk * 32 + (lq >> 1) * 16;
            const uint32_t qaddr = sb + (akb >> 7) * 16384 + sw128(arow * 128 + (akb & 127));
            uint32_t a4[4];
            ldsm4(a4, qaddr);
#pragma unroll
            for (int nt = 0; nt < 4; ++nt) {
                const int brow = nt * 16 + (lq >> 1) * 8 + lr;
                const uint32_t bkb = kk * 32 + (lq & 1) * 16;
                const uint32_t kaddr = kvb + (bkb >> 7) * 8192 + sw128(brow * 128 + (bkb & 127));
                uint32_t b4[4];
                ldsm4(b4, kaddr);
                mma_f16(s[2 * nt],     a4, b4[0], b4[1]);
                mma_f16(s[2 * nt + 1], a4, b4[2], b4[3]);
            }
        }

        // causal mask near diagonal
        if (c * 64 + 63 > q0 + wq) {
            const int r0g = q0 + wq + lrow;
#pragma unroll
            for (int j = 0; j < 8; ++j) {
                const int k0 = c * 64 + 8 * j + 2 * lc;
                if (k0 > r0g)         s[j][0] = -1e30f;
                if (k0 + 1 > r0g)     s[j][1] = -1e30f;
                if (k0 > r0g + 8)     s[j][2] = -1e30f;
                if (k0 + 1 > r0g + 8) s[j][3] = -1e30f;
            }
        }

        // online softmax
        float mx0 = -1e30f, mx1 = -1e30f;
#pragma unroll
        for (int j = 0; j < 8; ++j) {
            mx0 = fmaxf(mx0, fmaxf(s[j][0], s[j][1]));
            mx1 = fmaxf(mx1, fmaxf(s[j][2], s[j][3]));
        }
        mx0 = fmaxf(mx0, __shfl_xor_sync(0xffffffffu, mx0, 1));
        mx0 = fmaxf(mx0, __shfl_xor_sync(0xffffffffu, mx0, 2));
        mx1 = fmaxf(mx1, __shfl_xor_sync(0xffffffffu, mx1, 1));
        mx1 = fmaxf(mx1, __shfl_xor_sync(0xffffffffu, mx1, 2));
        const float mn0 = fmaxf(m0, mx0), mn1 = fmaxf(m1, mx1);
        const float al0 = ex2((m0 - mn0) * C), al1 = ex2((m1 - mn1) * C);
        m0 = mn0; m1 = mn1;
        l0 *= al0; l1 *= al1;
#pragma unroll
        for (int t = 0; t < 16; ++t) {
            o[t][0] *= al0; o[t][1] *= al0; o[t][2] *= al1; o[t][3] *= al1;
        }
        uint32_t ph[8][2];
#pragma unroll
        for (int j = 0; j < 8; ++j) {
            float p0 = ex2((s[j][0] - m0) * C);
            float p1 = ex2((s[j][1] - m0) * C);
            float p2 = ex2((s[j][2] - m1) * C);
            float p3 = ex2((s[j][3] - m1) * C);
            l0 += p0 + p1; l1 += p2 + p3;
            ph[j][0] = packh(p0, p1);
            ph[j][1] = packh(p2, p3);
        }

        // MMA2: O += P @ V (V via trans ldmatrix)
#pragma unroll
        for (int kk = 0; kk < 4; ++kk) {
            uint32_t pa[4] = { ph[2 * kk][0], ph[2 * kk][1], ph[2 * kk + 1][0], ph[2 * kk + 1][1] };
#pragma unroll
            for (int nt = 0; nt < 8; ++nt) {
                const int vrow = kk * 16 + (lq & 1) * 8 + lr;
                const uint32_t nb = nt * 32 + (lq >> 1) * 16;
                const uint32_t vaddr = kvb + 16384 + (nb >> 7) * 8192 + sw128(vrow * 128 + (nb & 127));
                uint32_t v4[4];
                ldsm4t(v4, vaddr);
                mma_f16(o[2 * nt],     pa, v4[0], v4[1]);
                mma_f16(o[2 * nt + 1], pa, v4[2], v4[3]);
            }
        }

        cpa_wait0();
        __syncthreads();
    }

    l0 += __shfl_xor_sync(0xffffffffu, l0, 1);
    l0 += __shfl_xor_sync(0xffffffffu, l0, 2);
    l1 += __shfl_xor_sync(0xffffffffu, l1, 1);
    l1 += __shfl_xor_sync(0xffffffffu, l1, 2);
    const float inv0 = 1.f / l0, inv1 = 1.f / l1;

    // write attn as fp16 [B,S,D]
    const int b = bh >> 4, h = bh & 15;
    const int row0 = q0 + wq + lrow;
    const long long base0 = ((long long)(b * S_ + row0)) * D_ + h * HD_ + 2 * lc;
    const long long base1 = base0 + 8LL * D_;
#pragma unroll
    for (int t = 0; t < 16; ++t) {
        *(uint32_t*)(g_ah + base0 + 8 * t) = packh(o[t][0] * inv0, o[t][1] * inv0);
        *(uint32_t*)(g_ah + base1 + 8 * t) = packh(o[t][2] * inv1, o[t][3] * inv1);
    }
}

// ---------------- launch ----------------
extern "C" void kernel_launch(void* const* d_in, const int* in_sizes, int n_in,
                              void* d_out, int out_size)
{
    const float* x     = (const float*)d_in[0]; // [4,2048,2048]
    const float* cosT  = (const float*)d_in[1]; // [2048,64]
    const float* sinT  = (const float*)d_in[2]; // [2048,64]
    const float* w_qkv = (const float*)d_in[3]; // [2048,6144]
    const float* w_out = (const float*)d_in[4]; // [2048,2048]
    float* out = (float*)d_out;                 // [4,2048,2048]
    (void)in_sizes; (void)n_in; (void)out_size;

    __half *xh, *wqh, *woh, *ah;
    cudaGetSymbolAddress((void**)&xh, g_xh);
    cudaGetSymbolAddress((void**)&wqh, g_wqh);
    cudaGetSymbolAddress((void**)&woh, g_woh);
    cudaGetSymbolAddress((void**)&ah, g_ah);

    cudaFuncSetAttribute(gemm_hf<0>, cudaFuncAttributeMaxDynamicSharedMemorySize, SMEM_GEMM_BYTES);
    cudaFuncSetAttribute(gemm_hf<1>, cudaFuncAttributeMaxDynamicSharedMemorySize, SMEM_GEMM_BYTES);
    cudaFuncSetAttribute(flash_attn, cudaFuncAttributeMaxDynamicSharedMemorySize, FA_SMEM);

    // 0) one-time conversions
    round_f32h<<<16384, 256>>>(x, xh);
    transpose_h<<<dim3(6144 / 32, 2048 / 32), dim3(32, 8)>>>(w_qkv, wqh, 2048, 6144);
    transpose_h<<<dim3(2048 / 32, 2048 / 32), dim3(32, 8)>>>(w_out, woh, 2048, 2048);

    // 1) QKV projection; scatter q,k fp32 and v fp16
    gemm_hf<1><<<dim3(48, 64, 1), 256, SMEM_GEMM_BYTES>>>(
        xh, wqh, nullptr, 2048, 2048, 2048, 0);

    // 2) RoPE -> fp16 q,k
    rope_split<<<(Bb_ * H_ * S_ * (HD_ / 2)) / 256, 256>>>(cosT, sinT);

    // 3) fused flash attention -> g_ah fp16 [B,S,D]
    flash_attn<<<dim3(16, Bb_ * H_), 256, FA_SMEM>>>();

    // 4) out = attn @ w_outT^T
    gemm_hf<0><<<dim3(16, 64, 1), 256, SMEM_GEMM_BYTES>>>(
        ah, woh, out, 2048, 2048, 2048, 2048);
}

// round 15
// speedup vs baseline: 7.3128x; 1.0405x over previous
#include <cuda_runtime.h>
#include <cuda_fp16.h>
#include <cstdint>
#include <math.h>

// Problem constants: B=4, S=2048, D=2048, H=16, hd=128
#define Bb_ 4
#define S_  2048
#define H_  16
#define HD_ 128
#define D_  2048

// ---------------- scratch (device globals; allocation-free) ----------------
__device__ float g_q[16777216];       // [B,H,S,hd] fp32 (pre-rope)
__device__ float g_k[16777216];       // [B,H,S,hd] fp32 (pre-rope)
__device__ __half g_qh[16777216];     // post-rope Q fp16
__device__ __half g_kh[16777216];     // post-rope K fp16
__device__ __half g_vh[16777216];     // V fp16
__device__ __half g_xh[16777216];     // x fp16 [8192,2048]
__device__ __half g_wqh[12582912];    // w_qkv^T fp16 [6144,2048]
__device__ __half g_woh[4194304];     // w_out^T fp16 [2048,2048]
__device__ __half g_ah[16777216];     // attn fp16 [B,S,D]

// ---------------- helpers ----------------
__device__ __forceinline__ uint32_t smem_u32(const void* p) {
    uint32_t a;
    asm("{ .reg .u64 t; cvta.to.shared.u64 t, %1; cvt.u32.u64 %0, t; }" : "=r"(a) : "l"(p));
    return a;
}
__device__ __forceinline__ void ldsm4(uint32_t* r, uint32_t addr) {
    asm volatile("ldmatrix.sync.aligned.m8n8.x4.shared.b16 {%0,%1,%2,%3}, [%4];"
                 : "=r"(r[0]), "=r"(r[1]), "=r"(r[2]), "=r"(r[3]) : "r"(addr));
}
__device__ __forceinline__ void ldsm4t(uint32_t* r, uint32_t addr) {
    asm volatile("ldmatrix.sync.aligned.m8n8.x4.trans.shared.b16 {%0,%1,%2,%3}, [%4];"
                 : "=r"(r[0]), "=r"(r[1]), "=r"(r[2]), "=r"(r[3]) : "r"(addr));
}
__device__ __forceinline__ void mma_f16(float* c, const uint32_t* a, uint32_t b0, uint32_t b1) {
    asm volatile(
        "mma.sync.aligned.m16n8k16.row.col.f32.f16.f16.f32 "
        "{%0,%1,%2,%3}, {%4,%5,%6,%7}, {%8,%9}, {%0,%1,%2,%3};"
        : "+f"(c[0]), "+f"(c[1]), "+f"(c[2]), "+f"(c[3])
        : "r"(a[0]), "r"(a[1]), "r"(a[2]), "r"(a[3]), "r"(b0), "r"(b1));
}
__device__ __forceinline__ uint32_t sw128(uint32_t off) { return off ^ ((off >> 3) & 0x70); }
__device__ __forceinline__ void cpa16(uint32_t dst, const void* src) {
    asm volatile("cp.async.cg.shared.global [%0], [%1], 16;" :: "r"(dst), "l"(src));
}
__device__ __forceinline__ void cpa_commit() { asm volatile("cp.async.commit_group;" ::: "memory"); }
__device__ __forceinline__ void cpa_wait0()  { asm volatile("cp.async.wait_group 0;" ::: "memory"); }
__device__ __forceinline__ void cpa_wait1()  { asm volatile("cp.async.wait_group 1;" ::: "memory"); }
__device__ __forceinline__ float ex2(float x) {
    float r; asm("ex2.approx.f32 %0, %1;" : "=f"(r) : "f"(x)); return r;
}
__device__ __forceinline__ uint32_t packh(float a, float b) {
    __half ha = __float2half(a), hb = __float2half(b);
    return (uint32_t)__half_as_ushort(ha) | ((uint32_t)__half_as_ushort(hb) << 16);
}

// ---------------- one-time conversion kernels ----------------
__global__ void round_f32h(const float* __restrict__ src, __half* __restrict__ dst)
{
    const long long i = (long long)blockIdx.x * 256 + threadIdx.x;   // per float4
    float4 v = ((const float4*)src)[i];
    uint2 h;
    h.x = packh(v.x, v.y);
    h.y = packh(v.z, v.w);
    ((uint2*)dst)[i] = h;
}

// transpose + fp16 round: dst[C][R] = fp16(src[R][C])
__global__ void transpose_h(const float* __restrict__ src, __half* __restrict__ dst,
                            int R, int Cc)
{
    __shared__ float t[32][33];
    const int bx = blockIdx.x * 32, by = blockIdx.y * 32;
    const int txx = threadIdx.x, tyy = threadIdx.y;
#pragma unroll
    for (int i = 0; i < 4; ++i)
        t[tyy + i * 8][txx] = src[(long long)(by + tyy + i * 8) * Cc + bx + txx];
    __syncthreads();
#pragma unroll
    for (int i = 0; i < 4; ++i)
        dst[(long long)(bx + tyy + i * 8) * R + by + txx] = __float2half(t[txx][tyy + i * 8]);
}

// ---------------- fp16 mma.sync TN GEMM, 256x128 tile ----------------
// C[M,N] = Ah[M,K] @ Bh[N,K]^T, fp32 accum. Block 256x128, 8 warps (4x2),
// warp tile 64x64, K chunk 64, 3-stage cp.async.
// MODE: 0 = plain fp32 C write, 1 = qkv scatter (q,k fp32; v fp16)
#define SMEM_GEMM_BYTES 148480   // 1024 + 3 * 49152
#define TOFF_A(buf) (1024u + (uint32_t)(buf) * 49152u)
#define TOFF_B(buf) (1024u + (uint32_t)(buf) * 49152u + 32768u)

// A tile 256x64 fp16 (32KB): 2048 16B-segments, 256 threads x 8
__device__ __forceinline__ void cpa_tile_a(uint32_t sdst, const __half* __restrict__ src,
                                           int ld, int row0, int kbase, int tid) {
#pragma unroll
    for (int p = 0; p < 8; ++p) {
        const int g = tid + p * 256;         // 0..2047
        const int row = g >> 3;              // 0..255
        const int seg = g & 7;
        cpa16(sdst + sw128(row * 128 + seg * 16),
              src + (long long)(row0 + row) * ld + kbase + seg * 8);
    }
}
// B tile 128x64 fp16 (16KB): 1024 segments, 256 threads x 4
__device__ __forceinline__ void cpa_tile_b(uint32_t sdst, const __half* __restrict__ src,
                                           int ld, int row0, int kbase, int tid) {
#pragma unroll
    for (int p = 0; p < 4; ++p) {
        const int g = tid + p * 256;         // 0..1023
        const int row = g >> 3;              // 0..127
        const int seg = g & 7;
        cpa16(sdst + sw128(row * 128 + seg * 16),
              src + (long long)(row0 + row) * ld + kbase + seg * 8);
    }
}

template<int MODE>
__global__ __launch_bounds__(256, 1)
void gemm_hf(const __half* __restrict__ Ah, const __half* __restrict__ Bh,
             float* __restrict__ C, int K, int lda, int ldb, int ldc)
{
    const int m0 = blockIdx.y * 256;
    const int n0 = blockIdx.x * 128;
    const int nchunks = K >> 6;

    extern __shared__ char smem[];
    const uint32_t sb = smem_u32(smem);
    const int tid = threadIdx.x;
    const int lane = tid & 31;
    const int wid = tid >> 5;
    const int wm = (wid & 3) * 64;       // warp M offset (0..192)
    const int wn = (wid >> 2) * 64;      // warp N offset (0/64)
    const int lq = lane >> 3, lr = lane & 7;

    const int a_row = wm + (lq & 1) * 8 + lr;     // + i*16, i<4
    const int a_kc2 = (lq >> 1) * 16;
    const int b_row = wn + (lq >> 1) * 8 + lr;    // + jp*16, jp<4
    const int b_kc2 = (lq & 1) * 16;

    float acc[4][8][4];
#pragma unroll
    for (int i = 0; i < 4; i++)
#pragma unroll
        for (int j = 0; j < 8; j++)
#pragma unroll
            for (int e = 0; e < 4; e++) acc[i][j][e] = 0.f;

    // prologue: stage chunks 0 and 1
    cpa_tile_a(TOFF_A(0) + sb, Ah, lda, m0, 0, tid);
    cpa_tile_b(TOFF_B(0) + sb, Bh, ldb, n0, 0, tid);
    cpa_commit();
    cpa_tile_a(TOFF_A(1) + sb, Ah, lda, m0, 64, tid);
    cpa_tile_b(TOFF_B(1) + sb, Bh, ldb, n0, 64, tid);
    cpa_commit();
    cpa_wait1();            // chunk 0 resident
    __syncthreads();

    for (int c = 0; c < nchunks; ++c) {
        const int buf = c % 3;
        if (c + 2 < nchunks) {
            const int nb = (c + 2) % 3;
            const int kb = (c + 2) * 64;
            cpa_tile_a(TOFF_A(nb) + sb, Ah, lda, m0, kb, tid);
            cpa_tile_b(TOFF_B(nb) + sb, Bh, ldb, n0, kb, tid);
        }
        cpa_commit();

        const uint32_t sA = sb + TOFF_A(buf);
        const uint32_t sB = sb + TOFF_B(buf);
#pragma unroll
        for (int kk = 0; kk < 4; ++kk) {
            uint32_t aF[4][4], bF[4][4];
#pragma unroll
            for (int i = 0; i < 4; ++i)
                ldsm4(aF[i], sA + sw128((a_row + i * 16) * 128 + kk * 32 + a_kc2));
#pragma unroll
            for (int jp = 0; jp < 4; ++jp)
                ldsm4(bF[jp], sB + sw128((b_row + jp * 16) * 128 + kk * 32 + b_kc2));
#pragma unroll
            for (int i = 0; i < 4; ++i)
#pragma unroll
                for (int jp = 0; jp < 4; ++jp) {
                    mma_f16(acc[i][2 * jp],     aF[i], bF[jp][0], bF[jp][1]);
                    mma_f16(acc[i][2 * jp + 1], aF[i], bF[jp][2], bF[jp][3]);
                }
        }

        cpa_wait1();
        __syncthreads();
    }

    const int lm = lane >> 2;
    const int ln = (lane & 3) * 2;
#pragma unroll
    for (int i = 0; i < 4; ++i) {
#pragma unroll
        for (int j = 0; j < 8; ++j) {
            const int gn = n0 + wn + j * 8 + ln;
#pragma unroll
            for (int half = 0; half < 2; ++half) {
                const int gm = m0 + wm + i * 16 + lm + half * 8;
                float v0 = acc[i][j][half * 2 + 0];
                float v1 = acc[i][j][half * 2 + 1];
                if (MODE == 0) {
                    *(float2*)(C + (long long)gm * ldc + gn) = make_float2(v0, v1);
                } else {
                    const int t = gn >> 11, h = (gn >> 7) & 15, d = gn & 127;
                    const int b = gm >> 11, s = gm & 2047;
                    const long long idx = ((long long)(b * H_ + h) * S_ + s) * HD_ + d;
                    if (t == 0)      *(float2*)(g_q + idx) = make_float2(v0, v1);
                    else if (t == 1) *(float2*)(g_k + idx) = make_float2(v0, v1);
                    else             *(uint32_t*)(g_vh + idx) = packh(v0, v1);
                }
            }
        }
    }
}

// ---------------- RoPE: Q,K -> fp16 ----------------
__global__ void rope_split(const float* __restrict__ cosT, const float* __restrict__ sinT)
{
    const long long idx = (long long)blockIdx.x * 256 + threadIdx.x;
    const int i = (int)(idx & 63);
    const int s = (int)((idx >> 6) & 2047);
    const int z = (int)(idx >> 17);
    const float c  = cosT[s * 64 + i];
    const float sn = sinT[s * 64 + i];
    const long long base = ((long long)z * S_ + s) * HD_;

    float q1 = g_q[base + i], q2 = g_q[base + 64 + i];
    g_qh[base + i]      = __float2half(q1 * c - q2 * sn);
    g_qh[base + 64 + i] = __float2half(q1 * sn + q2 * c);

    float k1 = g_k[base + i], k2 = g_k[base + 64 + i];
    g_kh[base + i]      = __float2half(k1 * c - k2 * sn);
    g_kh[base + 64 + i] = __float2half(k1 * sn + k2 * c);
}

// ---------------- fused flash attention (fp16, fp32 accum) ----------------
// CTA: (q-tile 128, bh). 8 warps x 16 q-rows. K/V chunks 64 rows, double-
// buffered cp.async. Scores in registers; MMA1 C-frag repacked as MMA2 A-frag.
// smem: Q 32KB @0; kv buf b @32768+b*32768: Kh 16KB, Vh 16KB.
#define FA_SMEM 98304

__device__ __forceinline__ void fa_load_kv(uint32_t kvbase, int bh, int s0, int tid) {
#pragma unroll
    for (int p = 0; p < 4; ++p) {
        const int g = tid + p * 256;          // 0..1023
        const int row = g >> 4;               // 0..63
        const int b16i = g & 15;
        const uint32_t byte = b16i * 16;
        const long long srcoff = (((long long)(bh << 11) + s0 + row) << 7) + b16i * 8;
        const uint32_t dst = kvbase + (byte >> 7) * 8192 + sw128(row * 128 + (byte & 127));
        cpa16(dst,         g_kh + srcoff);
        cpa16(dst + 16384, g_vh + srcoff);
    }
}

__global__ __launch_bounds__(256, 1)
void flash_attn()
{
    const int qt = 15 - blockIdx.x;           // big tiles first
    const int q0 = qt << 7;
    const int bh = blockIdx.y;
    const int nch = (qt + 1) * 2;

    extern __shared__ char smem[];
    const uint32_t sb = smem_u32(smem);
    const int tid = threadIdx.x;
    const int w = tid >> 5;
    const int lane = tid & 31;
    const int wq = w * 16;
    const int lq = lane >> 3, lr = lane & 7;
    const int lc = lane & 3;
    const int lrow = lane >> 2;

    // prologue: Q + chunk 0
#pragma unroll
    for (int p = 0; p < 4; ++p) {
        const int g = tid + p * 256;          // 0..1023
        const int row = g >> 3;               // 0..127
        const int b16i = g & 7;
        const uint32_t byte0 = b16i * 16;
        const long long srcoff0 = (((long long)(bh << 11) + q0 + row) << 7) + b16i * 8;
        cpa16(sb + (byte0 >> 7) * 16384 + sw128(row * 128 + (byte0 & 127)), g_qh + srcoff0);
        const uint32_t byte1 = byte0 + 128;
        const long long srcoff1 = srcoff0 + 64;
        cpa16(sb + (byte1 >> 7) * 16384 + sw128(row * 128 + (byte1 & 127)), g_qh + srcoff1);
    }
    fa_load_kv(sb + 32768, bh, 0, tid);
    cpa_commit();
    cpa_wait0();
    __syncthreads();

    const float C = 0.08838834764831845f * 1.4426950408889634f; // scale*log2(e)
    float o[16][4];
#pragma unroll
    for (int t = 0; t < 16; ++t)
#pragma unroll
        for (int e = 0; e < 4; ++e) o[t][e] = 0.f;
    float m0 = -1e30f, m1 = -1e30f, l0 = 0.f, l1 = 0.f;

    for (int c = 0; c < nch; ++c) {
        const uint32_t kvb = sb + 32768 + (uint32_t)(c & 1) * 32768;
        if (c + 1 < nch) {
            fa_load_kv(sb + 32768 + (uint32_t)((c + 1) & 1) * 32768, bh, (c + 1) * 64, tid);
            cpa_commit();
        }

        // MMA1: scores[16q x 64k] = Q @ K^T
        float s[8][4];
#pragma unroll
        for (int j = 0; j < 8; ++j)
#pragma unroll
            for (int e = 0; e < 4; ++e) s[j][e] = 0.f;

#pragma unroll
        for (int kk = 0; kk < 8; ++kk) {
            const int arow = wq + (lq & 1) * 8 + lr;
            const uint32_t akb = kk * 32 + (lq >> 1) * 16;
            const uint32_t qaddr = sb + (akb >> 7) * 16384 + sw128(arow * 128 + (akb & 127));
            uint32_t a4[4];
            ldsm4(a4, qaddr);
#pragma unroll
            for (int nt = 0; nt < 4; ++nt) {
                const int brow = nt * 16 + (lq >> 1) * 8 + lr;
                const uint32_t bkb = kk * 32 + (lq & 1) * 16;
                const uint32_t kaddr = kvb + (bkb >> 7) * 8192 + sw128(brow * 128 + (bkb & 127));
                uint32_t b4[4];
                ldsm4(b4, kaddr);
                mma_f16(s[2 * nt],     a4, b4[0], b4[1]);
                mma_f16(s[2 * nt + 1], a4, b4[2], b4[3]);
            }
        }

        // causal mask near diagonal
        if (c * 64 + 63 > q0 + wq) {
            const int r0g = q0 + wq + lrow;
#pragma unroll
            for (int j = 0; j < 8; ++j) {
                const int k0 = c * 64 + 8 * j + 2 * lc;
                if (k0 > r0g)         s[j][0] = -1e30f;
                if (k0 + 1 > r0g)     s[j][1] = -1e30f;
                if (k0 > r0g + 8)     s[j][2] = -1e30f;
                if (k0 + 1 > r0g + 8) s[j][3] = -1e30f;
            }
        }

        // online softmax
        float mx0 = -1e30f, mx1 = -1e30f;
#pragma unroll
        for (int j = 0; j < 8; ++j) {
            mx0 = fmaxf(mx0, fmaxf(s[j][0], s[j][1]));
            mx1 = fmaxf(mx1, fmaxf(s[j][2], s[j][3]));
        }
        mx0 = fmaxf(mx0, __shfl_xor_sync(0xffffffffu, mx0, 1));
        mx0 = fmaxf(mx0, __shfl_xor_sync(0xffffffffu, mx0, 2));
        mx1 = fmaxf(mx1, __shfl_xor_sync(0xffffffffu, mx1, 1));
        mx1 = fmaxf(mx1, __shfl_xor_sync(0xffffffffu, mx1, 2));
        const float mn0 = fmaxf(m0, mx0), mn1 = fmaxf(m1, mx1);
        const float al0 = ex2((m0 - mn0) * C), al1 = ex2((m1 - mn1) * C);
        m0 = mn0; m1 = mn1;
        l0 *= al0; l1 *= al1;
#pragma unroll
        for (int t = 0; t < 16; ++t) {
            o[t][0] *= al0; o[t][1] *= al0; o[t][2] *= al1; o[t][3] *= al1;
        }
        uint32_t ph[8][2];
#pragma unroll
        for (int j = 0; j < 8; ++j) {
            float p0 = ex2((s[j][0] - m0) * C);
            float p1 = ex2((s[j][1] - m0) * C);
            float p2 = ex2((s[j][2] - m1) * C);
            float p3 = ex2((s[j][3] - m1) * C);
            l0 += p0 + p1; l1 += p2 + p3;
            ph[j][0] = packh(p0, p1);
            ph[j][1] = packh(p2, p3);
        }

        // MMA2: O += P @ V (V via trans ldmatrix)
#pragma unroll
        for (int kk = 0; kk < 4; ++kk) {
            uint32_t pa[4] = { ph[2 * kk][0], ph[2 * kk][1], ph[2 * kk + 1][0], ph[2 * kk + 1][1] };
#pragma unroll
            for (int nt = 0; nt < 8; ++nt) {
                const int vrow = kk * 16 + (lq & 1) * 8 + lr;
                const uint32_t nb = nt * 32 + (lq >> 1) * 16;
                const uint32_t vaddr = kvb + 16384 + (nb >> 7) * 8192 + sw128(vrow * 128 + (nb & 127));
                uint32_t v4[4];
                ldsm4t(v4, vaddr);
                mma_f16(o[2 * nt],     pa, v4[0], v4[1]);
                mma_f16(o[2 * nt + 1], pa, v4[2], v4[3]);
            }
        }

        cpa_wait0();
        __syncthreads();
    }

    l0 += __shfl_xor_sync(0xffffffffu, l0, 1);
    l0 += __shfl_xor_sync(0xffffffffu, l0, 2);
    l1 += __shfl_xor_sync(0xffffffffu, l1, 1);
    l1 += __shfl_xor_sync(0xffffffffu, l1, 2);
    const float inv0 = 1.f / l0, inv1 = 1.f / l1;

    // write attn as fp16 [B,S,D]
    const int b = bh >> 4, h = bh & 15;
    const int row0 = q0 + wq + lrow;
    const long long base0 = ((long long)(b * S_ + row0)) * D_ + h * HD_ + 2 * lc;
    const long long base1 = base0 + 8LL * D_;
#pragma unroll
    for (int t = 0; t < 16; ++t) {
        *(uint32_t*)(g_ah + base0 + 8 * t) = packh(o[t][0] * inv0, o[t][1] * inv0);
        *(uint32_t*)(g_ah + base1 + 8 * t) = packh(o[t][2] * inv1, o[t][3] * inv1);
    }
}

// ---------------- launch ----------------
extern "C" void kernel_launch(void* const* d_in, const int* in_sizes, int n_in,
                              void* d_out, int out_size)
{
    const float* x     = (const float*)d_in[0]; // [4,2048,2048]
    const float* cosT  = (const float*)d_in[1]; // [2048,64]
    const float* sinT  = (const float*)d_in[2]; // [2048,64]
    const float* w_qkv = (const float*)d_in[3]; // [2048,6144]
    const float* w_out = (const float*)d_in[4]; // [2048,2048]
    float* out = (float*)d_out;                 // [4,2048,2048]
    (void)in_sizes; (void)n_in; (void)out_size;

    __half *xh, *wqh, *woh, *ah;
    cudaGetSymbolAddress((void**)&xh, g_xh);
    cudaGetSymbolAddress((void**)&wqh, g_wqh);
    cudaGetSymbolAddress((void**)&woh, g_woh);
    cudaGetSymbolAddress((void**)&ah, g_ah);

    cudaFuncSetAttribute(gemm_hf<0>, cudaFuncAttributeMaxDynamicSharedMemorySize, SMEM_GEMM_BYTES);
    cudaFuncSetAttribute(gemm_hf<1>, cudaFuncAttributeMaxDynamicSharedMemorySize, SMEM_GEMM_BYTES);
    cudaFuncSetAttribute(flash_attn, cudaFuncAttributeMaxDynamicSharedMemorySize, FA_SMEM);

    // 0) one-time conversions
    round_f32h<<<16384, 256>>>(x, xh);
    transpose_h<<<dim3(6144 / 32, 2048 / 32), dim3(32, 8)>>>(w_qkv, wqh, 2048, 6144);
    transpose_h<<<dim3(2048 / 32, 2048 / 32), dim3(32, 8)>>>(w_out, woh, 2048, 2048);

    // 1) QKV projection (256x128 tile); scatter q,k fp32 and v fp16
    gemm_hf<1><<<dim3(48, 32, 1), 256, SMEM_GEMM_BYTES>>>(
        xh, wqh, nullptr, 2048, 2048, 2048, 0);

    // 2) RoPE -> fp16 q,k
    rope_split<<<(Bb_ * H_ * S_ * (HD_ / 2)) / 256, 256>>>(cosT, sinT);

    // 3) fused flash attention -> g_ah fp16 [B,S,D]
    flash_attn<<<dim3(16, Bb_ * H_), 256, FA_SMEM>>>();

    // 4) out = attn @ w_outT^T
    gemm_hf<0><<<dim3(16, 32, 1), 256, SMEM_GEMM_BYTES>>>(
        ah, woh, out, 2048, 2048, 2048, 2048);
}

// round 16
// speedup vs baseline: 7.7998x; 1.0666x over previous
#include <cuda_runtime.h>
#include <cuda_fp16.h>
#include <cstdint>
#include <math.h>

// Problem constants: B=4, S=2048, D=2048, H=16, hd=128
#define Bb_ 4
#define S_  2048
#define H_  16
#define HD_ 128
#define D_  2048

// ---------------- scratch (device globals; allocation-free) ----------------
__device__ float g_q[16777216];       // [B,H,S,hd] fp32 (pre-rope)
__device__ float g_k[16777216];       // [B,H,S,hd] fp32 (pre-rope)
__device__ __half g_qh[16777216];     // post-rope Q fp16
__device__ __half g_kh[16777216];     // post-rope K fp16
__device__ __half g_vh[16777216];     // V fp16
__device__ __half g_xh[16777216];     // x fp16 [8192,2048]
__device__ __half g_wqh[12582912];    // w_qkv^T fp16 [6144,2048]
__device__ __half g_woh[4194304];     // w_out^T fp16 [2048,2048]
__device__ __half g_ah[16777216];     // attn fp16 [B,S,D]

// ---------------- helpers ----------------
__device__ __forceinline__ uint32_t smem_u32(const void* p) {
    uint32_t a;
    asm("{ .reg .u64 t; cvta.to.shared.u64 t, %1; cvt.u32.u64 %0, t; }" : "=r"(a) : "l"(p));
    return a;
}
__device__ __forceinline__ void ldsm4(uint32_t* r, uint32_t addr) {
    asm volatile("ldmatrix.sync.aligned.m8n8.x4.shared.b16 {%0,%1,%2,%3}, [%4];"
                 : "=r"(r[0]), "=r"(r[1]), "=r"(r[2]), "=r"(r[3]) : "r"(addr));
}
__device__ __forceinline__ void ldsm4t(uint32_t* r, uint32_t addr) {
    asm volatile("ldmatrix.sync.aligned.m8n8.x4.trans.shared.b16 {%0,%1,%2,%3}, [%4];"
                 : "=r"(r[0]), "=r"(r[1]), "=r"(r[2]), "=r"(r[3]) : "r"(addr));
}
__device__ __forceinline__ void mma_f16(float* c, const uint32_t* a, uint32_t b0, uint32_t b1) {
    asm volatile(
        "mma.sync.aligned.m16n8k16.row.col.f32.f16.f16.f32 "
        "{%0,%1,%2,%3}, {%4,%5,%6,%7}, {%8,%9}, {%0,%1,%2,%3};"
        : "+f"(c[0]), "+f"(c[1]), "+f"(c[2]), "+f"(c[3])
        : "r"(a[0]), "r"(a[1]), "r"(a[2]), "r"(a[3]), "r"(b0), "r"(b1));
}
__device__ __forceinline__ uint32_t sw128(uint32_t off) { return off ^ ((off >> 3) & 0x70); }
__device__ __forceinline__ void cpa16(uint32_t dst, const void* src) {
    asm volatile("cp.async.cg.shared.global [%0], [%1], 16;" :: "r"(dst), "l"(src));
}
__device__ __forceinline__ void cpa_commit() { asm volatile("cp.async.commit_group;" ::: "memory"); }
__device__ __forceinline__ void cpa_wait0()  { asm volatile("cp.async.wait_group 0;" ::: "memory"); }
__device__ __forceinline__ void cpa_wait1()  { asm volatile("cp.async.wait_group 1;" ::: "memory"); }
__device__ __forceinline__ float ex2(float x) {
    float r; asm("ex2.approx.f32 %0, %1;" : "=f"(r) : "f"(x)); return r;
}
__device__ __forceinline__ uint32_t packh(float a, float b) {
    __half ha = __float2half(a), hb = __float2half(b);
    return (uint32_t)__half_as_ushort(ha) | ((uint32_t)__half_as_ushort(hb) << 16);
}

// ---------------- one-time conversion kernels ----------------
__global__ void round_f32h(const float* __restrict__ src, __half* __restrict__ dst)
{
    const long long i = (long long)blockIdx.x * 256 + threadIdx.x;   // per float4
    float4 v = ((const float4*)src)[i];
    uint2 h;
    h.x = packh(v.x, v.y);
    h.y = packh(v.z, v.w);
    ((uint2*)dst)[i] = h;
}

// transpose + fp16 round: dst[C][R] = fp16(src[R][C])
__global__ void transpose_h(const float* __restrict__ src, __half* __restrict__ dst,
                            int R, int Cc)
{
    __shared__ float t[32][33];
    const int bx = blockIdx.x * 32, by = blockIdx.y * 32;
    const int txx = threadIdx.x, tyy = threadIdx.y;
#pragma unroll
    for (int i = 0; i < 4; ++i)
        t[tyy + i * 8][txx] = src[(long long)(by + tyy + i * 8) * Cc + bx + txx];
    __syncthreads();
#pragma unroll
    for (int i = 0; i < 4; ++i)
        dst[(long long)(bx + tyy + i * 8) * R + by + txx] = __float2half(t[txx][tyy + i * 8]);
}

// ---------------- fp16 mma.sync TN GEMM, 128x128 tile, 2 CTAs/SM ----------
// C[M,N] = Ah[M,K] @ Bh[N,K]^T, fp32 accum. Block 128x128, 8 warps (4x2),
// warp tile 32x64, K chunk 64, 3-stage cp.async. __launch_bounds__(256,2)
// caps regs at 128 so two CTAs co-reside per SM and cover each other's
// barrier/LDSM-ramp idle on the tensor pipe.
// MODE: 0 = plain fp32 C write, 1 = qkv scatter (q,k fp32; v fp16)
#define SMEM_GEMM_BYTES 99328   // 1024 + 3 * 32768
#define TOFF(buf, which) (1024u + (uint32_t)(buf) * 32768u + (uint32_t)(which) * 16384u)

// one 128x64 fp16 tile -> SW128 smem via cp.async (256 threads, 4 per thread)
__device__ __forceinline__ void cpa_tile(uint32_t sdst, const __half* __restrict__ src,
                                         int ld, int row0, int kbase, int tid) {
#pragma unroll
    for (int p = 0; p < 4; ++p) {
        const int g = tid + p * 256;         // 0..1023
        const int row = g >> 3;              // 0..127
        const int seg = g & 7;               // 16B segment
        cpa16(sdst + sw128(row * 128 + seg * 16),
              src + (long long)(row0 + row) * ld + kbase + seg * 8);
    }
}

template<int MODE>
__global__ __launch_bounds__(256, 2)
void gemm_hf(const __half* __restrict__ Ah, const __half* __restrict__ Bh,
             float* __restrict__ C, int K, int lda, int ldb, int ldc)
{
    const int m0 = blockIdx.y * 128;
    const int n0 = blockIdx.x * 128;
    const int nchunks = K >> 6;

    extern __shared__ char smem[];
    const uint32_t sb = smem_u32(smem);
    const int tid = threadIdx.x;
    const int lane = tid & 31;
    const int wid = tid >> 5;
    const int wm = (wid & 3) * 32;
    const int wn = (wid >> 2) * 64;
    const int lq = lane >> 3, lr = lane & 7;

    const int a_row = wm + (lq & 1) * 8 + lr;
    const int a_kc2 = (lq >> 1) * 16;
    const int b_row = wn + (lq >> 1) * 8 + lr;
    const int b_kc2 = (lq & 1) * 16;

    float acc[2][8][4];
#pragma unroll
    for (int i = 0; i < 2; i++)
#pragma unroll
        for (int j = 0; j < 8; j++)
#pragma unroll
            for (int e = 0; e < 4; e++) acc[i][j][e] = 0.f;

    // prologue: stage chunks 0 and 1 as separate commit groups
    cpa_tile(sb + TOFF(0, 0), Ah, lda, m0, 0, tid);
    cpa_tile(sb + TOFF(0, 1), Bh, ldb, n0, 0, tid);
    cpa_commit();
    cpa_tile(sb + TOFF(1, 0), Ah, lda, m0, 64, tid);
    cpa_tile(sb + TOFF(1, 1), Bh, ldb, n0, 64, tid);
    cpa_commit();
    cpa_wait1();            // chunk 0 resident
    __syncthreads();

    for (int c = 0; c < nchunks; ++c) {
        const int buf = c % 3;
        // prefetch chunk c+2 (always commit to keep wait_group bookkeeping exact)
        if (c + 2 < nchunks) {
            const int nb = (c + 2) % 3;
            const int kb = (c + 2) * 64;
            cpa_tile(sb + TOFF(nb, 0), Ah, lda, m0, kb, tid);
            cpa_tile(sb + TOFF(nb, 1), Bh, ldb, n0, kb, tid);
        }
        cpa_commit();

        const uint32_t sA = sb + TOFF(buf, 0);
        const uint32_t sB = sb + TOFF(buf, 1);
#pragma unroll
        for (int kk = 0; kk < 4; ++kk) {
            uint32_t aF[2][4], bF[4][4];
#pragma unroll
            for (int i = 0; i < 2; ++i)
                ldsm4(aF[i], sA + sw128((a_row + i * 16) * 128 + kk * 32 + a_kc2));
#pragma unroll
            for (int jp = 0; jp < 4; ++jp)
                ldsm4(bF[jp], sB + sw128((b_row + jp * 16) * 128 + kk * 32 + b_kc2));
#pragma unroll
            for (int i = 0; i < 2; ++i)
#pragma unroll
                for (int jp = 0; jp < 4; ++jp) {
                    mma_f16(acc[i][2 * jp],     aF[i], bF[jp][0], bF[jp][1]);
                    mma_f16(acc[i][2 * jp + 1], aF[i], bF[jp][2], bF[jp][3]);
                }
        }

        cpa_wait1();        // chunk c+1's group retired (newest may still fly)
        __syncthreads();
    }

    const int lm = lane >> 2;
    const int ln = (lane & 3) * 2;
#pragma unroll
    for (int i = 0; i < 2; ++i) {
#pragma unroll
        for (int j = 0; j < 8; ++j) {
            const int gn = n0 + wn + j * 8 + ln;
#pragma unroll
            for (int half = 0; half < 2; ++half) {
                const int gm = m0 + wm + i * 16 + lm + half * 8;
                float v0 = acc[i][j][half * 2 + 0];
                float v1 = acc[i][j][half * 2 + 1];
                if (MODE == 0) {
                    *(float2*)(C + (long long)gm * ldc + gn) = make_float2(v0, v1);
                } else {
                    const int t = gn >> 11, h = (gn >> 7) & 15, d = gn & 127;
                    const int b = gm >> 11, s = gm & 2047;
                    const long long idx = ((long long)(b * H_ + h) * S_ + s) * HD_ + d;
                    if (t == 0)      *(float2*)(g_q + idx) = make_float2(v0, v1);
                    else if (t == 1) *(float2*)(g_k + idx) = make_float2(v0, v1);
                    else             *(uint32_t*)(g_vh + idx) = packh(v0, v1);
                }
            }
        }
    }
}

// ---------------- RoPE: Q,K -> fp16 ----------------
__global__ void rope_split(const float* __restrict__ cosT, const float* __restrict__ sinT)
{
    const long long idx = (long long)blockIdx.x * 256 + threadIdx.x;
    const int i = (int)(idx & 63);
    const int s = (int)((idx >> 6) & 2047);
    const int z = (int)(idx >> 17);
    const float c  = cosT[s * 64 + i];
    const float sn = sinT[s * 64 + i];
    const long long base = ((long long)z * S_ + s) * HD_;

    float q1 = g_q[base + i], q2 = g_q[base + 64 + i];
    g_qh[base + i]      = __float2half(q1 * c - q2 * sn);
    g_qh[base + 64 + i] = __float2half(q1 * sn + q2 * c);

    float k1 = g_k[base + i], k2 = g_k[base + 64 + i];
    g_kh[base + i]      = __float2half(k1 * c - k2 * sn);
    g_kh[base + 64 + i] = __float2half(k1 * sn + k2 * c);
}

// ---------------- fused flash attention (fp16, fp32 accum) ----------------
// CTA: (q-tile 128, bh). 8 warps x 16 q-rows. K/V chunks 64 rows, double-
// buffered cp.async. Scores in registers; MMA1 C-frag repacked as MMA2 A-frag.
// smem: Q 32KB @0; kv buf b @32768+b*32768: Kh 16KB, Vh 16KB.
#define FA_SMEM 98304

__device__ __forceinline__ void fa_load_kv(uint32_t kvbase, int bh, int s0, int tid) {
#pragma unroll
    for (int p = 0; p < 4; ++p) {
        const int g = tid + p * 256;          // 0..1023
        const int row = g >> 4;               // 0..63
        const int b16i = g & 15;
        const uint32_t byte = b16i * 16;
        const long long srcoff = (((long long)(bh << 11) + s0 + row) << 7) + b16i * 8;
        const uint32_t dst = kvbase + (byte >> 7) * 8192 + sw128(row * 128 + (byte & 127));
        cpa16(dst,         g_kh + srcoff);
        cpa16(dst + 16384, g_vh + srcoff);
    }
}

__global__ __launch_bounds__(256, 1)
void flash_attn()
{
    const int qt = 15 - blockIdx.x;           // big tiles first
    const int q0 = qt << 7;
    const int bh = blockIdx.y;
    const int nch = (qt + 1) * 2;

    extern __shared__ char smem[];
    const uint32_t sb = smem_u32(smem);
    const int tid = threadIdx.x;
    const int w = tid >> 5;
    const int lane = tid & 31;
    const int wq = w * 16;
    const int lq = lane >> 3, lr = lane & 7;
    const int lc = lane & 3;
    const int lrow = lane >> 2;

    // prologue: Q + chunk 0
#pragma unroll
    for (int p = 0; p < 4; ++p) {
        const int g = tid + p * 256;          // 0..1023
        const int row = g >> 3;               // 0..127
        const int b16i = g & 7;
        const uint32_t byte0 = b16i * 16;
        const long long srcoff0 = (((long long)(bh << 11) + q0 + row) << 7) + b16i * 8;
        cpa16(sb + (byte0 >> 7) * 16384 + sw128(row * 128 + (byte0 & 127)), g_qh + srcoff0);
        const uint32_t byte1 = byte0 + 128;
        const long long srcoff1 = srcoff0 + 64;
        cpa16(sb + (byte1 >> 7) * 16384 + sw128(row * 128 + (byte1 & 127)), g_qh + srcoff1);
    }
    fa_load_kv(sb + 32768, bh, 0, tid);
    cpa_commit();
    cpa_wait0();
    __syncthreads();

    const float C = 0.08838834764831845f * 1.4426950408889634f; // scale*log2(e)
    float o[16][4];
#pragma unroll
    for (int t = 0; t < 16; ++t)
#pragma unroll
        for (int e = 0; e < 4; ++e) o[t][e] = 0.f;
    float m0 = -1e30f, m1 = -1e30f, l0 = 0.f, l1 = 0.f;

    for (int c = 0; c < nch; ++c) {
        const uint32_t kvb = sb + 32768 + (uint32_t)(c & 1) * 32768;
        if (c + 1 < nch) {
            fa_load_kv(sb + 32768 + (uint32_t)((c + 1) & 1) * 32768, bh, (c + 1) * 64, tid);
            cpa_commit();
        }

        // MMA1: scores[16q x 64k] = Q @ K^T
        float s[8][4];
#pragma unroll
        for (int j = 0; j < 8; ++j)
#pragma unroll
            for (int e = 0; e < 4; ++e) s[j][e] = 0.f;

#pragma unroll
        for (int kk = 0; kk < 8; ++kk) {
            const int arow = wq + (lq & 1) * 8 + lr;
            const uint32_t akb = kk * 32 + (lq >> 1) * 16;
            const uint32_t qaddr = sb + (akb >> 7) * 16384 + sw128(arow * 128 + (akb & 127));
            uint32_t a4[4];
            ldsm4(a4, qaddr);
#pragma unroll
            for (int nt = 0; nt < 4; ++nt) {
                const int brow = nt * 16 + (lq >> 1) * 8 + lr;
                const uint32_t bkb = kk * 32 + (lq & 1) * 16;
                const uint32_t kaddr = kvb + (bkb >> 7) * 8192 + sw128(brow * 128 + (bkb & 127));
                uint32_t b4[4];
                ldsm4(b4, kaddr);
                mma_f16(s[2 * nt],     a4, b4[0], b4[1]);
                mma_f16(s[2 * nt + 1], a4, b4[2], b4[3]);
            }
        }

        // causal mask near diagonal
        if (c * 64 + 63 > q0 + wq) {
            const int r0g = q0 + wq + lrow;
#pragma unroll
            for (int j = 0; j < 8; ++j) {
                const int k0 = c * 64 + 8 * j + 2 * lc;
                if (k0 > r0g)         s[j][0] = -1e30f;
                if (k0 + 1 > r0g)     s[j][1] = -1e30f;
                if (k0 > r0g + 8)     s[j][2] = -1e30f;
                if (k0 + 1 > r0g + 8) s[j][3] = -1e30f;
            }
        }

        // online softmax
        float mx0 = -1e30f, mx1 = -1e30f;
#pragma unroll
        for (int j = 0; j < 8; ++j) {
            mx0 = fmaxf(mx0, fmaxf(s[j][0], s[j][1]));
            mx1 = fmaxf(mx1, fmaxf(s[j][2], s[j][3]));
        }
        mx0 = fmaxf(mx0, __shfl_xor_sync(0xffffffffu, mx0, 1));
        mx0 = fmaxf(mx0, __shfl_xor_sync(0xffffffffu, mx0, 2));
        mx1 = fmaxf(mx1, __shfl_xor_sync(0xffffffffu, mx1, 1));
        mx1 = fmaxf(mx1, __shfl_xor_sync(0xffffffffu, mx1, 2));
        const float mn0 = fmaxf(m0, mx0), mn1 = fmaxf(m1, mx1);
        const float al0 = ex2((m0 - mn0) * C), al1 = ex2((m1 - mn1) * C);
        m0 = mn0; m1 = mn1;
        l0 *= al0; l1 *= al1;
#pragma unroll
        for (int t = 0; t < 16; ++t) {
            o[t][0] *= al0; o[t][1] *= al0; o[t][2] *= al1; o[t][3] *= al1;
        }
        uint32_t ph[8][2];
#pragma unroll
        for (int j = 0; j < 8; ++j) {
            float p0 = ex2((s[j][0] - m0) * C);
            float p1 = ex2((s[j][1] - m0) * C);
            float p2 = ex2((s[j][2] - m1) * C);
            float p3 = ex2((s[j][3] - m1) * C);
            l0 += p0 + p1; l1 += p2 + p3;
            ph[j][0] = packh(p0, p1);
            ph[j][1] = packh(p2, p3);
        }

        // MMA2: O += P @ V (V via trans ldmatrix)
#pragma unroll
        for (int kk = 0; kk < 4; ++kk) {
            uint32_t pa[4] = { ph[2 * kk][0], ph[2 * kk][1], ph[2 * kk + 1][0], ph[2 * kk + 1][1] };
#pragma unroll
            for (int nt = 0; nt < 8; ++nt) {
                const int vrow = kk * 16 + (lq & 1) * 8 + lr;
                const uint32_t nb = nt * 32 + (lq >> 1) * 16;
                const uint32_t vaddr = kvb + 16384 + (nb >> 7) * 8192 + sw128(vrow * 128 + (nb & 127));
                uint32_t v4[4];
                ldsm4t(v4, vaddr);
                mma_f16(o[2 * nt],     pa, v4[0], v4[1]);
                mma_f16(o[2 * nt + 1], pa, v4[2], v4[3]);
            }
        }

        cpa_wait0();
        __syncthreads();
    }

    l0 += __shfl_xor_sync(0xffffffffu, l0, 1);
    l0 += __shfl_xor_sync(0xffffffffu, l0, 2);
    l1 += __shfl_xor_sync(0xffffffffu, l1, 1);
    l1 += __shfl_xor_sync(0xffffffffu, l1, 2);
    const float inv0 = 1.f / l0, inv1 = 1.f / l1;

    // write attn as fp16 [B,S,D]
    const int b = bh >> 4, h = bh & 15;
    const int row0 = q0 + wq + lrow;
    const long long base0 = ((long long)(b * S_ + row0)) * D_ + h * HD_ + 2 * lc;
    const long long base1 = base0 + 8LL * D_;
#pragma unroll
    for (int t = 0; t < 16; ++t) {
        *(uint32_t*)(g_ah + base0 + 8 * t) = packh(o[t][0] * inv0, o[t][1] * inv0);
        *(uint32_t*)(g_ah + base1 + 8 * t) = packh(o[t][2] * inv1, o[t][3] * inv1);
    }
}

// ---------------- launch ----------------
extern "C" void kernel_launch(void* const* d_in, const int* in_sizes, int n_in,
                              void* d_out, int out_size)
{
    const float* x     = (const float*)d_in[0]; // [4,2048,2048]
    const float* cosT  = (const float*)d_in[1]; // [2048,64]
    const float* sinT  = (const float*)d_in[2]; // [2048,64]
    const float* w_qkv = (const float*)d_in[3]; // [2048,6144]
    const float* w_out = (const float*)d_in[4]; // [2048,2048]
    float* out = (float*)d_out;                 // [4,2048,2048]
    (void)in_sizes; (void)n_in; (void)out_size;

    __half *xh, *wqh, *woh, *ah;
    cudaGetSymbolAddress((void**)&xh, g_xh);
    cudaGetSymbolAddress((void**)&wqh, g_wqh);
    cudaGetSymbolAddress((void**)&woh, g_woh);
    cudaGetSymbolAddress((void**)&ah, g_ah);

    cudaFuncSetAttribute(gemm_hf<0>, cudaFuncAttributeMaxDynamicSharedMemorySize, SMEM_GEMM_BYTES);
    cudaFuncSetAttribute(gemm_hf<1>, cudaFuncAttributeMaxDynamicSharedMemorySize, SMEM_GEMM_BYTES);
    cudaFuncSetAttribute(flash_attn, cudaFuncAttributeMaxDynamicSharedMemorySize, FA_SMEM);

    // 0) one-time conversions
    round_f32h<<<16384, 256>>>(x, xh);
    transpose_h<<<dim3(6144 / 32, 2048 / 32), dim3(32, 8)>>>(w_qkv, wqh, 2048, 6144);
    transpose_h<<<dim3(2048 / 32, 2048 / 32), dim3(32, 8)>>>(w_out, woh, 2048, 2048);

    // 1) QKV projection (128x128 tile, 2 CTAs/SM); scatter q,k fp32 and v fp16
    gemm_hf<1><<<dim3(48, 64, 1), 256, SMEM_GEMM_BYTES>>>(
        xh, wqh, nullptr, 2048, 2048, 2048, 0);

    // 2) RoPE -> fp16 q,k
    rope_split<<<(Bb_ * H_ * S_ * (HD_ / 2)) / 256, 256>>>(cosT, sinT);

    // 3) fused flash attention -> g_ah fp16 [B,S,D]
    flash_attn<<<dim3(16, Bb_ * H_), 256, FA_SMEM>>>();

    // 4) out = attn @ w_outT^T (2 CTAs/SM)
    gemm_hf<0><<<dim3(16, 64, 1), 256, SMEM_GEMM_BYTES>>>(
        ah, woh, out, 2048, 2048, 2048, 2048);
}